// round 1
// baseline (speedup 1.0000x reference)
#include <cuda_runtime.h>
#include <cuda_bf16.h>
#include <math.h>

#define SEQ 4096
#define CDIM 768
#define NH 12
#define HD 64
#define FDIM 3072

// ---------------- scratch (device globals; no allocation allowed) ----------
__device__ float g_q[SEQ * CDIM];
__device__ float g_k[SEQ * CDIM];
__device__ float g_v[SEQ * CDIM];
__device__ float g_attn[SEQ * CDIM];   // attention output (pre-Wo)
__device__ float g_proj[SEQ * CDIM];   // attn @ Wo
__device__ float g_h[SEQ * CDIM];      // after LN1
__device__ float g_mlp1[SEQ * FDIM];   // gelu(h@W1+b1)
__device__ float g_mlp2[SEQ * CDIM];   // mlp1@W2+b2

// ---------------- SGEMM: C[M,N] = A[M,K] @ B[K,N] + bias (opt GELU) --------
// BM=BN=128, BK=16, 256 threads, 8x8 per-thread microtile.
template <bool GELU>
__global__ __launch_bounds__(256) void sgemm_bias(
    const float* __restrict__ A, const float* __restrict__ B,
    const float* __restrict__ bias, float* __restrict__ C,
    int M, int N, int K)
{
    constexpr int BM = 128, BN = 128, BK = 16, TM = 8, TN = 8;
    __shared__ float As[BK][BM];
    __shared__ float Bs[BK][BN];

    const int bx = blockIdx.x;          // N tiles
    const int by = blockIdx.y;          // M tiles
    const int tid = threadIdx.x;
    const int tx = tid & 15;            // 0..15 (col group)
    const int ty = tid >> 4;            // 0..15 (row group)

    const float* Aptr = A + (size_t)by * BM * K;
    const float* Bptr = B + (size_t)bx * BN;

    // A loader: 128 rows x 16 cols, float4 -> transpose into As
    const int aRow = tid >> 2;          // 0..63
    const int aCol = (tid & 3) * 4;     // 0,4,8,12
    // B loader: 16 rows x 128 cols, float4
    const int bRow = tid >> 5;          // 0..7
    const int bCol = (tid & 31) * 4;

    float acc[TM][TN] = {};

    for (int k0 = 0; k0 < K; k0 += BK) {
#pragma unroll
        for (int i = 0; i < 2; i++) {
            int r = aRow + i * 64;
            float4 a4 = *reinterpret_cast<const float4*>(Aptr + (size_t)r * K + k0 + aCol);
            As[aCol + 0][r] = a4.x;
            As[aCol + 1][r] = a4.y;
            As[aCol + 2][r] = a4.z;
            As[aCol + 3][r] = a4.w;
        }
#pragma unroll
        for (int i = 0; i < 2; i++) {
            int r = bRow + i * 8;
            float4 b4 = *reinterpret_cast<const float4*>(Bptr + (size_t)(k0 + r) * N + bCol);
            *reinterpret_cast<float4*>(&Bs[r][bCol]) = b4;
        }
        __syncthreads();

#pragma unroll
        for (int kk = 0; kk < BK; kk++) {
            float a[TM], b[TN];
#pragma unroll
            for (int i = 0; i < TM; i++) a[i] = As[kk][ty * TM + i];
#pragma unroll
            for (int j = 0; j < TN; j++) b[j] = Bs[kk][tx * TN + j];
#pragma unroll
            for (int i = 0; i < TM; i++)
#pragma unroll
                for (int j = 0; j < TN; j++)
                    acc[i][j] = fmaf(a[i], b[j], acc[i][j]);
        }
        __syncthreads();
    }

#pragma unroll
    for (int i = 0; i < TM; i++) {
        int row = by * BM + ty * TM + i;
#pragma unroll
        for (int j = 0; j < TN; j += 4) {
            int col = bx * BN + tx * TN + j;
            float4 r;
            r.x = acc[i][j + 0] + bias[col + 0];
            r.y = acc[i][j + 1] + bias[col + 1];
            r.z = acc[i][j + 2] + bias[col + 2];
            r.w = acc[i][j + 3] + bias[col + 3];
            if (GELU) {
                r.x = 0.5f * r.x * (1.0f + erff(r.x * 0.70710678118654752f));
                r.y = 0.5f * r.y * (1.0f + erff(r.y * 0.70710678118654752f));
                r.z = 0.5f * r.z * (1.0f + erff(r.z * 0.70710678118654752f));
                r.w = 0.5f * r.w * (1.0f + erff(r.w * 0.70710678118654752f));
            }
            *reinterpret_cast<float4*>(C + (size_t)row * N + col) = r;
        }
    }
}

// ---------------- causal flash attention, fp32, D=64 ------------------------
// grid: (SEQ/128, NH), block 128. One query row per thread, online softmax
// over 16-key chunks staged through shared memory.
__global__ __launch_bounds__(128) void flash_attn(
    const float* __restrict__ Q, const float* __restrict__ K,
    const float* __restrict__ V, float* __restrict__ O)
{
    constexpr int D = HD, BM = 128, BN = 16;
    const int h = blockIdx.y;
    const int qb = blockIdx.x;
    const int tid = threadIdx.x;
    const int qr = qb * BM + tid;

    __shared__ float Ks[BN][D];
    __shared__ float Vs[BN][D];

    float qreg[D];
    const float* qp = Q + (size_t)qr * CDIM + h * D;
#pragma unroll
    for (int d = 0; d < D; d += 4) {
        float4 t = *reinterpret_cast<const float4*>(qp + d);
        qreg[d + 0] = t.x * 0.125f;   // 1/sqrt(64) folded into q
        qreg[d + 1] = t.y * 0.125f;
        qreg[d + 2] = t.z * 0.125f;
        qreg[d + 3] = t.w * 0.125f;
    }

    float oacc[D];
#pragma unroll
    for (int d = 0; d < D; d++) oacc[d] = 0.f;
    float m = -1e30f, l = 0.f;

    const int nch = (qb + 1) * (BM / BN);
    for (int cb = 0; cb < nch; cb++) {
        const int kbase = cb * BN;
        // cooperative load of 16x64 K and V tiles (256 float4 each)
#pragma unroll
        for (int i = 0; i < 2; i++) {
            int idx = tid * 2 + i;             // 0..255
            int rrow = idx >> 4;
            int c4 = (idx & 15) * 4;
            *reinterpret_cast<float4*>(&Ks[rrow][c4]) =
                *reinterpret_cast<const float4*>(K + (size_t)(kbase + rrow) * CDIM + h * D + c4);
            *reinterpret_cast<float4*>(&Vs[rrow][c4]) =
                *reinterpret_cast<const float4*>(V + (size_t)(kbase + rrow) * CDIM + h * D + c4);
        }
        __syncthreads();

        float s[BN];
        float mloc = -1e30f;
#pragma unroll
        for (int j = 0; j < BN; j++) {
            float acc = 0.f;
#pragma unroll
            for (int d = 0; d < D; d += 4) {
                float4 kv = *reinterpret_cast<const float4*>(&Ks[j][d]);
                acc = fmaf(qreg[d + 0], kv.x, acc);
                acc = fmaf(qreg[d + 1], kv.y, acc);
                acc = fmaf(qreg[d + 2], kv.z, acc);
                acc = fmaf(qreg[d + 3], kv.w, acc);
            }
            s[j] = (kbase + j <= qr) ? acc : -1e30f;
            mloc = fmaxf(mloc, s[j]);
        }

        float newm = fmaxf(m, mloc);
        float corr = __expf(m - newm);
        l *= corr;
#pragma unroll
        for (int d = 0; d < D; d++) oacc[d] *= corr;

#pragma unroll
        for (int j = 0; j < BN; j++) {
            float p = __expf(s[j] - newm);
            l += p;
#pragma unroll
            for (int d = 0; d < D; d += 4) {
                float4 vv = *reinterpret_cast<const float4*>(&Vs[j][d]);
                oacc[d + 0] = fmaf(p, vv.x, oacc[d + 0]);
                oacc[d + 1] = fmaf(p, vv.y, oacc[d + 1]);
                oacc[d + 2] = fmaf(p, vv.z, oacc[d + 2]);
                oacc[d + 3] = fmaf(p, vv.w, oacc[d + 3]);
            }
        }
        m = newm;
        __syncthreads();
    }

    float inv = 1.f / l;
    float* op = O + (size_t)qr * CDIM + h * D;
#pragma unroll
    for (int d = 0; d < D; d += 4) {
        float4 t;
        t.x = oacc[d + 0] * inv;
        t.y = oacc[d + 1] * inv;
        t.z = oacc[d + 2] * inv;
        t.w = oacc[d + 3] * inv;
        *reinterpret_cast<float4*>(op + d) = t;
    }
}

// ---------------- fused residual add + LayerNorm ---------------------------
// out[row] = LN(A[row] + B[row]) * g + beta ; one block per row, 256 threads
__global__ __launch_bounds__(256) void add_ln(
    const float* __restrict__ A, const float* __restrict__ Bb,
    const float* __restrict__ g, const float* __restrict__ be,
    float* __restrict__ out)
{
    const int row = blockIdx.x;
    const int tid = threadIdx.x;
    const float* pa = A + (size_t)row * CDIM;
    const float* pb = Bb + (size_t)row * CDIM;

    float v[3];
    float s = 0.f, sq = 0.f;
#pragma unroll
    for (int i = 0; i < 3; i++) {
        int idx = tid + i * 256;
        v[i] = pa[idx] + pb[idx];
        s += v[i];
        sq += v[i] * v[i];
    }
#pragma unroll
    for (int off = 16; off; off >>= 1) {
        s += __shfl_xor_sync(0xffffffffu, s, off);
        sq += __shfl_xor_sync(0xffffffffu, sq, off);
    }
    __shared__ float ss[8], ssq[8];
    int w = tid >> 5, lane = tid & 31;
    if (lane == 0) { ss[w] = s; ssq[w] = sq; }
    __syncthreads();
    if (tid < 32) {
        s = (tid < 8) ? ss[tid] : 0.f;
        sq = (tid < 8) ? ssq[tid] : 0.f;
#pragma unroll
        for (int off = 4; off; off >>= 1) {
            s += __shfl_xor_sync(0xffffffffu, s, off);
            sq += __shfl_xor_sync(0xffffffffu, sq, off);
        }
        if (tid == 0) { ss[0] = s; ssq[0] = sq; }
    }
    __syncthreads();
    const float mean = ss[0] * (1.0f / CDIM);
    const float var = ssq[0] * (1.0f / CDIM) - mean * mean;
    const float inv = rsqrtf(var + 1e-5f);
#pragma unroll
    for (int i = 0; i < 3; i++) {
        int idx = tid + i * 256;
        out[(size_t)row * CDIM + idx] = (v[i] - mean) * inv * g[idx] + be[idx];
    }
}

// ---------------- launch ----------------------------------------------------
extern "C" void kernel_launch(void* const* d_in, const int* in_sizes, int n_in,
                              void* d_out, int out_size)
{
    const float* x     = (const float*)d_in[0];
    const float* Wq    = (const float*)d_in[1];
    const float* bq    = (const float*)d_in[2];
    const float* Wk    = (const float*)d_in[3];
    const float* bk    = (const float*)d_in[4];
    const float* Wv    = (const float*)d_in[5];
    const float* bv    = (const float*)d_in[6];
    const float* Wo    = (const float*)d_in[7];
    const float* bo    = (const float*)d_in[8];
    const float* ln1g  = (const float*)d_in[9];
    const float* ln1b  = (const float*)d_in[10];
    const float* W1    = (const float*)d_in[11];
    const float* b1    = (const float*)d_in[12];
    const float* W2    = (const float*)d_in[13];
    const float* b2    = (const float*)d_in[14];
    const float* ln2g  = (const float*)d_in[15];
    const float* ln2b  = (const float*)d_in[16];
    float* y = (float*)d_out;

    float *q, *k, *v, *attn, *proj, *h, *m1, *m2;
    cudaGetSymbolAddress((void**)&q,    g_q);
    cudaGetSymbolAddress((void**)&k,    g_k);
    cudaGetSymbolAddress((void**)&v,    g_v);
    cudaGetSymbolAddress((void**)&attn, g_attn);
    cudaGetSymbolAddress((void**)&proj, g_proj);
    cudaGetSymbolAddress((void**)&h,    g_h);
    cudaGetSymbolAddress((void**)&m1,   g_mlp1);
    cudaGetSymbolAddress((void**)&m2,   g_mlp2);

    dim3 blk(256);
    dim3 grid_cc(CDIM / 128, SEQ / 128);   // N=768
    dim3 grid_cf(FDIM / 128, SEQ / 128);   // N=3072

    // QKV projections
    sgemm_bias<false><<<grid_cc, blk>>>(x, Wq, bq, q, SEQ, CDIM, CDIM);
    sgemm_bias<false><<<grid_cc, blk>>>(x, Wk, bk, k, SEQ, CDIM, CDIM);
    sgemm_bias<false><<<grid_cc, blk>>>(x, Wv, bv, v, SEQ, CDIM, CDIM);

    // causal attention
    flash_attn<<<dim3(SEQ / 128, NH), 128>>>(q, k, v, attn);

    // output projection
    sgemm_bias<false><<<grid_cc, blk>>>(attn, Wo, bo, proj, SEQ, CDIM, CDIM);

    // h = LN(x + proj)
    add_ln<<<SEQ, 256>>>(x, proj, ln1g, ln1b, h);

    // MLP
    sgemm_bias<true><<<grid_cf, blk>>>(h, W1, b1, m1, SEQ, FDIM, CDIM);
    sgemm_bias<false><<<grid_cc, blk>>>(m1, W2, b2, m2, SEQ, CDIM, FDIM);

    // y = LN(h + mlp)
    add_ln<<<SEQ, 256>>>(h, m2, ln2g, ln2b, y);

    (void)in_sizes; (void)n_in; (void)out_size;
}

// round 2
// speedup vs baseline: 1.2321x; 1.2321x over previous
#include <cuda_runtime.h>
#include <cuda_bf16.h>
#include <math.h>

#define SEQ 4096
#define CDIM 768
#define NH 12
#define HD 64
#define FDIM 3072

// ---------------- scratch (device globals; no allocation allowed) ----------
__device__ float g_q[SEQ * CDIM];
__device__ float g_k[SEQ * CDIM];
__device__ float g_v[SEQ * CDIM];
__device__ float g_attn[SEQ * CDIM];   // attention output (pre-Wo)
__device__ float g_proj[SEQ * CDIM];   // attn @ Wo
__device__ float g_h[SEQ * CDIM];      // after LN1
__device__ float g_mlp1[SEQ * FDIM];   // gelu(h@W1+b1)
__device__ float g_mlp2[SEQ * CDIM];   // mlp1@W2+b2

// ---------------- TF32 tensor-core GEMM -------------------------------------
// C[M,N] = A[M,K] @ B[K,N] + bias (optional exact GELU).
// BM=BN=128, BK=32, 256 threads = 8 warps (4 along M x 2 along N),
// warp tile 32x64 via mma.sync.m16n8k8.tf32 (2 m-tiles x 8 n-tiles x 4 k-steps).
// Inputs converted with cvt.rna.tf32 (round-to-nearest) at smem store.
template <bool GELU>
__global__ __launch_bounds__(256) void gemm_tf32(
    const float* __restrict__ A, const float* __restrict__ B,
    const float* __restrict__ bias, float* __restrict__ C,
    int M, int N, int K)
{
    constexpr int BM = 128, BN = 128, BK = 32;
    __shared__ unsigned As[BK][BM + 4];   // k-major A (transposed)
    __shared__ unsigned Bs[BK][BN + 4];   // k-major B

    const int tid  = threadIdx.x;
    const int lane = tid & 31;
    const int warp = tid >> 5;
    const int wm = warp & 3;              // warp row (4 along M)
    const int wn = warp >> 2;             // warp col (2 along N)
    const int g  = lane >> 2;             // octet row 0..7
    const int t  = lane & 3;              // thread-in-group 0..3

    const int bx = blockIdx.x, by = blockIdx.y;

    // A loader: 128 rows x 32 k, 2 threads/row, 16 floats each
    const int arow  = tid >> 1;
    const int akseg = (tid & 1) * 16;
    // B loader: 32 k-rows x 128 n, 8 threads/row, 16 floats each
    const int brow = tid >> 3;
    const int bnb  = (tid & 7) * 16;

    const float* Ap = A + (size_t)(by * BM + arow) * K + akseg;
    const float* Bp = B + (size_t)brow * N + (size_t)bx * BN + bnb;

    float a_st[16], b_st[16];

    // prefetch tile 0
#pragma unroll
    for (int i = 0; i < 4; i++) {
        float4 v = *reinterpret_cast<const float4*>(Ap + 4 * i);
        a_st[4 * i + 0] = v.x; a_st[4 * i + 1] = v.y;
        a_st[4 * i + 2] = v.z; a_st[4 * i + 3] = v.w;
    }
#pragma unroll
    for (int i = 0; i < 4; i++) {
        float4 v = *reinterpret_cast<const float4*>(Bp + 4 * i);
        b_st[4 * i + 0] = v.x; b_st[4 * i + 1] = v.y;
        b_st[4 * i + 2] = v.z; b_st[4 * i + 3] = v.w;
    }

    float acc[2][8][4] = {};

    const int niter = K / BK;
    for (int it = 0; it < niter; it++) {
        // staged regs -> smem (with RNA tf32 rounding)
#pragma unroll
        for (int i = 0; i < 16; i++) {
            unsigned u;
            asm("cvt.rna.tf32.f32 %0, %1;" : "=r"(u) : "f"(a_st[i]));
            As[akseg + i][arow] = u;
        }
#pragma unroll
        for (int i = 0; i < 4; i++) {
            unsigned u0, u1, u2, u3;
            asm("cvt.rna.tf32.f32 %0, %1;" : "=r"(u0) : "f"(b_st[4 * i + 0]));
            asm("cvt.rna.tf32.f32 %0, %1;" : "=r"(u1) : "f"(b_st[4 * i + 1]));
            asm("cvt.rna.tf32.f32 %0, %1;" : "=r"(u2) : "f"(b_st[4 * i + 2]));
            asm("cvt.rna.tf32.f32 %0, %1;" : "=r"(u3) : "f"(b_st[4 * i + 3]));
            *reinterpret_cast<uint4*>(&Bs[brow][bnb + 4 * i]) = make_uint4(u0, u1, u2, u3);
        }
        __syncthreads();

        // prefetch next tile while computing this one
        if (it + 1 < niter) {
            Ap += BK;
            Bp += (size_t)BK * N;
#pragma unroll
            for (int i = 0; i < 4; i++) {
                float4 v = *reinterpret_cast<const float4*>(Ap + 4 * i);
                a_st[4 * i + 0] = v.x; a_st[4 * i + 1] = v.y;
                a_st[4 * i + 2] = v.z; a_st[4 * i + 3] = v.w;
            }
#pragma unroll
            for (int i = 0; i < 4; i++) {
                float4 v = *reinterpret_cast<const float4*>(Bp + 4 * i);
                b_st[4 * i + 0] = v.x; b_st[4 * i + 1] = v.y;
                b_st[4 * i + 2] = v.z; b_st[4 * i + 3] = v.w;
            }
        }

        // 4 k-steps of m16n8k8
#pragma unroll
        for (int ks = 0; ks < 4; ks++) {
            const int k8 = ks * 8;
            unsigned af[2][4], bf[8][2];
#pragma unroll
            for (int mt = 0; mt < 2; mt++) {
                const int mb = wm * 32 + mt * 16;
                af[mt][0] = As[k8 + t][mb + g];
                af[mt][1] = As[k8 + t][mb + g + 8];
                af[mt][2] = As[k8 + t + 4][mb + g];
                af[mt][3] = As[k8 + t + 4][mb + g + 8];
            }
#pragma unroll
            for (int nt = 0; nt < 8; nt++) {
                const int nb = wn * 64 + nt * 8;
                bf[nt][0] = Bs[k8 + t][nb + g];
                bf[nt][1] = Bs[k8 + t + 4][nb + g];
            }
#pragma unroll
            for (int mt = 0; mt < 2; mt++)
#pragma unroll
                for (int nt = 0; nt < 8; nt++)
                    asm volatile(
                        "mma.sync.aligned.m16n8k8.row.col.f32.tf32.tf32.f32 "
                        "{%0,%1,%2,%3},{%4,%5,%6,%7},{%8,%9},{%0,%1,%2,%3};"
                        : "+f"(acc[mt][nt][0]), "+f"(acc[mt][nt][1]),
                          "+f"(acc[mt][nt][2]), "+f"(acc[mt][nt][3])
                        : "r"(af[mt][0]), "r"(af[mt][1]), "r"(af[mt][2]), "r"(af[mt][3]),
                          "r"(bf[nt][0]), "r"(bf[nt][1]));
        }
        __syncthreads();
    }

    // epilogue: bias (+ GELU), float2 stores
#pragma unroll
    for (int mt = 0; mt < 2; mt++) {
        const int r0 = by * BM + wm * 32 + mt * 16 + g;
#pragma unroll
        for (int nt = 0; nt < 8; nt++) {
            const int c0 = bx * BN + wn * 64 + nt * 8 + t * 2;
            const float bz0 = bias[c0], bz1 = bias[c0 + 1];
            float v0 = acc[mt][nt][0] + bz0;
            float v1 = acc[mt][nt][1] + bz1;
            float v2 = acc[mt][nt][2] + bz0;
            float v3 = acc[mt][nt][3] + bz1;
            if (GELU) {
                v0 = 0.5f * v0 * (1.0f + erff(v0 * 0.70710678118654752f));
                v1 = 0.5f * v1 * (1.0f + erff(v1 * 0.70710678118654752f));
                v2 = 0.5f * v2 * (1.0f + erff(v2 * 0.70710678118654752f));
                v3 = 0.5f * v3 * (1.0f + erff(v3 * 0.70710678118654752f));
            }
            *reinterpret_cast<float2*>(C + (size_t)r0 * N + c0) = make_float2(v0, v1);
            *reinterpret_cast<float2*>(C + (size_t)(r0 + 8) * N + c0) = make_float2(v2, v3);
        }
    }
}

// ---------------- causal flash attention, fp32, D=64 ------------------------
// grid: (SEQ/128, NH), block 128. One query row per thread, online softmax
// over 16-key chunks staged through shared memory.
__global__ __launch_bounds__(128) void flash_attn(
    const float* __restrict__ Q, const float* __restrict__ K,
    const float* __restrict__ V, float* __restrict__ O)
{
    constexpr int D = HD, BM = 128, BN = 16;
    const int h = blockIdx.y;
    const int qb = blockIdx.x;
    const int tid = threadIdx.x;
    const int qr = qb * BM + tid;

    __shared__ float Ks[BN][D];
    __shared__ float Vs[BN][D];

    float qreg[D];
    const float* qp = Q + (size_t)qr * CDIM + h * D;
#pragma unroll
    for (int d = 0; d < D; d += 4) {
        float4 t = *reinterpret_cast<const float4*>(qp + d);
        qreg[d + 0] = t.x * 0.125f;   // 1/sqrt(64) folded into q
        qreg[d + 1] = t.y * 0.125f;
        qreg[d + 2] = t.z * 0.125f;
        qreg[d + 3] = t.w * 0.125f;
    }

    float oacc[D];
#pragma unroll
    for (int d = 0; d < D; d++) oacc[d] = 0.f;
    float m = -1e30f, l = 0.f;

    const int nch = (qb + 1) * (BM / BN);
    for (int cb = 0; cb < nch; cb++) {
        const int kbase = cb * BN;
#pragma unroll
        for (int i = 0; i < 2; i++) {
            int idx = tid * 2 + i;             // 0..255
            int rrow = idx >> 4;
            int c4 = (idx & 15) * 4;
            *reinterpret_cast<float4*>(&Ks[rrow][c4]) =
                *reinterpret_cast<const float4*>(K + (size_t)(kbase + rrow) * CDIM + h * D + c4);
            *reinterpret_cast<float4*>(&Vs[rrow][c4]) =
                *reinterpret_cast<const float4*>(V + (size_t)(kbase + rrow) * CDIM + h * D + c4);
        }
        __syncthreads();

        float s[BN];
        float mloc = -1e30f;
#pragma unroll
        for (int j = 0; j < BN; j++) {
            float acc = 0.f;
#pragma unroll
            for (int d = 0; d < D; d += 4) {
                float4 kv = *reinterpret_cast<const float4*>(&Ks[j][d]);
                acc = fmaf(qreg[d + 0], kv.x, acc);
                acc = fmaf(qreg[d + 1], kv.y, acc);
                acc = fmaf(qreg[d + 2], kv.z, acc);
                acc = fmaf(qreg[d + 3], kv.w, acc);
            }
            s[j] = (kbase + j <= qr) ? acc : -1e30f;
            mloc = fmaxf(mloc, s[j]);
        }

        float newm = fmaxf(m, mloc);
        float corr = __expf(m - newm);
        l *= corr;
#pragma unroll
        for (int d = 0; d < D; d++) oacc[d] *= corr;

#pragma unroll
        for (int j = 0; j < BN; j++) {
            float p = __expf(s[j] - newm);
            l += p;
#pragma unroll
            for (int d = 0; d < D; d += 4) {
                float4 vv = *reinterpret_cast<const float4*>(&Vs[j][d]);
                oacc[d + 0] = fmaf(p, vv.x, oacc[d + 0]);
                oacc[d + 1] = fmaf(p, vv.y, oacc[d + 1]);
                oacc[d + 2] = fmaf(p, vv.z, oacc[d + 2]);
                oacc[d + 3] = fmaf(p, vv.w, oacc[d + 3]);
            }
        }
        m = newm;
        __syncthreads();
    }

    float inv = 1.f / l;
    float* op = O + (size_t)qr * CDIM + h * D;
#pragma unroll
    for (int d = 0; d < D; d += 4) {
        float4 t;
        t.x = oacc[d + 0] * inv;
        t.y = oacc[d + 1] * inv;
        t.z = oacc[d + 2] * inv;
        t.w = oacc[d + 3] * inv;
        *reinterpret_cast<float4*>(op + d) = t;
    }
}

// ---------------- fused residual add + LayerNorm ---------------------------
__global__ __launch_bounds__(256) void add_ln(
    const float* __restrict__ A, const float* __restrict__ Bb,
    const float* __restrict__ g, const float* __restrict__ be,
    float* __restrict__ out)
{
    const int row = blockIdx.x;
    const int tid = threadIdx.x;
    const float* pa = A + (size_t)row * CDIM;
    const float* pb = Bb + (size_t)row * CDIM;

    float v[3];
    float s = 0.f, sq = 0.f;
#pragma unroll
    for (int i = 0; i < 3; i++) {
        int idx = tid + i * 256;
        v[i] = pa[idx] + pb[idx];
        s += v[i];
        sq += v[i] * v[i];
    }
#pragma unroll
    for (int off = 16; off; off >>= 1) {
        s += __shfl_xor_sync(0xffffffffu, s, off);
        sq += __shfl_xor_sync(0xffffffffu, sq, off);
    }
    __shared__ float ss[8], ssq[8];
    int w = tid >> 5, lane = tid & 31;
    if (lane == 0) { ss[w] = s; ssq[w] = sq; }
    __syncthreads();
    if (tid < 32) {
        s = (tid < 8) ? ss[tid] : 0.f;
        sq = (tid < 8) ? ssq[tid] : 0.f;
#pragma unroll
        for (int off = 4; off; off >>= 1) {
            s += __shfl_xor_sync(0xffffffffu, s, off);
            sq += __shfl_xor_sync(0xffffffffu, sq, off);
        }
        if (tid == 0) { ss[0] = s; ssq[0] = sq; }
    }
    __syncthreads();
    const float mean = ss[0] * (1.0f / CDIM);
    const float var = ssq[0] * (1.0f / CDIM) - mean * mean;
    const float inv = rsqrtf(var + 1e-5f);
#pragma unroll
    for (int i = 0; i < 3; i++) {
        int idx = tid + i * 256;
        out[(size_t)row * CDIM + idx] = (v[i] - mean) * inv * g[idx] + be[idx];
    }
}

// ---------------- launch ----------------------------------------------------
extern "C" void kernel_launch(void* const* d_in, const int* in_sizes, int n_in,
                              void* d_out, int out_size)
{
    const float* x     = (const float*)d_in[0];
    const float* Wq    = (const float*)d_in[1];
    const float* bq    = (const float*)d_in[2];
    const float* Wk    = (const float*)d_in[3];
    const float* bk    = (const float*)d_in[4];
    const float* Wv    = (const float*)d_in[5];
    const float* bv    = (const float*)d_in[6];
    const float* Wo    = (const float*)d_in[7];
    const float* bo    = (const float*)d_in[8];
    const float* ln1g  = (const float*)d_in[9];
    const float* ln1b  = (const float*)d_in[10];
    const float* W1    = (const float*)d_in[11];
    const float* b1    = (const float*)d_in[12];
    const float* W2    = (const float*)d_in[13];
    const float* b2    = (const float*)d_in[14];
    const float* ln2g  = (const float*)d_in[15];
    const float* ln2b  = (const float*)d_in[16];
    float* y = (float*)d_out;

    float *q, *k, *v, *attn, *proj, *h, *m1, *m2;
    cudaGetSymbolAddress((void**)&q,    g_q);
    cudaGetSymbolAddress((void**)&k,    g_k);
    cudaGetSymbolAddress((void**)&v,    g_v);
    cudaGetSymbolAddress((void**)&attn, g_attn);
    cudaGetSymbolAddress((void**)&proj, g_proj);
    cudaGetSymbolAddress((void**)&h,    g_h);
    cudaGetSymbolAddress((void**)&m1,   g_mlp1);
    cudaGetSymbolAddress((void**)&m2,   g_mlp2);

    dim3 blk(256);
    dim3 grid_cc(CDIM / 128, SEQ / 128);   // (6,32)
    dim3 grid_cf(FDIM / 128, SEQ / 128);   // (24,32)

    // QKV projections
    gemm_tf32<false><<<grid_cc, blk>>>(x, Wq, bq, q, SEQ, CDIM, CDIM);
    gemm_tf32<false><<<grid_cc, blk>>>(x, Wk, bk, k, SEQ, CDIM, CDIM);
    gemm_tf32<false><<<grid_cc, blk>>>(x, Wv, bv, v, SEQ, CDIM, CDIM);

    // causal attention
    flash_attn<<<dim3(SEQ / 128, NH), 128>>>(q, k, v, attn);

    // output projection
    gemm_tf32<false><<<grid_cc, blk>>>(attn, Wo, bo, proj, SEQ, CDIM, CDIM);

    // h = LN(x + proj)
    add_ln<<<SEQ, 256>>>(x, proj, ln1g, ln1b, h);

    // MLP
    gemm_tf32<true><<<grid_cf, blk>>>(h, W1, b1, m1, SEQ, FDIM, CDIM);
    gemm_tf32<false><<<grid_cc, blk>>>(m1, W2, b2, m2, SEQ, CDIM, FDIM);

    // y = LN(h + mlp)
    add_ln<<<SEQ, 256>>>(h, m2, ln2g, ln2b, y);

    (void)in_sizes; (void)n_in; (void)out_size;
}

// round 3
// speedup vs baseline: 2.6812x; 2.1761x over previous
#include <cuda_runtime.h>
#include <cuda_bf16.h>
#include <math.h>

#define SEQ 4096
#define CDIM 768
#define NH 12
#define HD 64
#define FDIM 3072

__device__ float g_q[SEQ * CDIM];
__device__ float g_k[SEQ * CDIM];
__device__ float g_v[SEQ * CDIM];
__device__ float g_attn[SEQ * CDIM];
__device__ float g_proj[SEQ * CDIM];
__device__ float g_h[SEQ * CDIM];
__device__ float g_mlp1[SEQ * FDIM];
__device__ float g_mlp2[SEQ * CDIM];

__device__ __forceinline__ unsigned f2tf32(float f) {
    unsigned u;
    asm("cvt.rna.tf32.f32 %0, %1;" : "=r"(u) : "f"(f));
    return u;
}

template <bool GELU>
__global__ __launch_bounds__(256) void gemm_tf32(
    const float* __restrict__ A, const float* __restrict__ B,
    const float* __restrict__ bias, float* __restrict__ C,
    int M, int N, int K)
{
    constexpr int BM = 128, BN = 128, BK = 32;
    __shared__ unsigned As[BK][BM + 4];
    __shared__ unsigned Bs[BK][BN + 4];

    const int tid  = threadIdx.x;
    const int lane = tid & 31;
    const int warp = tid >> 5;
    const int wm = warp & 3;
    const int wn = warp >> 2;
    const int g  = lane >> 2;
    const int t  = lane & 3;

    const int bx = blockIdx.x, by = blockIdx.y;

    const int arow  = tid >> 1;
    const int akseg = (tid & 1) * 16;
    const int brow = tid >> 3;
    const int bnb  = (tid & 7) * 16;

    const float* Ap = A + (size_t)(by * BM + arow) * K + akseg;
    const float* Bp = B + (size_t)brow * N + (size_t)bx * BN + bnb;

    float a_st[16], b_st[16];

#pragma unroll
    for (int i = 0; i < 4; i++) {
        float4 v = *reinterpret_cast<const float4*>(Ap + 4 * i);
        a_st[4 * i + 0] = v.x; a_st[4 * i + 1] = v.y;
        a_st[4 * i + 2] = v.z; a_st[4 * i + 3] = v.w;
    }
#pragma unroll
    for (int i = 0; i < 4; i++) {
        float4 v = *reinterpret_cast<const float4*>(Bp + 4 * i);
        b_st[4 * i + 0] = v.x; b_st[4 * i + 1] = v.y;
        b_st[4 * i + 2] = v.z; b_st[4 * i + 3] = v.w;
    }

    float acc[2][8][4] = {};

    const int niter = K / BK;
    for (int it = 0; it < niter; it++) {
#pragma unroll
        for (int i = 0; i < 16; i++)
            As[akseg + i][arow] = f2tf32(a_st[i]);
#pragma unroll
        for (int i = 0; i < 4; i++) {
            uint4 u;
            u.x = f2tf32(b_st[4 * i + 0]);
            u.y = f2tf32(b_st[4 * i + 1]);
            u.z = f2tf32(b_st[4 * i + 2]);
            u.w = f2tf32(b_st[4 * i + 3]);
            *reinterpret_cast<uint4*>(&Bs[brow][bnb + 4 * i]) = u;
        }
        __syncthreads();

        if (it + 1 < niter) {
            Ap += BK;
            Bp += (size_t)BK * N;
#pragma unroll
            for (int i = 0; i < 4; i++) {
                float4 v = *reinterpret_cast<const float4*>(Ap + 4 * i);
                a_st[4 * i + 0] = v.x; a_st[4 * i + 1] = v.y;
                a_st[4 * i + 2] = v.z; a_st[4 * i + 3] = v.w;
            }
#pragma unroll
            for (int i = 0; i < 4; i++) {
                float4 v = *reinterpret_cast<const float4*>(Bp + 4 * i);
                b_st[4 * i + 0] = v.x; b_st[4 * i + 1] = v.y;
                b_st[4 * i + 2] = v.z; b_st[4 * i + 3] = v.w;
            }
        }

#pragma unroll
        for (int ks = 0; ks < 4; ks++) {
            const int k8 = ks * 8;
            unsigned af[2][4], bf[8][2];
#pragma unroll
            for (int mt = 0; mt < 2; mt++) {
                const int mb = wm * 32 + mt * 16;
                af[mt][0] = As[k8 + t][mb + g];
                af[mt][1] = As[k8 + t][mb + g + 8];
                af[mt][2] = As[k8 + t + 4][mb + g];
                af[mt][3] = As[k8 + t + 4][mb + g + 8];
            }
#pragma unroll
            for (int nt = 0; nt < 8; nt++) {
                const int nb = wn * 64 + nt * 8;
                bf[nt][0] = Bs[k8 + t][nb + g];
                bf[nt][1] = Bs[k8 + t + 4][nb + g];
            }
#pragma unroll
            for (int mt = 0; mt < 2; mt++)
#pragma unroll
                for (int nt = 0; nt < 8; nt++)
                    asm volatile(
                        "mma.sync.aligned.m16n8k8.row.col.f32.tf32.tf32.f32 "
                        "{%0,%1,%2,%3},{%4,%5,%6,%7},{%8,%9},{%0,%1,%2,%3};"
                        : "+f"(acc[mt][nt][0]), "+f"(acc[mt][nt][1]),
                          "+f"(acc[mt][nt][2]), "+f"(acc[mt][nt][3])
                        : "r"(af[mt][0]), "r"(af[mt][1]), "r"(af[mt][2]), "r"(af[mt][3]),
                          "r"(bf[nt][0]), "r"(bf[nt][1]));
        }
        __syncthreads();
    }

#pragma unroll
    for (int mt = 0; mt < 2; mt++) {
        const int r0 = by * BM + wm * 32 + mt * 16 + g;
#pragma unroll
        for (int nt = 0; nt < 8; nt++) {
            const int c0 = bx * BN + wn * 64 + nt * 8 + t * 2;
            const float bz0 = bias[c0], bz1 = bias[c0 + 1];
            float v0 = acc[mt][nt][0] + bz0;
            float v1 = acc[mt][nt][1] + bz1;
            float v2 = acc[mt][nt][2] + bz0;
            float v3 = acc[mt][nt][3] + bz1;
            if (GELU) {
                v0 = 0.5f * v0 * (1.0f + erff(v0 * 0.70710678118654752f));
                v1 = 0.5f * v1 * (1.0f + erff(v1 * 0.70710678118654752f));
                v2 = 0.5f * v2 * (1.0f + erff(v2 * 0.70710678118654752f));
                v3 = 0.5f * v3 * (1.0f + erff(v3 * 0.70710678118654752f));
            }
            *reinterpret_cast<float2*>(C + (size_t)r0 * N + c0) = make_float2(v0, v1);
            *reinterpret_cast<float2*>(C + (size_t)(r0 + 8) * N + c0) = make_float2(v2, v3);
        }
    }
}

__global__ __launch_bounds__(256) void flash_attn_mma(
    const float* __restrict__ Q, const float* __restrict__ K,
    const float* __restrict__ V, float* __restrict__ O)
{
    constexpr int D = HD;
    __shared__ unsigned Ks[64][D + 4];
    __shared__ unsigned Vs[64][D + 4];

    const int h  = blockIdx.y;
    const int qb = blockIdx.x;
    const int tid  = threadIdx.x;
    const int lane = tid & 31;
    const int w = tid >> 5;
    const int g = lane >> 2;
    const int t = lane & 3;

    const int r0 = qb * 128 + w * 16 + g;
    const int r1 = r0 + 8;

    unsigned qf[8][4];
    {
        const float* q0p = Q + (size_t)r0 * CDIM + h * D;
        const float* q1p = Q + (size_t)r1 * CDIM + h * D;
#pragma unroll
        for (int kk = 0; kk < 8; kk++) {
            qf[kk][0] = f2tf32(q0p[kk * 8 + t] * 0.125f);
            qf[kk][1] = f2tf32(q1p[kk * 8 + t] * 0.125f);
            qf[kk][2] = f2tf32(q0p[kk * 8 + t + 4] * 0.125f);
            qf[kk][3] = f2tf32(q1p[kk * 8 + t + 4] * 0.125f);
        }
    }

    float o[8][4] = {};
    float m0 = -1e30f, m1 = -1e30f, l0 = 0.f, l1 = 0.f;

    const int krow = tid >> 2;
    const int kcol = (tid & 3) * 16;
    const int ntiles = 2 * (qb + 1);

    for (int kb = 0; kb < ntiles; kb++) {
        {
            const float* kp = K + (size_t)(kb * 64 + krow) * CDIM + h * D + kcol;
            const float* vp = V + (size_t)(kb * 64 + krow) * CDIM + h * D + kcol;
#pragma unroll
            for (int i = 0; i < 4; i++) {
                float4 kv = *reinterpret_cast<const float4*>(kp + 4 * i);
                Ks[krow][kcol + 4 * i + 0] = f2tf32(kv.x);
                Ks[krow][kcol + 4 * i + 1] = f2tf32(kv.y);
                Ks[krow][kcol + 4 * i + 2] = f2tf32(kv.z);
                Ks[krow][kcol + 4 * i + 3] = f2tf32(kv.w);
                float4 vv = *reinterpret_cast<const float4*>(vp + 4 * i);
                Vs[krow][kcol + 4 * i + 0] = f2tf32(vv.x);
                Vs[krow][kcol + 4 * i + 1] = f2tf32(vv.y);
                Vs[krow][kcol + 4 * i + 2] = f2tf32(vv.z);
                Vs[krow][kcol + 4 * i + 3] = f2tf32(vv.w);
            }
        }
        __syncthreads();

        float s[8][4] = {};
#pragma unroll
        for (int kk = 0; kk < 8; kk++) {
#pragma unroll
            for (int nt = 0; nt < 8; nt++) {
                unsigned b0 = Ks[nt * 8 + g][kk * 8 + t];
                unsigned b1 = Ks[nt * 8 + g][kk * 8 + t + 4];
                asm volatile(
                    "mma.sync.aligned.m16n8k8.row.col.f32.tf32.tf32.f32 "
                    "{%0,%1,%2,%3},{%4,%5,%6,%7},{%8,%9},{%0,%1,%2,%3};"
                    : "+f"(s[nt][0]), "+f"(s[nt][1]), "+f"(s[nt][2]), "+f"(s[nt][3])
                    : "r"(qf[kk][0]), "r"(qf[kk][1]), "r"(qf[kk][2]), "r"(qf[kk][3]),
                      "r"(b0), "r"(b1));
            }
        }

        if (kb >= 2 * qb) {
            const int cb = kb * 64;
#pragma unroll
            for (int nt = 0; nt < 8; nt++) {
                const int c0 = cb + nt * 8 + 2 * t;
                if (c0 > r0)     s[nt][0] = -1e30f;
                if (c0 + 1 > r0) s[nt][1] = -1e30f;
                if (c0 > r1)     s[nt][2] = -1e30f;
                if (c0 + 1 > r1) s[nt][3] = -1e30f;
            }
        }

        float mx0 = -1e30f, mx1 = -1e30f;
#pragma unroll
        for (int nt = 0; nt < 8; nt++) {
            mx0 = fmaxf(mx0, fmaxf(s[nt][0], s[nt][1]));
            mx1 = fmaxf(mx1, fmaxf(s[nt][2], s[nt][3]));
        }
        mx0 = fmaxf(mx0, __shfl_xor_sync(0xffffffffu, mx0, 1));
        mx0 = fmaxf(mx0, __shfl_xor_sync(0xffffffffu, mx0, 2));
        mx1 = fmaxf(mx1, __shfl_xor_sync(0xffffffffu, mx1, 1));
        mx1 = fmaxf(mx1, __shfl_xor_sync(0xffffffffu, mx1, 2));

        const float nm0 = fmaxf(m0, mx0);
        const float nm1 = fmaxf(m1, mx1);
        const float cr0 = __expf(m0 - nm0);
        const float cr1 = __expf(m1 - nm1);
        m0 = nm0; m1 = nm1;

        float sm0 = 0.f, sm1 = 0.f;
#pragma unroll
        for (int nt = 0; nt < 8; nt++) {
            float p0 = __expf(s[nt][0] - nm0);
            float p1 = __expf(s[nt][1] - nm0);
            float p2 = __expf(s[nt][2] - nm1);
            float p3 = __expf(s[nt][3] - nm1);
            s[nt][0] = p0; s[nt][1] = p1; s[nt][2] = p2; s[nt][3] = p3;
            sm0 += p0 + p1;
            sm1 += p2 + p3;
        }
        sm0 += __shfl_xor_sync(0xffffffffu, sm0, 1);
        sm0 += __shfl_xor_sync(0xffffffffu, sm0, 2);
        sm1 += __shfl_xor_sync(0xffffffffu, sm1, 1);
        sm1 += __shfl_xor_sync(0xffffffffu, sm1, 2);
        l0 = l0 * cr0 + sm0;
        l1 = l1 * cr1 + sm1;

#pragma unroll
        for (int nt = 0; nt < 8; nt++) {
            o[nt][0] *= cr0; o[nt][1] *= cr0;
            o[nt][2] *= cr1; o[nt][3] *= cr1;
        }

        unsigned pu[8][4];
#pragma unroll
        for (int nt = 0; nt < 8; nt++) {
            pu[nt][0] = f2tf32(s[nt][0]);
            pu[nt][1] = f2tf32(s[nt][1]);
            pu[nt][2] = f2tf32(s[nt][2]);
            pu[nt][3] = f2tf32(s[nt][3]);
        }

        const int srcA = (g << 2) + (t >> 1);
        const int srcB = srcA + 2;
#pragma unroll
        for (int kk = 0; kk < 8; kk++) {
            unsigned u0 = __shfl_sync(0xffffffffu, pu[kk][0], srcA);
            unsigned u1 = __shfl_sync(0xffffffffu, pu[kk][1], srcA);
            unsigned a0 = (t & 1) ? u1 : u0;
            unsigned u2 = __shfl_sync(0xffffffffu, pu[kk][0], srcB);
            unsigned u3 = __shfl_sync(0xffffffffu, pu[kk][1], srcB);
            unsigned a2 = (t & 1) ? u3 : u2;
            unsigned u4 = __shfl_sync(0xffffffffu, pu[kk][2], srcA);
            unsigned u5 = __shfl_sync(0xffffffffu, pu[kk][3], srcA);
            unsigned a1 = (t & 1) ? u5 : u4;
            unsigned u6 = __shfl_sync(0xffffffffu, pu[kk][2], srcB);
            unsigned u7 = __shfl_sync(0xffffffffu, pu[kk][3], srcB);
            unsigned a3 = (t & 1) ? u7 : u6;
#pragma unroll
            for (int nt = 0; nt < 8; nt++) {
                unsigned b0 = Vs[kk * 8 + t][nt * 8 + g];
                unsigned b1 = Vs[kk * 8 + t + 4][nt * 8 + g];
                asm volatile(
                    "mma.sync.aligned.m16n8k8.row.col.f32.tf32.tf32.f32 "
                    "{%0,%1,%2,%3},{%4,%5,%6,%7},{%8,%9},{%0,%1,%2,%3};"
                    : "+f"(o[nt][0]), "+f"(o[nt][1]), "+f"(o[nt][2]), "+f"(o[nt][3])
                    : "r"(a0), "r"(a1), "r"(a2), "r"(a3),
                      "r"(b0), "r"(b1));
            }
        }
        __syncthreads();
    }

    const float inv0 = 1.f / l0;
    const float inv1 = 1.f / l1;
    float* o0p = O + (size_t)r0 * CDIM + h * D;
    float* o1p = O + (size_t)r1 * CDIM + h * D;
#pragma unroll
    for (int nt = 0; nt < 8; nt++) {
        const int c = nt * 8 + 2 * t;
        *reinterpret_cast<float2*>(o0p + c) = make_float2(o[nt][0] * inv0, o[nt][1] * inv0);
        *reinterpret_cast<float2*>(o1p + c) = make_float2(o[nt][2] * inv1, o[nt][3] * inv1);
    }
}

__global__ __launch_bounds__(256) void add_ln(
    const float* __restrict__ A, const float* __restrict__ Bb,
    const float* __restrict__ g, const float* __restrict__ be,
    float* __restrict__ out)
{
    const int row = blockIdx.x;
    const int tid = threadIdx.x;
    const float* pa = A + (size_t)row * CDIM;
    const float* pb = Bb + (size_t)row * CDIM;

    float v[3];
    float s = 0.f, sq = 0.f;
#pragma unroll
    for (int i = 0; i < 3; i++) {
        int idx = tid + i * 256;
        v[i] = pa[idx] + pb[idx];
        s += v[i];
        sq += v[i] * v[i];
    }
#pragma unroll
    for (int off = 16; off; off >>= 1) {
        s += __shfl_xor_sync(0xffffffffu, s, off);
        sq += __shfl_xor_sync(0xffffffffu, sq, off);
    }
    __shared__ float ss[8], ssq[8];
    int w = tid >> 5, lane = tid & 31;
    if (lane == 0) { ss[w] = s; ssq[w] = sq; }
    __syncthreads();
    if (tid < 32) {
        s = (tid < 8) ? ss[tid] : 0.f;
        sq = (tid < 8) ? ssq[tid] : 0.f;
#pragma unroll
        for (int off = 4; off; off >>= 1) {
            s += __shfl_xor_sync(0xffffffffu, s, off);
            sq += __shfl_xor_sync(0xffffffffu, sq, off);
        }
        if (tid == 0) { ss[0] = s; ssq[0] = sq; }
    }
    __syncthreads();
    const float mean = ss[0] * (1.0f / CDIM);
    const float var = ssq[0] * (1.0f / CDIM) - mean * mean;
    const float inv = rsqrtf(var + 1e-5f);
#pragma unroll
    for (int i = 0; i < 3; i++) {
        int idx = tid + i * 256;
        out[(size_t)row * CDIM + idx] = (v[i] - mean) * inv * g[idx] + be[idx];
    }
}

extern "C" void kernel_launch(void* const* d_in, const int* in_sizes, int n_in,
                              void* d_out, int out_size)
{
    const float* x     = (const float*)d_in[0];
    const float* Wq    = (const float*)d_in[1];
    const float* bq    = (const float*)d_in[2];
    const float* Wk    = (const float*)d_in[3];
    const float* bk    = (const float*)d_in[4];
    const float* Wv    = (const float*)d_in[5];
    const float* bv    = (const float*)d_in[6];
    const float* Wo    = (const float*)d_in[7];
    const float* bo    = (const float*)d_in[8];
    const float* ln1g  = (const float*)d_in[9];
    const float* ln1b  = (const float*)d_in[10];
    const float* W1    = (const float*)d_in[11];
    const float* b1    = (const float*)d_in[12];
    const float* W2    = (const float*)d_in[13];
    const float* b2    = (const float*)d_in[14];
    const float* ln2g  = (const float*)d_in[15];
    const float* ln2b  = (const float*)d_in[16];
    float* y = (float*)d_out;

    float *q, *k, *v, *attn, *proj, *h, *m1, *m2;
    cudaGetSymbolAddress((void**)&q,    g_q);
    cudaGetSymbolAddress((void**)&k,    g_k);
    cudaGetSymbolAddress((void**)&v,    g_v);
    cudaGetSymbolAddress((void**)&attn, g_attn);
    cudaGetSymbolAddress((void**)&proj, g_proj);
    cudaGetSymbolAddress((void**)&h,    g_h);
    cudaGetSymbolAddress((void**)&m1,   g_mlp1);
    cudaGetSymbolAddress((void**)&m2,   g_mlp2);

    dim3 blk(256);
    dim3 grid_cc(CDIM / 128, SEQ / 128);
    dim3 grid_cf(FDIM / 128, SEQ / 128);

    gemm_tf32<false><<<grid_cc, blk>>>(x, Wq, bq, q, SEQ, CDIM, CDIM);
    gemm_tf32<false><<<grid_cc, blk>>>(x, Wk, bk, k, SEQ, CDIM, CDIM);
    gemm_tf32<false><<<grid_cc, blk>>>(x, Wv, bv, v, SEQ, CDIM, CDIM);

    flash_attn_mma<<<dim3(SEQ / 128, NH), 256>>>(q, k, v, attn);

    gemm_tf32<false><<<grid_cc, blk>>>(attn, Wo, bo, proj, SEQ, CDIM, CDIM);
    add_ln<<<SEQ, 256>>>(x, proj, ln1g, ln1b, h);
    gemm_tf32<true><<<grid_cf, blk>>>(h, W1, b1, m1, SEQ, FDIM, CDIM);
    gemm_tf32<false><<<grid_cc, blk>>>(m1, W2, b2, m2, SEQ, CDIM, FDIM);
    add_ln<<<SEQ, 256>>>(h, m2, ln2g, ln2b, y);

    (void)in_sizes; (void)n_in; (void)out_size;
}

// round 5
// speedup vs baseline: 3.5653x; 1.3298x over previous
#include <cuda_runtime.h>
#include <cuda_bf16.h>
#include <math.h>
#include <cstdint>
#include <stdint.h>

#define SEQ 4096
#define CDIM 768
#define NH 12
#define HD 64
#define FDIM 3072

// ---------------- scratch (device globals; no allocation allowed) ----------
__device__ float g_q[SEQ * CDIM];
__device__ float g_k[SEQ * CDIM];
__device__ float g_v[SEQ * CDIM];
__device__ float g_attn[SEQ * CDIM];
__device__ float g_proj[SEQ * CDIM];
__device__ float g_h[SEQ * CDIM];
__device__ float g_ht[SEQ * CDIM];      // tf32-rounded copy of h
__device__ float g_mlp1[SEQ * FDIM];
__device__ float g_mlp2[SEQ * CDIM];
__device__ float g_xt[SEQ * CDIM];      // tf32-rounded x
__device__ float g_wq[CDIM * CDIM];
__device__ float g_wk[CDIM * CDIM];
__device__ float g_wv[CDIM * CDIM];
__device__ float g_wo[CDIM * CDIM];
__device__ float g_w1[CDIM * FDIM];
__device__ float g_w2[FDIM * CDIM];

__device__ __forceinline__ unsigned f2tf32(float f) {
    unsigned u;
    asm("cvt.rna.tf32.f32 %0, %1;" : "=r"(u) : "f"(f));
    return u;
}

__device__ __forceinline__ void cp16(unsigned int dst, const float* src) {
    asm volatile("cp.async.cg.shared.global [%0], [%1], 16;" :: "r"(dst), "l"(src));
}

// ---------------- tf32 rounding convert ------------------------------------
__global__ __launch_bounds__(256) void cvt_tf32_kernel(
    const float* __restrict__ in, float* __restrict__ out, int n)
{
    int i = (blockIdx.x * 256 + threadIdx.x) * 4;
    if (i < n) {
        float4 v = *reinterpret_cast<const float4*>(in + i);
        uint4 u;
        u.x = f2tf32(v.x); u.y = f2tf32(v.y);
        u.z = f2tf32(v.z); u.w = f2tf32(v.w);
        *reinterpret_cast<uint4*>(out + i) = u;
    }
}

// ---------------- cp.async double-buffered tf32 GEMM ------------------------
// A, B must be pre-rounded to tf32 (low mantissa bits zero). C[M,N]=A@B+bias.
// BM=BN=128, BK=32, 256 thr = 8 warps (4Mx2N), warp tile 32x64, 2 CTAs/SM.
template <bool GELU, bool ROUND>
__device__ __forceinline__ void gemm_body(
    const float* __restrict__ A, const float* __restrict__ B,
    const float* __restrict__ bias, float* __restrict__ C,
    int N, int K, int bx, int by, float* smem)
{
    constexpr int BM = 128, BN = 128, BK = 32;
    constexpr int SA = BK + 4;    // 36: A-frag banks 4g+t, conflict-free
    constexpr int SB = BN + 8;    // 136: B-frag banks 8t+g, conflict-free
    float* As = smem;                       // [2][BM][SA]
    float* Bs = smem + 2 * BM * SA;         // [2][BK][SB]

    const int tid = threadIdx.x, lane = tid & 31, warp = tid >> 5;
    const int wm = warp & 3, wn = warp >> 2, g = lane >> 2, t = lane & 3;

    const int arow = tid >> 1, acol = (tid & 1) * 16;   // 2 thr/row, 64B each
    const int brow = tid >> 3, bcol = (tid & 7) * 16;   // 8 thr/row, 64B each

    const float* Apt = A + (size_t)(by * BM + arow) * K + acol;
    const float* Bpt = B + (size_t)brow * N + (size_t)bx * BN + bcol;

    const unsigned int sA = (unsigned int)__cvta_generic_to_shared(As + arow * SA + acol);
    const unsigned int sB = (unsigned int)__cvta_generic_to_shared(Bs + brow * SB + bcol);
    const unsigned int bufA = BM * SA * 4, bufB = BK * SB * 4;

#pragma unroll
    for (int i = 0; i < 4; i++) cp16(sA + i * 16, Apt + 4 * i);
#pragma unroll
    for (int i = 0; i < 4; i++) cp16(sB + i * 16, Bpt + 4 * i);
    asm volatile("cp.async.commit_group;");

    float acc[2][8][4] = {};
    const int nit = K / BK;
    int buf = 0;

    for (int it = 0; it < nit; it++) {
        asm volatile("cp.async.wait_group 0;");
        __syncthreads();
        if (it + 1 < nit) {
            const float* An = Apt + (it + 1) * BK;
            const float* Bn = Bpt + (size_t)(it + 1) * BK * N;
            const unsigned int dA = sA + (buf ^ 1) * bufA;
            const unsigned int dB = sB + (buf ^ 1) * bufB;
#pragma unroll
            for (int i = 0; i < 4; i++) cp16(dA + i * 16, An + 4 * i);
#pragma unroll
            for (int i = 0; i < 4; i++) cp16(dB + i * 16, Bn + 4 * i);
            asm volatile("cp.async.commit_group;");
        }
        const float* Ab = As + buf * BM * SA;
        const float* Bb = Bs + buf * BK * SB;

#pragma unroll
        for (int ks = 0; ks < 4; ks++) {
            const int k8 = ks * 8;
            unsigned af[2][4], bf[8][2];
#pragma unroll
            for (int mt = 0; mt < 2; mt++) {
                const int mb = wm * 32 + mt * 16;
                af[mt][0] = __float_as_uint(Ab[(mb + g) * SA + k8 + t]);
                af[mt][1] = __float_as_uint(Ab[(mb + g + 8) * SA + k8 + t]);
                af[mt][2] = __float_as_uint(Ab[(mb + g) * SA + k8 + t + 4]);
                af[mt][3] = __float_as_uint(Ab[(mb + g + 8) * SA + k8 + t + 4]);
            }
#pragma unroll
            for (int nt = 0; nt < 8; nt++) {
                const int nb = wn * 64 + nt * 8;
                bf[nt][0] = __float_as_uint(Bb[(k8 + t) * SB + nb + g]);
                bf[nt][1] = __float_as_uint(Bb[(k8 + t + 4) * SB + nb + g]);
            }
#pragma unroll
            for (int mt = 0; mt < 2; mt++)
#pragma unroll
                for (int nt = 0; nt < 8; nt++)
                    asm volatile(
                        "mma.sync.aligned.m16n8k8.row.col.f32.tf32.tf32.f32 "
                        "{%0,%1,%2,%3},{%4,%5,%6,%7},{%8,%9},{%0,%1,%2,%3};"
                        : "+f"(acc[mt][nt][0]), "+f"(acc[mt][nt][1]),
                          "+f"(acc[mt][nt][2]), "+f"(acc[mt][nt][3])
                        : "r"(af[mt][0]), "r"(af[mt][1]), "r"(af[mt][2]), "r"(af[mt][3]),
                          "r"(bf[nt][0]), "r"(bf[nt][1]));
        }
        buf ^= 1;
    }

#pragma unroll
    for (int mt = 0; mt < 2; mt++) {
        const int r0 = by * BM + wm * 32 + mt * 16 + g;
#pragma unroll
        for (int nt = 0; nt < 8; nt++) {
            const int c0 = bx * BN + wn * 64 + nt * 8 + t * 2;
            const float bz0 = bias[c0], bz1 = bias[c0 + 1];
            float v0 = acc[mt][nt][0] + bz0;
            float v1 = acc[mt][nt][1] + bz1;
            float v2 = acc[mt][nt][2] + bz0;
            float v3 = acc[mt][nt][3] + bz1;
            if (GELU) {
                v0 = 0.5f * v0 * (1.0f + erff(v0 * 0.70710678118654752f));
                v1 = 0.5f * v1 * (1.0f + erff(v1 * 0.70710678118654752f));
                v2 = 0.5f * v2 * (1.0f + erff(v2 * 0.70710678118654752f));
                v3 = 0.5f * v3 * (1.0f + erff(v3 * 0.70710678118654752f));
            }
            if (ROUND) {
                v0 = __uint_as_float(f2tf32(v0));
                v1 = __uint_as_float(f2tf32(v1));
                v2 = __uint_as_float(f2tf32(v2));
                v3 = __uint_as_float(f2tf32(v3));
            }
            *reinterpret_cast<float2*>(C + (size_t)r0 * N + c0) = make_float2(v0, v1);
            *reinterpret_cast<float2*>(C + (size_t)(r0 + 8) * N + c0) = make_float2(v2, v3);
        }
    }
}

template <bool GELU, bool ROUND>
__global__ __launch_bounds__(256, 2) void gemm_k(
    const float* __restrict__ A, const float* __restrict__ B,
    const float* __restrict__ bias, float* __restrict__ C, int N, int K)
{
    extern __shared__ float smem[];
    gemm_body<GELU, ROUND>(A, B, bias, C, N, K, blockIdx.x, blockIdx.y, smem);
}

// fused QKV: bx 0..17 -> which matrix (bx/6) and its column tile (bx%6)
__global__ __launch_bounds__(256, 2) void gemm_qkv(
    const float* __restrict__ X,
    const float* __restrict__ Wq, const float* __restrict__ Wk, const float* __restrict__ Wv,
    const float* __restrict__ bq, const float* __restrict__ bk, const float* __restrict__ bv,
    float* __restrict__ q, float* __restrict__ k, float* __restrict__ v)
{
    extern __shared__ float smem[];
    const int which = blockIdx.x / 6;
    const int bx = blockIdx.x % 6;
    const float* B   = (which == 0) ? Wq : (which == 1) ? Wk : Wv;
    const float* bias= (which == 0) ? bq : (which == 1) ? bk : bv;
    float* C         = (which == 0) ? q  : (which == 1) ? k  : v;
    gemm_body<false, true>(X, B, bias, C, CDIM, CDIM, bx, blockIdx.y, smem);
}

// ---------------- tensor-core causal flash attention (tf32 mma) -------------
__global__ __launch_bounds__(256, 2) void flash_attn_mma(
    const float* __restrict__ Q, const float* __restrict__ K,
    const float* __restrict__ V, float* __restrict__ O)
{
    constexpr int D = HD;
    __shared__ unsigned Ks[64][D + 4];
    __shared__ unsigned Vs[64][D + 4];

    const int h  = blockIdx.y;
    const int qb = (gridDim.x - 1) - blockIdx.x;   // heavy blocks first
    const int tid  = threadIdx.x;
    const int lane = tid & 31;
    const int w = tid >> 5;
    const int g = lane >> 2;
    const int t = lane & 3;

    const int r0 = qb * 128 + w * 16 + g;
    const int r1 = r0 + 8;

    // Q already tf32-rounded; *0.125f (power of 2) preserves tf32 form
    unsigned qf[8][4];
    {
        const float* q0p = Q + (size_t)r0 * CDIM + h * D;
        const float* q1p = Q + (size_t)r1 * CDIM + h * D;
#pragma unroll
        for (int kk = 0; kk < 8; kk++) {
            qf[kk][0] = __float_as_uint(q0p[kk * 8 + t] * 0.125f);
            qf[kk][1] = __float_as_uint(q1p[kk * 8 + t] * 0.125f);
            qf[kk][2] = __float_as_uint(q0p[kk * 8 + t + 4] * 0.125f);
            qf[kk][3] = __float_as_uint(q1p[kk * 8 + t + 4] * 0.125f);
        }
    }

    float o[8][4] = {};
    float m0 = -1e30f, m1 = -1e30f, l0 = 0.f, l1 = 0.f;

    const int krow = tid >> 2;
    const int kcol = (tid & 3) * 16;
    const int ntiles = 2 * (qb + 1);

    for (int kb = 0; kb < ntiles; kb++) {
        {
            const float* kp = K + (size_t)(kb * 64 + krow) * CDIM + h * D + kcol;
            const float* vp = V + (size_t)(kb * 64 + krow) * CDIM + h * D + kcol;
#pragma unroll
            for (int i = 0; i < 4; i++) {
                float4 kv = *reinterpret_cast<const float4*>(kp + 4 * i);
                Ks[krow][kcol + 4 * i + 0] = __float_as_uint(kv.x);
                Ks[krow][kcol + 4 * i + 1] = __float_as_uint(kv.y);
                Ks[krow][kcol + 4 * i + 2] = __float_as_uint(kv.z);
                Ks[krow][kcol + 4 * i + 3] = __float_as_uint(kv.w);
                float4 vv = *reinterpret_cast<const float4*>(vp + 4 * i);
                Vs[krow][kcol + 4 * i + 0] = __float_as_uint(vv.x);
                Vs[krow][kcol + 4 * i + 1] = __float_as_uint(vv.y);
                Vs[krow][kcol + 4 * i + 2] = __float_as_uint(vv.z);
                Vs[krow][kcol + 4 * i + 3] = __float_as_uint(vv.w);
            }
        }
        __syncthreads();

        float s[8][4] = {};
#pragma unroll
        for (int kk = 0; kk < 8; kk++) {
#pragma unroll
            for (int nt = 0; nt < 8; nt++) {
                unsigned b0 = Ks[nt * 8 + g][kk * 8 + t];
                unsigned b1 = Ks[nt * 8 + g][kk * 8 + t + 4];
                asm volatile(
                    "mma.sync.aligned.m16n8k8.row.col.f32.tf32.tf32.f32 "
                    "{%0,%1,%2,%3},{%4,%5,%6,%7},{%8,%9},{%0,%1,%2,%3};"
                    : "+f"(s[nt][0]), "+f"(s[nt][1]), "+f"(s[nt][2]), "+f"(s[nt][3])
                    : "r"(qf[kk][0]), "r"(qf[kk][1]), "r"(qf[kk][2]), "r"(qf[kk][3]),
                      "r"(b0), "r"(b1));
            }
        }

        if (kb >= 2 * qb) {
            const int cb = kb * 64;
#pragma unroll
            for (int nt = 0; nt < 8; nt++) {
                const int c0 = cb + nt * 8 + 2 * t;
                if (c0 > r0)     s[nt][0] = -1e30f;
                if (c0 + 1 > r0) s[nt][1] = -1e30f;
                if (c0 > r1)     s[nt][2] = -1e30f;
                if (c0 + 1 > r1) s[nt][3] = -1e30f;
            }
        }

        float mx0 = -1e30f, mx1 = -1e30f;
#pragma unroll
        for (int nt = 0; nt < 8; nt++) {
            mx0 = fmaxf(mx0, fmaxf(s[nt][0], s[nt][1]));
            mx1 = fmaxf(mx1, fmaxf(s[nt][2], s[nt][3]));
        }
        mx0 = fmaxf(mx0, __shfl_xor_sync(0xffffffffu, mx0, 1));
        mx0 = fmaxf(mx0, __shfl_xor_sync(0xffffffffu, mx0, 2));
        mx1 = fmaxf(mx1, __shfl_xor_sync(0xffffffffu, mx1, 1));
        mx1 = fmaxf(mx1, __shfl_xor_sync(0xffffffffu, mx1, 2));

        const float nm0 = fmaxf(m0, mx0);
        const float nm1 = fmaxf(m1, mx1);
        const float cr0 = __expf(m0 - nm0);
        const float cr1 = __expf(m1 - nm1);
        m0 = nm0; m1 = nm1;

        float sm0 = 0.f, sm1 = 0.f;
#pragma unroll
        for (int nt = 0; nt < 8; nt++) {
            float p0 = __expf(s[nt][0] - nm0);
            float p1 = __expf(s[nt][1] - nm0);
            float p2 = __expf(s[nt][2] - nm1);
            float p3 = __expf(s[nt][3] - nm1);
            s[nt][0] = p0; s[nt][1] = p1; s[nt][2] = p2; s[nt][3] = p3;
            sm0 += p0 + p1;
            sm1 += p2 + p3;
        }
        sm0 += __shfl_xor_sync(0xffffffffu, sm0, 1);
        sm0 += __shfl_xor_sync(0xffffffffu, sm0, 2);
        sm1 += __shfl_xor_sync(0xffffffffu, sm1, 1);
        sm1 += __shfl_xor_sync(0xffffffffu, sm1, 2);
        l0 = l0 * cr0 + sm0;
        l1 = l1 * cr1 + sm1;

#pragma unroll
        for (int nt = 0; nt < 8; nt++) {
            o[nt][0] *= cr0; o[nt][1] *= cr0;
            o[nt][2] *= cr1; o[nt][3] *= cr1;
        }

        // P C-frag -> A-frag via quad shuffles (floats), cvt after select
        const int srcA = (g << 2) + (t >> 1);
        const int srcB = srcA + 2;
#pragma unroll
        for (int kk = 0; kk < 8; kk++) {
            float f0 = __shfl_sync(0xffffffffu, s[kk][0], srcA);
            float f1 = __shfl_sync(0xffffffffu, s[kk][1], srcA);
            unsigned a0 = f2tf32((t & 1) ? f1 : f0);
            float f2 = __shfl_sync(0xffffffffu, s[kk][0], srcB);
            float f3 = __shfl_sync(0xffffffffu, s[kk][1], srcB);
            unsigned a2 = f2tf32((t & 1) ? f3 : f2);
            float f4 = __shfl_sync(0xffffffffu, s[kk][2], srcA);
            float f5 = __shfl_sync(0xffffffffu, s[kk][3], srcA);
            unsigned a1 = f2tf32((t & 1) ? f5 : f4);
            float f6 = __shfl_sync(0xffffffffu, s[kk][2], srcB);
            float f7 = __shfl_sync(0xffffffffu, s[kk][3], srcB);
            unsigned a3 = f2tf32((t & 1) ? f7 : f6);
#pragma unroll
            for (int nt = 0; nt < 8; nt++) {
                unsigned b0 = Vs[kk * 8 + t][nt * 8 + g];
                unsigned b1 = Vs[kk * 8 + t + 4][nt * 8 + g];
                asm volatile(
                    "mma.sync.aligned.m16n8k8.row.col.f32.tf32.tf32.f32 "
                    "{%0,%1,%2,%3},{%4,%5,%6,%7},{%8,%9},{%0,%1,%2,%3};"
                    : "+f"(o[nt][0]), "+f"(o[nt][1]), "+f"(o[nt][2]), "+f"(o[nt][3])
                    : "r"(a0), "r"(a1), "r"(a2), "r"(a3),
                      "r"(b0), "r"(b1));
            }
        }
        __syncthreads();
    }

    // write tf32-rounded O (feeds the Wo GEMM)
    const float inv0 = 1.f / l0;
    const float inv1 = 1.f / l1;
    float* o0p = O + (size_t)r0 * CDIM + h * D;
    float* o1p = O + (size_t)r1 * CDIM + h * D;
#pragma unroll
    for (int nt = 0; nt < 8; nt++) {
        const int c = nt * 8 + 2 * t;
        float2 w0 = make_float2(__uint_as_float(f2tf32(o[nt][0] * inv0)),
                                __uint_as_float(f2tf32(o[nt][1] * inv0)));
        float2 w1 = make_float2(__uint_as_float(f2tf32(o[nt][2] * inv1)),
                                __uint_as_float(f2tf32(o[nt][3] * inv1)));
        *reinterpret_cast<float2*>(o0p + c) = w0;
        *reinterpret_cast<float2*>(o1p + c) = w1;
    }
}

// ---------------- fused residual add + LayerNorm ---------------------------
template <bool DUALOUT>
__global__ __launch_bounds__(256) void add_ln(
    const float* __restrict__ A, const float* __restrict__ Bb,
    const float* __restrict__ g, const float* __restrict__ be,
    float* __restrict__ out, float* __restrict__ out_t)
{
    const int row = blockIdx.x;
    const int tid = threadIdx.x;
    const float* pa = A + (size_t)row * CDIM;
    const float* pb = Bb + (size_t)row * CDIM;

    float v[3];
    float s = 0.f, sq = 0.f;
#pragma unroll
    for (int i = 0; i < 3; i++) {
        int idx = tid + i * 256;
        v[i] = pa[idx] + pb[idx];
        s += v[i];
        sq += v[i] * v[i];
    }
#pragma unroll
    for (int off = 16; off; off >>= 1) {
        s += __shfl_xor_sync(0xffffffffu, s, off);
        sq += __shfl_xor_sync(0xffffffffu, sq, off);
    }
    __shared__ float ss[8], ssq[8];
    int w = tid >> 5, lane = tid & 31;
    if (lane == 0) { ss[w] = s; ssq[w] = sq; }
    __syncthreads();
    if (tid < 32) {
        s = (tid < 8) ? ss[tid] : 0.f;
        sq = (tid < 8) ? ssq[tid] : 0.f;
#pragma unroll
        for (int off = 4; off; off >>= 1) {
            s += __shfl_xor_sync(0xffffffffu, s, off);
            sq += __shfl_xor_sync(0xffffffffu, sq, off);
        }
        if (tid == 0) { ss[0] = s; ssq[0] = sq; }
    }
    __syncthreads();
    const float mean = ss[0] * (1.0f / CDIM);
    const float var = ssq[0] * (1.0f / CDIM) - mean * mean;
    const float inv = rsqrtf(var + 1e-5f);
#pragma unroll
    for (int i = 0; i < 3; i++) {
        int idx = tid + i * 256;
        float r = (v[i] - mean) * inv * g[idx] + be[idx];
        out[(size_t)row * CDIM + idx] = r;
        if (DUALOUT)
            out_t[(size_t)row * CDIM + idx] = __uint_as_float(f2tf32(r));
    }
}

// ---------------- launch ----------------------------------------------------
extern "C" void kernel_launch(void* const* d_in, const int* in_sizes, int n_in,
                              void* d_out, int out_size)
{
    const float* x     = (const float*)d_in[0];
    const float* Wq    = (const float*)d_in[1];
    const float* bq    = (const float*)d_in[2];
    const float* Wk    = (const float*)d_in[3];
    const float* bk    = (const float*)d_in[4];
    const float* Wv    = (const float*)d_in[5];
    const float* bv    = (const float*)d_in[6];
    const float* Wo    = (const float*)d_in[7];
    const float* bo    = (const float*)d_in[8];
    const float* ln1g  = (const float*)d_in[9];
    const float* ln1b  = (const float*)d_in[10];
    const float* W1    = (const float*)d_in[11];
    const float* b1    = (const float*)d_in[12];
    const float* W2    = (const float*)d_in[13];
    const float* b2    = (const float*)d_in[14];
    const float* ln2g  = (const float*)d_in[15];
    const float* ln2b  = (const float*)d_in[16];
    float* y = (float*)d_out;

    float *q, *k, *v, *attn, *proj, *h, *ht, *m1, *m2;
    float *xt, *wq, *wk, *wv, *wo, *w1, *w2;
    cudaGetSymbolAddress((void**)&q,    g_q);
    cudaGetSymbolAddress((void**)&k,    g_k);
    cudaGetSymbolAddress((void**)&v,    g_v);
    cudaGetSymbolAddress((void**)&attn, g_attn);
    cudaGetSymbolAddress((void**)&proj, g_proj);
    cudaGetSymbolAddress((void**)&h,    g_h);
    cudaGetSymbolAddress((void**)&ht,   g_ht);
    cudaGetSymbolAddress((void**)&m1,   g_mlp1);
    cudaGetSymbolAddress((void**)&m2,   g_mlp2);
    cudaGetSymbolAddress((void**)&xt,   g_xt);
    cudaGetSymbolAddress((void**)&wq,   g_wq);
    cudaGetSymbolAddress((void**)&wk,   g_wk);
    cudaGetSymbolAddress((void**)&wv,   g_wv);
    cudaGetSymbolAddress((void**)&wo,   g_wo);
    cudaGetSymbolAddress((void**)&w1,   g_w1);
    cudaGetSymbolAddress((void**)&w2,   g_w2);

    const int SMEM_G = (2 * 128 * 36 + 2 * 32 * 136) * 4;   // 71680 bytes
    cudaFuncSetAttribute(gemm_qkv, cudaFuncAttributeMaxDynamicSharedMemorySize, SMEM_G);
    cudaFuncSetAttribute(gemm_k<false, false>, cudaFuncAttributeMaxDynamicSharedMemorySize, SMEM_G);
    cudaFuncSetAttribute(gemm_k<true, true>,   cudaFuncAttributeMaxDynamicSharedMemorySize, SMEM_G);

    // pre-round inputs/weights to tf32 (RNA)
    cvt_tf32_kernel<<<SEQ * CDIM / 1024, 256>>>(x,  xt, SEQ * CDIM);
    cvt_tf32_kernel<<<CDIM * CDIM / 1024, 256>>>(Wq, wq, CDIM * CDIM);
    cvt_tf32_kernel<<<CDIM * CDIM / 1024, 256>>>(Wk, wk, CDIM * CDIM);
    cvt_tf32_kernel<<<CDIM * CDIM / 1024, 256>>>(Wv, wv, CDIM * CDIM);
    cvt_tf32_kernel<<<CDIM * CDIM / 1024, 256>>>(Wo, wo, CDIM * CDIM);
    cvt_tf32_kernel<<<CDIM * FDIM / 1024, 256>>>(W1, w1, CDIM * FDIM);
    cvt_tf32_kernel<<<FDIM * CDIM / 1024, 256>>>(W2, w2, FDIM * CDIM);

    // fused QKV projection (writes tf32-rounded q,k,v)
    gemm_qkv<<<dim3(18, SEQ / 128), 256, SMEM_G>>>(xt, wq, wk, wv, bq, bk, bv, q, k, v);

    // causal attention (writes tf32-rounded attn)
    flash_attn_mma<<<dim3(SEQ / 128, NH), 256>>>(q, k, v, attn);

    // output projection
    gemm_k<false, false><<<dim3(CDIM / 128, SEQ / 128), 256, SMEM_G>>>(attn, wo, bo, proj, CDIM, CDIM);

    // h = LN(x + proj), plus rounded copy for the W1 GEMM
    add_ln<true><<<SEQ, 256>>>(x, proj, ln1g, ln1b, h, ht);

    // MLP
    gemm_k<true, true><<<dim3(FDIM / 128, SEQ / 128), 256, SMEM_G>>>(ht, w1, b1, m1, FDIM, CDIM);
    gemm_k<false, false><<<dim3(CDIM / 128, SEQ / 128), 256, SMEM_G>>>(m1, w2, b2, m2, CDIM, FDIM);

    // y = LN(h + mlp)
    add_ln<false><<<SEQ, 256>>>(h, m2, ln2g, ln2b, y, nullptr);

    (void)in_sizes; (void)n_in; (void)out_size;
}

// round 7
// speedup vs baseline: 6.1955x; 1.7377x over previous
#include <cuda_runtime.h>
#include <cuda_fp16.h>
#include <math.h>
#include <cstdint>
#include <stdint.h>

#define SEQ 4096
#define CDIM 768
#define NH 12
#define HD 64
#define FDIM 3072

// ---------------- scratch (device globals; no allocation allowed) ----------
__device__ __half g_q[SEQ * CDIM];
__device__ __half g_k[SEQ * CDIM];
__device__ __half g_v[SEQ * CDIM];
__device__ __half g_attn[SEQ * CDIM];
__device__ float  g_proj[SEQ * CDIM];
__device__ float  g_h[SEQ * CDIM];
__device__ __half g_hh[SEQ * CDIM];      // half copy of h
__device__ __half g_mlp1[SEQ * FDIM];
__device__ float  g_mlp2[SEQ * CDIM];
__device__ __half g_xh[SEQ * CDIM];      // half x
__device__ __half g_wq[CDIM * CDIM];     // transposed half weights [N,K]
__device__ __half g_wk[CDIM * CDIM];
__device__ __half g_wv[CDIM * CDIM];
__device__ __half g_wo[CDIM * CDIM];
__device__ __half g_w1[FDIM * CDIM];     // W1^T: [F, C]
__device__ __half g_w2[CDIM * FDIM];     // W2^T: [C, F]

__device__ __forceinline__ void cp16(unsigned int dst, const void* src) {
    asm volatile("cp.async.cg.shared.global [%0], [%1], 16;" :: "r"(dst), "l"(src));
}

__device__ __forceinline__ unsigned smem_u32(const void* p) {
    unsigned a;
    asm("{ .reg .u64 t; cvta.to.shared.u64 t, %1; cvt.u32.u64 %0, t; }" : "=r"(a) : "l"(p));
    return a;
}

__device__ __forceinline__ void mma_f16(
    float& d0, float& d1, float& d2, float& d3,
    unsigned a0, unsigned a1, unsigned a2, unsigned a3,
    unsigned b0, unsigned b1)
{
    asm volatile(
        "mma.sync.aligned.m16n8k16.row.col.f32.f16.f16.f32 "
        "{%0,%1,%2,%3},{%4,%5,%6,%7},{%8,%9},{%0,%1,%2,%3};"
        : "+f"(d0), "+f"(d1), "+f"(d2), "+f"(d3)
        : "r"(a0), "r"(a1), "r"(a2), "r"(a3), "r"(b0), "r"(b1));
}

__device__ __forceinline__ unsigned pack_h2(float lo, float hi) {
    __half2 h = __floats2half2_rn(lo, hi);
    return *reinterpret_cast<unsigned*>(&h);
}

// ---------------- float -> half convert -------------------------------------
__global__ __launch_bounds__(256) void cvt_h_kernel(
    const float* __restrict__ in, __half* __restrict__ out, int n)
{
    int i = (blockIdx.x * 256 + threadIdx.x) * 4;
    if (i < n) {
        float4 v = *reinterpret_cast<const float4*>(in + i);
        uint2 u;
        u.x = pack_h2(v.x, v.y);
        u.y = pack_h2(v.z, v.w);
        *reinterpret_cast<uint2*>(out + i) = u;
    }
}

// ---------------- transpose + convert: in[K,N] f32 -> out[N,K] half ---------
__global__ __launch_bounds__(256) void cvt_t_kernel(
    const float* __restrict__ in, __half* __restrict__ out, int K, int N)
{
    __shared__ float t[32][33];
    const int k0 = blockIdx.x * 32, n0 = blockIdx.y * 32;
    const int tx = threadIdx.x & 31, ty = threadIdx.x >> 5;   // 32x8
#pragma unroll
    for (int i = 0; i < 4; i++)
        t[ty + i * 8][tx] = in[(size_t)(k0 + ty + i * 8) * N + n0 + tx];
    __syncthreads();
#pragma unroll
    for (int i = 0; i < 4; i++)
        out[(size_t)(n0 + ty + i * 8) * K + k0 + tx] = __float2half_rn(t[tx][ty + i * 8]);
}

// ---------------- FP16 tensor-core GEMM -------------------------------------
// C[M,N] = A[M,K] @ Bt[N,K]^T + bias.  A, Bt are half. 128x128 tile, BK=64,
// double-buffered cp.async, 256 thr = 8 warps (4Mx2N), warp tile 32x64,
// mma.m16n8k16, 2 CTAs/SM.  Smem rows padded to 72 halves (conflict-free).
template <bool GELU, typename OutT>
__device__ __forceinline__ void gemm_h_body(
    const __half* __restrict__ A, const __half* __restrict__ Bt,
    const float* __restrict__ bias, OutT* __restrict__ C,
    int N, int K, int bx, int by)
{
    constexpr int BK = 64, SR = 72;              // halves
    extern __shared__ __half smh[];
    // layout: As0 [0], Bs0 [9216], As1 [18432], Bs1 [27648]  (halves)
    const unsigned smb = smem_u32(smh);

    const int tid = threadIdx.x, lane = tid & 31, warp = tid >> 5;
    const int wm = warp & 3, wn = warp >> 2, g = lane >> 2, t = lane & 3;

    // loader: 128 rows x 8 x 16B units per tile; 4 units/thread
    const int u0 = tid * 4;
    const __half* Abase = A + (size_t)(by * 128) * K;
    const __half* Bbase = Bt + (size_t)(bx * 128) * K;

    float acc[2][8][4] = {};
    const int nchunks = K / BK;

    // prefetch chunk 0 into buffer 0
    {
#pragma unroll
        for (int j = 0; j < 4; j++) {
            const int u = u0 + j, row = u >> 3, c16 = u & 7;
            const unsigned off = (unsigned)(row * SR + c16 * 8) * 2;
            cp16(smb + off, Abase + (size_t)row * K + c16 * 8);
            cp16(smb + 18432 + off, Bbase + (size_t)row * K + c16 * 8);
        }
        asm volatile("cp.async.commit_group;");
    }

    for (int ch = 0; ch < nchunks; ch++) {
        asm volatile("cp.async.wait_group 0;");
        __syncthreads();
        const int buf = ch & 1;
        if (ch + 1 < nchunks) {
            const int k0 = (ch + 1) * BK;
            const unsigned dst = smb + (buf ^ 1) * 36864;
#pragma unroll
            for (int j = 0; j < 4; j++) {
                const int u = u0 + j, row = u >> 3, c16 = u & 7;
                const unsigned off = (unsigned)(row * SR + c16 * 8) * 2;
                cp16(dst + off, Abase + (size_t)row * K + k0 + c16 * 8);
                cp16(dst + 18432 + off, Bbase + (size_t)row * K + k0 + c16 * 8);
            }
            asm volatile("cp.async.commit_group;");
        }
        const __half* Ab = smh + buf * 18432;
        const __half* Bb = Ab + 9216;

#pragma unroll
        for (int kk = 0; kk < 4; kk++) {
            const int k16 = kk * 16;
            unsigned af[2][4], bf[8][2];
#pragma unroll
            for (int mt = 0; mt < 2; mt++) {
                const int mb = wm * 32 + mt * 16;
                af[mt][0] = *reinterpret_cast<const unsigned*>(&Ab[(mb + g) * SR + k16 + 2 * t]);
                af[mt][1] = *reinterpret_cast<const unsigned*>(&Ab[(mb + g + 8) * SR + k16 + 2 * t]);
                af[mt][2] = *reinterpret_cast<const unsigned*>(&Ab[(mb + g) * SR + k16 + 2 * t + 8]);
                af[mt][3] = *reinterpret_cast<const unsigned*>(&Ab[(mb + g + 8) * SR + k16 + 2 * t + 8]);
            }
#pragma unroll
            for (int nt = 0; nt < 8; nt++) {
                const int nb = wn * 64 + nt * 8;
                bf[nt][0] = *reinterpret_cast<const unsigned*>(&Bb[(nb + g) * SR + k16 + 2 * t]);
                bf[nt][1] = *reinterpret_cast<const unsigned*>(&Bb[(nb + g) * SR + k16 + 2 * t + 8]);
            }
#pragma unroll
            for (int mt = 0; mt < 2; mt++)
#pragma unroll
                for (int nt = 0; nt < 8; nt++)
                    mma_f16(acc[mt][nt][0], acc[mt][nt][1], acc[mt][nt][2], acc[mt][nt][3],
                            af[mt][0], af[mt][1], af[mt][2], af[mt][3],
                            bf[nt][0], bf[nt][1]);
        }
        __syncthreads();
    }

#pragma unroll
    for (int mt = 0; mt < 2; mt++) {
        const int r0 = by * 128 + wm * 32 + mt * 16 + g;
#pragma unroll
        for (int nt = 0; nt < 8; nt++) {
            const int c0 = bx * 128 + wn * 64 + nt * 8 + t * 2;
            const float bz0 = bias[c0], bz1 = bias[c0 + 1];
            float v0 = acc[mt][nt][0] + bz0;
            float v1 = acc[mt][nt][1] + bz1;
            float v2 = acc[mt][nt][2] + bz0;
            float v3 = acc[mt][nt][3] + bz1;
            if (GELU) {
                v0 = 0.5f * v0 * (1.0f + erff(v0 * 0.70710678118654752f));
                v1 = 0.5f * v1 * (1.0f + erff(v1 * 0.70710678118654752f));
                v2 = 0.5f * v2 * (1.0f + erff(v2 * 0.70710678118654752f));
                v3 = 0.5f * v3 * (1.0f + erff(v3 * 0.70710678118654752f));
            }
            if (sizeof(OutT) == 2) {
                __half* Ch = reinterpret_cast<__half*>(C);
                unsigned p0 = pack_h2(v0, v1);
                unsigned p1 = pack_h2(v2, v3);
                *reinterpret_cast<unsigned*>(Ch + (size_t)r0 * N + c0) = p0;
                *reinterpret_cast<unsigned*>(Ch + (size_t)(r0 + 8) * N + c0) = p1;
            } else {
                float* Cf = reinterpret_cast<float*>(C);
                *reinterpret_cast<float2*>(Cf + (size_t)r0 * N + c0) = make_float2(v0, v1);
                *reinterpret_cast<float2*>(Cf + (size_t)(r0 + 8) * N + c0) = make_float2(v2, v3);
            }
        }
    }
}

template <bool GELU, typename OutT>
__global__ __launch_bounds__(256, 2) void gemm_h(
    const __half* __restrict__ A, const __half* __restrict__ Bt,
    const float* __restrict__ bias, OutT* __restrict__ C, int N, int K)
{
    gemm_h_body<GELU, OutT>(A, Bt, bias, C, N, K, blockIdx.x, blockIdx.y);
}

// fused QKV: bx 0..17 -> which matrix (bx/6) and column tile (bx%6)
__global__ __launch_bounds__(256, 2) void gemm_h_qkv(
    const __half* __restrict__ X,
    const __half* __restrict__ WqT, const __half* __restrict__ WkT, const __half* __restrict__ WvT,
    const float* __restrict__ bq, const float* __restrict__ bk, const float* __restrict__ bv,
    __half* __restrict__ q, __half* __restrict__ k, __half* __restrict__ v)
{
    const int which = blockIdx.x / 6;
    const int bx = blockIdx.x % 6;
    const __half* Bt  = (which == 0) ? WqT : (which == 1) ? WkT : WvT;
    const float* bias = (which == 0) ? bq  : (which == 1) ? bk  : bv;
    __half* C         = (which == 0) ? q   : (which == 1) ? k   : v;
    gemm_h_body<false, __half>(X, Bt, bias, C, CDIM, CDIM, bx, blockIdx.y);
}

// ---------------- FP16 tensor-core causal flash attention --------------------
// grid (SEQ/128, NH), 256 thr = 8 warps; warp w owns 16 query rows.
// 64-key tiles; S = Q@K^T and O += P@V via mma.m16n8k16.f16.
// S C-frag is directly the P A-frag (no shuffles).
__global__ __launch_bounds__(256, 2) void flash_attn_h(
    const __half* __restrict__ Q, const __half* __restrict__ K,
    const __half* __restrict__ V, __half* __restrict__ O)
{
    constexpr int D = HD, SR = 72;
    __shared__ __half Ks[64][SR];     // [key][d]
    __shared__ __half Vt[64][SR];     // [d][key]  (transposed)

    const int h  = blockIdx.y;
    const int qb = (gridDim.x - 1) - blockIdx.x;   // heavy blocks first
    const int tid  = threadIdx.x;
    const int lane = tid & 31;
    const int w = tid >> 5;
    const int g = lane >> 2;
    const int t = lane & 3;

    const int r0 = qb * 128 + w * 16 + g;
    const int r1 = r0 + 8;

    // Q A-fragments (4 k16 steps), scaled by 1/8 (exact power of 2)
    unsigned qf[4][4];
    {
        const __half2 sc = __float2half2_rn(0.125f);
        const __half* q0p = Q + (size_t)r0 * CDIM + h * D;
        const __half* q1p = Q + (size_t)r1 * CDIM + h * D;
#pragma unroll
        for (int kk = 0; kk < 4; kk++) {
            __half2 x0 = __hmul2(*reinterpret_cast<const __half2*>(q0p + kk * 16 + 2 * t), sc);
            __half2 x1 = __hmul2(*reinterpret_cast<const __half2*>(q1p + kk * 16 + 2 * t), sc);
            __half2 x2 = __hmul2(*reinterpret_cast<const __half2*>(q0p + kk * 16 + 2 * t + 8), sc);
            __half2 x3 = __hmul2(*reinterpret_cast<const __half2*>(q1p + kk * 16 + 2 * t + 8), sc);
            qf[kk][0] = *reinterpret_cast<unsigned*>(&x0);
            qf[kk][1] = *reinterpret_cast<unsigned*>(&x1);
            qf[kk][2] = *reinterpret_cast<unsigned*>(&x2);
            qf[kk][3] = *reinterpret_cast<unsigned*>(&x3);
        }
    }

    float o[8][4] = {};
    float m0 = -1e30f, m1 = -1e30f, l0 = 0.f, l1 = 0.f;

    const int krow = tid >> 2;          // 0..63
    const int kcol = (tid & 3) * 16;    // 0,16,32,48
    const int ntiles = 2 * (qb + 1);

    for (int kb = 0; kb < ntiles; kb++) {
        {
            const __half* kp = K + (size_t)(kb * 64 + krow) * CDIM + h * D + kcol;
            const __half* vp = V + (size_t)(kb * 64 + krow) * CDIM + h * D + kcol;
            // K: contiguous half2 copies into Ks[krow]
#pragma unroll
            for (int i = 0; i < 2; i++) {
                uint4 kv = *reinterpret_cast<const uint4*>(kp + i * 8);
                *reinterpret_cast<uint4*>(&Ks[krow][kcol + i * 8]) = kv;
            }
            // V: transpose into Vt[d][key]
#pragma unroll
            for (int i = 0; i < 16; i++)
                Vt[kcol + i][krow] = vp[i];
        }
        __syncthreads();

        // S = Q @ K^T
        float s[8][4] = {};
#pragma unroll
        for (int kk = 0; kk < 4; kk++) {
            const int k16 = kk * 16;
#pragma unroll
            for (int nt = 0; nt < 8; nt++) {
                unsigned b0 = *reinterpret_cast<const unsigned*>(&Ks[nt * 8 + g][k16 + 2 * t]);
                unsigned b1 = *reinterpret_cast<const unsigned*>(&Ks[nt * 8 + g][k16 + 2 * t + 8]);
                mma_f16(s[nt][0], s[nt][1], s[nt][2], s[nt][3],
                        qf[kk][0], qf[kk][1], qf[kk][2], qf[kk][3], b0, b1);
            }
        }

        if (kb >= 2 * qb) {
            const int cb = kb * 64;
#pragma unroll
            for (int nt = 0; nt < 8; nt++) {
                const int c0 = cb + nt * 8 + 2 * t;
                if (c0 > r0)     s[nt][0] = -1e30f;
                if (c0 + 1 > r0) s[nt][1] = -1e30f;
                if (c0 > r1)     s[nt][2] = -1e30f;
                if (c0 + 1 > r1) s[nt][3] = -1e30f;
            }
        }

        float mx0 = -1e30f, mx1 = -1e30f;
#pragma unroll
        for (int nt = 0; nt < 8; nt++) {
            mx0 = fmaxf(mx0, fmaxf(s[nt][0], s[nt][1]));
            mx1 = fmaxf(mx1, fmaxf(s[nt][2], s[nt][3]));
        }
        mx0 = fmaxf(mx0, __shfl_xor_sync(0xffffffffu, mx0, 1));
        mx0 = fmaxf(mx0, __shfl_xor_sync(0xffffffffu, mx0, 2));
        mx1 = fmaxf(mx1, __shfl_xor_sync(0xffffffffu, mx1, 1));
        mx1 = fmaxf(mx1, __shfl_xor_sync(0xffffffffu, mx1, 2));

        const float nm0 = fmaxf(m0, mx0);
        const float nm1 = fmaxf(m1, mx1);
        const float cr0 = __expf(m0 - nm0);
        const float cr1 = __expf(m1 - nm1);
        m0 = nm0; m1 = nm1;

        float sm0 = 0.f, sm1 = 0.f;
#pragma unroll
        for (int nt = 0; nt < 8; nt++) {
            float p0 = __expf(s[nt][0] - nm0);
            float p1 = __expf(s[nt][1] - nm0);
            float p2 = __expf(s[nt][2] - nm1);
            float p3 = __expf(s[nt][3] - nm1);
            s[nt][0] = p0; s[nt][1] = p1; s[nt][2] = p2; s[nt][3] = p3;
            sm0 += p0 + p1;
            sm1 += p2 + p3;
        }
        sm0 += __shfl_xor_sync(0xffffffffu, sm0, 1);
        sm0 += __shfl_xor_sync(0xffffffffu, sm0, 2);
        sm1 += __shfl_xor_sync(0xffffffffu, sm1, 1);
        sm1 += __shfl_xor_sync(0xffffffffu, sm1, 2);
        l0 = l0 * cr0 + sm0;
        l1 = l1 * cr1 + sm1;

#pragma unroll
        for (int nt = 0; nt < 8; nt++) {
            o[nt][0] *= cr0; o[nt][1] *= cr0;
            o[nt][2] *= cr1; o[nt][3] *= cr1;
        }

        // O += P @ V : S C-frag IS the P A-frag in fp16 (no shuffles)
#pragma unroll
        for (int kk = 0; kk < 4; kk++) {
            unsigned a0 = pack_h2(s[2 * kk][0], s[2 * kk][1]);
            unsigned a1 = pack_h2(s[2 * kk][2], s[2 * kk][3]);
            unsigned a2 = pack_h2(s[2 * kk + 1][0], s[2 * kk + 1][1]);
            unsigned a3 = pack_h2(s[2 * kk + 1][2], s[2 * kk + 1][3]);
            const int k16 = kk * 16;
#pragma unroll
            for (int nt = 0; nt < 8; nt++) {
                unsigned b0 = *reinterpret_cast<const unsigned*>(&Vt[nt * 8 + g][k16 + 2 * t]);
                unsigned b1 = *reinterpret_cast<const unsigned*>(&Vt[nt * 8 + g][k16 + 2 * t + 8]);
                mma_f16(o[nt][0], o[nt][1], o[nt][2], o[nt][3], a0, a1, a2, a3, b0, b1);
            }
        }
        __syncthreads();
    }

    const float inv0 = 1.f / l0;
    const float inv1 = 1.f / l1;
    __half* o0p = O + (size_t)r0 * CDIM + h * D;
    __half* o1p = O + (size_t)r1 * CDIM + h * D;
#pragma unroll
    for (int nt = 0; nt < 8; nt++) {
        const int c = nt * 8 + 2 * t;
        *reinterpret_cast<unsigned*>(o0p + c) = pack_h2(o[nt][0] * inv0, o[nt][1] * inv0);
        *reinterpret_cast<unsigned*>(o1p + c) = pack_h2(o[nt][2] * inv1, o[nt][3] * inv1);
    }
}

// ---------------- fused residual add + LayerNorm ---------------------------
template <bool DUALOUT>
__global__ __launch_bounds__(256) void add_ln(
    const float* __restrict__ A, const float* __restrict__ Bb,
    const float* __restrict__ g, const float* __restrict__ be,
    float* __restrict__ out, __half* __restrict__ out_h)
{
    const int row = blockIdx.x;
    const int tid = threadIdx.x;
    const float* pa = A + (size_t)row * CDIM;
    const float* pb = Bb + (size_t)row * CDIM;

    float v[3];
    float s = 0.f, sq = 0.f;
#pragma unroll
    for (int i = 0; i < 3; i++) {
        int idx = tid + i * 256;
        v[i] = pa[idx] + pb[idx];
        s += v[i];
        sq += v[i] * v[i];
    }
#pragma unroll
    for (int off = 16; off; off >>= 1) {
        s += __shfl_xor_sync(0xffffffffu, s, off);
        sq += __shfl_xor_sync(0xffffffffu, sq, off);
    }
    __shared__ float ss[8], ssq[8];
    int w = tid >> 5, lane = tid & 31;
    if (lane == 0) { ss[w] = s; ssq[w] = sq; }
    __syncthreads();
    if (tid < 32) {
        s = (tid < 8) ? ss[tid] : 0.f;
        sq = (tid < 8) ? ssq[tid] : 0.f;
#pragma unroll
        for (int off = 4; off; off >>= 1) {
            s += __shfl_xor_sync(0xffffffffu, s, off);
            sq += __shfl_xor_sync(0xffffffffu, sq, off);
        }
        if (tid == 0) { ss[0] = s; ssq[0] = sq; }
    }
    __syncthreads();
    const float mean = ss[0] * (1.0f / CDIM);
    const float var = ssq[0] * (1.0f / CDIM) - mean * mean;
    const float inv = rsqrtf(var + 1e-5f);
#pragma unroll
    for (int i = 0; i < 3; i++) {
        int idx = tid + i * 256;
        float r = (v[i] - mean) * inv * g[idx] + be[idx];
        out[(size_t)row * CDIM + idx] = r;
        if (DUALOUT)
            out_h[(size_t)row * CDIM + idx] = __float2half_rn(r);
    }
}

// ---------------- launch ----------------------------------------------------
extern "C" void kernel_launch(void* const* d_in, const int* in_sizes, int n_in,
                              void* d_out, int out_size)
{
    const float* x     = (const float*)d_in[0];
    const float* Wq    = (const float*)d_in[1];
    const float* bq    = (const float*)d_in[2];
    const float* Wk    = (const float*)d_in[3];
    const float* bk    = (const float*)d_in[4];
    const float* Wv    = (const float*)d_in[5];
    const float* bv    = (const float*)d_in[6];
    const float* Wo    = (const float*)d_in[7];
    const float* bo    = (const float*)d_in[8];
    const float* ln1g  = (const float*)d_in[9];
    const float* ln1b  = (const float*)d_in[10];
    const float* W1    = (const float*)d_in[11];
    const float* b1    = (const float*)d_in[12];
    const float* W2    = (const float*)d_in[13];
    const float* b2    = (const float*)d_in[14];
    const float* ln2g  = (const float*)d_in[15];
    const float* ln2b  = (const float*)d_in[16];
    float* y = (float*)d_out;

    __half *q, *k, *v, *attn, *hh, *m1, *xh, *wq, *wk, *wv, *wo, *w1, *w2;
    float *proj, *h, *m2;
    cudaGetSymbolAddress((void**)&q,    g_q);
    cudaGetSymbolAddress((void**)&k,    g_k);
    cudaGetSymbolAddress((void**)&v,    g_v);
    cudaGetSymbolAddress((void**)&attn, g_attn);
    cudaGetSymbolAddress((void**)&proj, g_proj);
    cudaGetSymbolAddress((void**)&h,    g_h);
    cudaGetSymbolAddress((void**)&hh,   g_hh);
    cudaGetSymbolAddress((void**)&m1,   g_mlp1);
    cudaGetSymbolAddress((void**)&m2,   g_mlp2);
    cudaGetSymbolAddress((void**)&xh,   g_xh);
    cudaGetSymbolAddress((void**)&wq,   g_wq);
    cudaGetSymbolAddress((void**)&wk,   g_wk);
    cudaGetSymbolAddress((void**)&wv,   g_wv);
    cudaGetSymbolAddress((void**)&wo,   g_wo);
    cudaGetSymbolAddress((void**)&w1,   g_w1);
    cudaGetSymbolAddress((void**)&w2,   g_w2);

    const int SMEM_G = 4 * 128 * 72 * 2;   // 73728 bytes (2 buf x (A+B) tiles)
    cudaFuncSetAttribute(gemm_h_qkv, cudaFuncAttributeMaxDynamicSharedMemorySize, SMEM_G);
    cudaFuncSetAttribute(gemm_h<false, float>,  cudaFuncAttributeMaxDynamicSharedMemorySize, SMEM_G);
    cudaFuncSetAttribute(gemm_h<false, __half>, cudaFuncAttributeMaxDynamicSharedMemorySize, SMEM_G);
    cudaFuncSetAttribute(gemm_h<true, __half>,  cudaFuncAttributeMaxDynamicSharedMemorySize, SMEM_G);

    // converts: x -> half; weights -> transposed half [N,K]
    cvt_h_kernel<<<SEQ * CDIM / 1024, 256>>>(x, xh, SEQ * CDIM);
    cvt_t_kernel<<<dim3(CDIM / 32, CDIM / 32), 256>>>(Wq, wq, CDIM, CDIM);
    cvt_t_kernel<<<dim3(CDIM / 32, CDIM / 32), 256>>>(Wk, wk, CDIM, CDIM);
    cvt_t_kernel<<<dim3(CDIM / 32, CDIM / 32), 256>>>(Wv, wv, CDIM, CDIM);
    cvt_t_kernel<<<dim3(CDIM / 32, CDIM / 32), 256>>>(Wo, wo, CDIM, CDIM);
    cvt_t_kernel<<<dim3(CDIM / 32, FDIM / 32), 256>>>(W1, w1, CDIM, FDIM);
    cvt_t_kernel<<<dim3(FDIM / 32, CDIM / 32), 256>>>(W2, w2, FDIM, CDIM);

    // fused QKV projection
    gemm_h_qkv<<<dim3(18, SEQ / 128), 256, SMEM_G>>>(xh, wq, wk, wv, bq, bk, bv, q, k, v);

    // causal attention
    flash_attn_h<<<dim3(SEQ / 128, NH), 256>>>(q, k, v, attn);

    // output projection (fp32 out)
    gemm_h<false, float><<<dim3(CDIM / 128, SEQ / 128), 256, SMEM_G>>>(attn, wo, bo, proj, CDIM, CDIM);

    // h = LN(x + proj), plus half copy for W1
    add_ln<true><<<SEQ, 256>>>(x, proj, ln1g, ln1b, h, hh);

    // MLP
    gemm_h<true, __half><<<dim3(FDIM / 128, SEQ / 128), 256, SMEM_G>>>(hh, w1, b1, m1, FDIM, CDIM);
    gemm_h<false, float><<<dim3(CDIM / 128, SEQ / 128), 256, SMEM_G>>>(m1, w2, b2, m2, CDIM, FDIM);

    // y = LN(h + mlp)
    add_ln<false><<<SEQ, 256>>>(h, m2, ln2g, ln2b, y, nullptr);

    (void)in_sizes; (void)n_in; (void)out_size;
}

// round 8
// speedup vs baseline: 7.9581x; 1.2845x over previous
#include <cuda_runtime.h>
#include <cuda_fp16.h>
#include <math.h>
#include <cstdint>
#include <stdint.h>

#define SEQ 4096
#define CDIM 768
#define NH 12
#define HD 64
#define FDIM 3072

// ---------------- scratch (device globals; no allocation allowed) ----------
__device__ __half g_q[SEQ * CDIM];
__device__ __half g_k[SEQ * CDIM];
__device__ __half g_v[SEQ * CDIM];
__device__ __half g_attn[SEQ * CDIM];
__device__ float  g_proj[SEQ * CDIM];
__device__ float  g_h[SEQ * CDIM];
__device__ __half g_hh[SEQ * CDIM];
__device__ __half g_mlp1[SEQ * FDIM];
__device__ float  g_mlp2[SEQ * CDIM];
__device__ __half g_xh[SEQ * CDIM];
__device__ __half g_wq[CDIM * CDIM];     // [N,K] half
__device__ __half g_wk[CDIM * CDIM];
__device__ __half g_wv[CDIM * CDIM];
__device__ __half g_wo[CDIM * CDIM];
__device__ __half g_w1[FDIM * CDIM];     // W1^T
__device__ __half g_w2[CDIM * FDIM];     // W2^T

__device__ __forceinline__ void cp16(unsigned int dst, const void* src) {
    asm volatile("cp.async.cg.shared.global [%0], [%1], 16;" :: "r"(dst), "l"(src));
}

__device__ __forceinline__ unsigned smem_u32(const void* p) {
    unsigned a;
    asm("{ .reg .u64 t; cvta.to.shared.u64 t, %1; cvt.u32.u64 %0, t; }" : "=r"(a) : "l"(p));
    return a;
}

__device__ __forceinline__ void mma_f16(
    float& d0, float& d1, float& d2, float& d3,
    unsigned a0, unsigned a1, unsigned a2, unsigned a3,
    unsigned b0, unsigned b1)
{
    asm volatile(
        "mma.sync.aligned.m16n8k16.row.col.f32.f16.f16.f32 "
        "{%0,%1,%2,%3},{%4,%5,%6,%7},{%8,%9},{%0,%1,%2,%3};"
        : "+f"(d0), "+f"(d1), "+f"(d2), "+f"(d3)
        : "r"(a0), "r"(a1), "r"(a2), "r"(a3), "r"(b0), "r"(b1));
}

__device__ __forceinline__ void ldsm4(
    unsigned& r0, unsigned& r1, unsigned& r2, unsigned& r3, unsigned addr)
{
    asm volatile("ldmatrix.sync.aligned.m8n8.x4.shared.b16 {%0,%1,%2,%3}, [%4];"
                 : "=r"(r0), "=r"(r1), "=r"(r2), "=r"(r3) : "r"(addr));
}

__device__ __forceinline__ void ldsm4t(
    unsigned& r0, unsigned& r1, unsigned& r2, unsigned& r3, unsigned addr)
{
    asm volatile("ldmatrix.sync.aligned.m8n8.x4.trans.shared.b16 {%0,%1,%2,%3}, [%4];"
                 : "=r"(r0), "=r"(r1), "=r"(r2), "=r"(r3) : "r"(addr));
}

__device__ __forceinline__ unsigned pack_h2(float lo, float hi) {
    __half2 h = __floats2half2_rn(lo, hi);
    return *reinterpret_cast<unsigned*>(&h);
}

// ---------------- float -> half convert -------------------------------------
__global__ __launch_bounds__(256) void cvt_h_kernel(
    const float* __restrict__ in, __half* __restrict__ out, int n)
{
    int i = (blockIdx.x * 256 + threadIdx.x) * 4;
    if (i < n) {
        float4 v = *reinterpret_cast<const float4*>(in + i);
        uint2 u;
        u.x = pack_h2(v.x, v.y);
        u.y = pack_h2(v.z, v.w);
        *reinterpret_cast<uint2*>(out + i) = u;
    }
}

// ---------------- transpose + convert helpers -------------------------------
__device__ __forceinline__ void cvt_t_body(
    const float* __restrict__ in, __half* __restrict__ out, int K, int N)
{
    __shared__ float t[32][33];
    const int k0 = blockIdx.x * 32, n0 = blockIdx.y * 32;
    const int tx = threadIdx.x & 31, ty = threadIdx.x >> 5;
#pragma unroll
    for (int i = 0; i < 4; i++)
        t[ty + i * 8][tx] = in[(size_t)(k0 + ty + i * 8) * N + n0 + tx];
    __syncthreads();
#pragma unroll
    for (int i = 0; i < 4; i++)
        out[(size_t)(n0 + ty + i * 8) * K + k0 + tx] = __float2half_rn(t[tx][ty + i * 8]);
}

__global__ __launch_bounds__(256) void cvt_t_kernel(
    const float* __restrict__ in, __half* __restrict__ out, int K, int N)
{
    cvt_t_body(in, out, K, N);
}

struct Ptr4 {
    const float* s0; const float* s1; const float* s2; const float* s3;
    __half* d0; __half* d1; __half* d2; __half* d3;
};
__global__ __launch_bounds__(256) void cvt_t4_kernel(Ptr4 p)
{
    const int z = blockIdx.z;
    const float* in = (z == 0) ? p.s0 : (z == 1) ? p.s1 : (z == 2) ? p.s2 : p.s3;
    __half* out     = (z == 0) ? p.d0 : (z == 1) ? p.d1 : (z == 2) ? p.d2 : p.d3;
    cvt_t_body(in, out, CDIM, CDIM);
}

// ---------------- FP16 tensor-core GEMM (ldmatrix frags) --------------------
// C[M,N] = A[M,K] @ Bt[N,K]^T + bias. 128x128 tile, BK=64, cp.async double
// buffer, 256 thr = 8 warps (4Mx2N), warp tile 32x64, 2 CTAs/SM.
template <bool GELU, typename OutT>
__device__ __forceinline__ void gemm_h_body(
    const __half* __restrict__ A, const __half* __restrict__ Bt,
    const float* __restrict__ bias, OutT* __restrict__ C,
    int N, int K, int bx, int by)
{
    constexpr int BK = 64, SR = 72;              // halves
    extern __shared__ __half smh[];
    const unsigned smb = smem_u32(smh);

    const int tid = threadIdx.x, lane = tid & 31, warp = tid >> 5;
    const int wm = warp & 3, wn = warp >> 2, g = lane >> 2, t = lane & 3;

    // ldmatrix source offsets (bytes, relative to tile base)
    const int lr = lane & 15;
    const int lc = (lane >> 4) << 3;                        // 0 or 8 halves
    const unsigned aoff0 = ((wm * 32 + lr) * SR + lc) * 2;
    const unsigned aoff1 = ((wm * 32 + 16 + lr) * SR + lc) * 2;
    const int rb = (lane & 7) | ((lane & 16) >> 1);          // B row-in-16
    const int cbh = lane & 8;                                // 0 or 8 halves
    unsigned boff[4];
#pragma unroll
    for (int j = 0; j < 4; j++)
        boff[j] = ((wn * 64 + j * 16 + rb) * SR + cbh) * 2;

    // global loader: 128 rows x 8 16B units per tile; 4 units/thread
    const int u0 = tid * 4;
    const __half* Abase = A + (size_t)(by * 128) * K;
    const __half* Bbase = Bt + (size_t)(bx * 128) * K;

    float acc[2][8][4] = {};
    const int nchunks = K / BK;

    // prefetch chunk 0 into buffer 0
#pragma unroll
    for (int j = 0; j < 4; j++) {
        const int u = u0 + j, row = u >> 3, c16 = u & 7;
        const unsigned off = (unsigned)(row * SR + c16 * 8) * 2;
        cp16(smb + off, Abase + (size_t)row * K + c16 * 8);
        cp16(smb + 18432 + off, Bbase + (size_t)row * K + c16 * 8);
    }
    asm volatile("cp.async.commit_group;");

    for (int ch = 0; ch < nchunks; ch++) {
        asm volatile("cp.async.wait_group 0;");
        __syncthreads();
        const int buf = ch & 1;
        if (ch + 1 < nchunks) {
            const int k0 = (ch + 1) * BK;
            const unsigned dst = smb + (buf ^ 1) * 36864;
#pragma unroll
            for (int j = 0; j < 4; j++) {
                const int u = u0 + j, row = u >> 3, c16 = u & 7;
                const unsigned off = (unsigned)(row * SR + c16 * 8) * 2;
                cp16(dst + off, Abase + (size_t)row * K + k0 + c16 * 8);
                cp16(dst + 18432 + off, Bbase + (size_t)row * K + k0 + c16 * 8);
            }
            asm volatile("cp.async.commit_group;");
        }
        const unsigned abase = smb + buf * 36864;
        const unsigned bbase = abase + 18432;

#pragma unroll
        for (int kk = 0; kk < 4; kk++) {
            const unsigned kb2 = kk * 32;      // 16 halves = 32 bytes
            unsigned af[2][4], bf[8][2];
            ldsm4(af[0][0], af[0][1], af[0][2], af[0][3], abase + aoff0 + kb2);
            ldsm4(af[1][0], af[1][1], af[1][2], af[1][3], abase + aoff1 + kb2);
#pragma unroll
            for (int j = 0; j < 4; j++)
                ldsm4(bf[2 * j][0], bf[2 * j][1], bf[2 * j + 1][0], bf[2 * j + 1][1],
                      bbase + boff[j] + kb2);
#pragma unroll
            for (int mt = 0; mt < 2; mt++)
#pragma unroll
                for (int nt = 0; nt < 8; nt++)
                    mma_f16(acc[mt][nt][0], acc[mt][nt][1], acc[mt][nt][2], acc[mt][nt][3],
                            af[mt][0], af[mt][1], af[mt][2], af[mt][3],
                            bf[nt][0], bf[nt][1]);
        }
    }

#pragma unroll
    for (int mt = 0; mt < 2; mt++) {
        const int r0 = by * 128 + wm * 32 + mt * 16 + g;
#pragma unroll
        for (int nt = 0; nt < 8; nt++) {
            const int c0 = bx * 128 + wn * 64 + nt * 8 + t * 2;
            const float bz0 = bias[c0], bz1 = bias[c0 + 1];
            float v0 = acc[mt][nt][0] + bz0;
            float v1 = acc[mt][nt][1] + bz1;
            float v2 = acc[mt][nt][2] + bz0;
            float v3 = acc[mt][nt][3] + bz1;
            if (GELU) {
                v0 = 0.5f * v0 * (1.0f + erff(v0 * 0.70710678118654752f));
                v1 = 0.5f * v1 * (1.0f + erff(v1 * 0.70710678118654752f));
                v2 = 0.5f * v2 * (1.0f + erff(v2 * 0.70710678118654752f));
                v3 = 0.5f * v3 * (1.0f + erff(v3 * 0.70710678118654752f));
            }
            if (sizeof(OutT) == 2) {
                __half* Ch = reinterpret_cast<__half*>(C);
                *reinterpret_cast<unsigned*>(Ch + (size_t)r0 * N + c0) = pack_h2(v0, v1);
                *reinterpret_cast<unsigned*>(Ch + (size_t)(r0 + 8) * N + c0) = pack_h2(v2, v3);
            } else {
                float* Cf = reinterpret_cast<float*>(C);
                *reinterpret_cast<float2*>(Cf + (size_t)r0 * N + c0) = make_float2(v0, v1);
                *reinterpret_cast<float2*>(Cf + (size_t)(r0 + 8) * N + c0) = make_float2(v2, v3);
            }
        }
    }
}

template <bool GELU, typename OutT>
__global__ __launch_bounds__(256, 2) void gemm_h(
    const __half* __restrict__ A, const __half* __restrict__ Bt,
    const float* __restrict__ bias, OutT* __restrict__ C, int N, int K)
{
    gemm_h_body<GELU, OutT>(A, Bt, bias, C, N, K, blockIdx.x, blockIdx.y);
}

__global__ __launch_bounds__(256, 2) void gemm_h_qkv(
    const __half* __restrict__ X,
    const __half* __restrict__ WqT, const __half* __restrict__ WkT, const __half* __restrict__ WvT,
    const float* __restrict__ bq, const float* __restrict__ bk, const float* __restrict__ bv,
    __half* __restrict__ q, __half* __restrict__ k, __half* __restrict__ v)
{
    const int which = blockIdx.x / 6;
    const int bx = blockIdx.x % 6;
    const __half* Bt  = (which == 0) ? WqT : (which == 1) ? WkT : WvT;
    const float* bias = (which == 0) ? bq  : (which == 1) ? bk  : bv;
    __half* C         = (which == 0) ? q   : (which == 1) ? k   : v;
    gemm_h_body<false, __half>(X, Bt, bias, C, CDIM, CDIM, bx, blockIdx.y);
}

// ---------------- FP16 flash attention (cp.async + ldmatrix) ----------------
// grid (SEQ/128, NH), 256 thr = 8 warps; warp owns 16 query rows.
// K,V tiles (64 keys x 64 d) double-buffered via cp.async, row-major.
// S B-frags: ldmatrix; P@V B-frags: ldmatrix.trans on V.
__global__ __launch_bounds__(256, 2) void flash_attn_h(
    const __half* __restrict__ Q, const __half* __restrict__ K,
    const __half* __restrict__ V, __half* __restrict__ O)
{
    constexpr int SR = 72;
    __shared__ __align__(16) __half KV[2][2][64][SR];   // [buf][K/V][row][d]

    const int h  = blockIdx.y;
    const int qb = (gridDim.x - 1) - blockIdx.x;
    const int tid  = threadIdx.x;
    const int lane = tid & 31;
    const int w = tid >> 5;
    const int g = lane >> 2;
    const int t = lane & 3;

    const int r0 = qb * 128 + w * 16 + g;
    const int r1 = r0 + 8;

    // Q A-fragments, scaled by 1/8
    unsigned qf[4][4];
    {
        const __half2 sc = __float2half2_rn(0.125f);
        const __half* q0p = Q + (size_t)r0 * CDIM + h * HD;
        const __half* q1p = Q + (size_t)r1 * CDIM + h * HD;
#pragma unroll
        for (int kk = 0; kk < 4; kk++) {
            __half2 x0 = __hmul2(*reinterpret_cast<const __half2*>(q0p + kk * 16 + 2 * t), sc);
            __half2 x1 = __hmul2(*reinterpret_cast<const __half2*>(q1p + kk * 16 + 2 * t), sc);
            __half2 x2 = __hmul2(*reinterpret_cast<const __half2*>(q0p + kk * 16 + 2 * t + 8), sc);
            __half2 x3 = __hmul2(*reinterpret_cast<const __half2*>(q1p + kk * 16 + 2 * t + 8), sc);
            qf[kk][0] = *reinterpret_cast<unsigned*>(&x0);
            qf[kk][1] = *reinterpret_cast<unsigned*>(&x1);
            qf[kk][2] = *reinterpret_cast<unsigned*>(&x2);
            qf[kk][3] = *reinterpret_cast<unsigned*>(&x3);
        }
    }

    // ldmatrix offsets (bytes, relative to tile base)
    const int rb = (lane & 7) | ((lane & 16) >> 1);
    const int cbh = lane & 8;
    unsigned koff[4];
#pragma unroll
    for (int j = 0; j < 4; j++)
        koff[j] = ((j * 16 + rb) * SR + cbh) * 2;
    const int vr = lane & 15;
    const int vc = (lane >> 4) << 3;
    unsigned voff[4];
#pragma unroll
    for (int j = 0; j < 4; j++)
        voff[j] = (vr * SR + j * 16 + vc) * 2;

    float o[8][4] = {};
    float m0 = -1e30f, m1 = -1e30f, l0 = 0.f, l1 = 0.f;

    // loader: tile = 64 rows x 8 16B units; 2 units/thread per tile
    const int u0 = tid * 2;
    const int ntiles = 2 * (qb + 1);
    const unsigned kvb = smem_u32(&KV[0][0][0][0]);
    const unsigned tilebytes = 64 * SR * 2;     // 9216
    const unsigned bufbytes = 2 * tilebytes;    // 18432

    // prefetch tile 0
#pragma unroll
    for (int j = 0; j < 2; j++) {
        const int u = u0 + j, row = u >> 3, c = u & 7;
        const unsigned off = (unsigned)(row * SR + c * 8) * 2;
        cp16(kvb + off, K + (size_t)row * CDIM + h * HD + c * 8);
        cp16(kvb + tilebytes + off, V + (size_t)row * CDIM + h * HD + c * 8);
    }
    asm volatile("cp.async.commit_group;");

    for (int kb = 0; kb < ntiles; kb++) {
        asm volatile("cp.async.wait_group 0;");
        __syncthreads();
        const int buf = kb & 1;
        if (kb + 1 < ntiles) {
            const int kbase = (kb + 1) * 64;
            const unsigned dst = kvb + (buf ^ 1) * bufbytes;
#pragma unroll
            for (int j = 0; j < 2; j++) {
                const int u = u0 + j, row = u >> 3, c = u & 7;
                const unsigned off = (unsigned)(row * SR + c * 8) * 2;
                cp16(dst + off, K + (size_t)(kbase + row) * CDIM + h * HD + c * 8);
                cp16(dst + tilebytes + off, V + (size_t)(kbase + row) * CDIM + h * HD + c * 8);
            }
            asm volatile("cp.async.commit_group;");
        }
        const unsigned kbase_s = kvb + buf * bufbytes;
        const unsigned vbase_s = kbase_s + tilebytes;

        // S = Q @ K^T
        float s[8][4] = {};
#pragma unroll
        for (int kk = 0; kk < 4; kk++) {
            const unsigned kb2 = kk * 32;
#pragma unroll
            for (int j = 0; j < 4; j++) {
                unsigned b0, b1, b2, b3;
                ldsm4(b0, b1, b2, b3, kbase_s + koff[j] + kb2);
                mma_f16(s[2 * j][0], s[2 * j][1], s[2 * j][2], s[2 * j][3],
                        qf[kk][0], qf[kk][1], qf[kk][2], qf[kk][3], b0, b1);
                mma_f16(s[2 * j + 1][0], s[2 * j + 1][1], s[2 * j + 1][2], s[2 * j + 1][3],
                        qf[kk][0], qf[kk][1], qf[kk][2], qf[kk][3], b2, b3);
            }
        }

        if (kb >= 2 * qb) {
            const int cb = kb * 64;
#pragma unroll
            for (int nt = 0; nt < 8; nt++) {
                const int c0 = cb + nt * 8 + 2 * t;
                if (c0 > r0)     s[nt][0] = -1e30f;
                if (c0 + 1 > r0) s[nt][1] = -1e30f;
                if (c0 > r1)     s[nt][2] = -1e30f;
                if (c0 + 1 > r1) s[nt][3] = -1e30f;
            }
        }

        float mx0 = -1e30f, mx1 = -1e30f;
#pragma unroll
        for (int nt = 0; nt < 8; nt++) {
            mx0 = fmaxf(mx0, fmaxf(s[nt][0], s[nt][1]));
            mx1 = fmaxf(mx1, fmaxf(s[nt][2], s[nt][3]));
        }
        mx0 = fmaxf(mx0, __shfl_xor_sync(0xffffffffu, mx0, 1));
        mx0 = fmaxf(mx0, __shfl_xor_sync(0xffffffffu, mx0, 2));
        mx1 = fmaxf(mx1, __shfl_xor_sync(0xffffffffu, mx1, 1));
        mx1 = fmaxf(mx1, __shfl_xor_sync(0xffffffffu, mx1, 2));

        const float nm0 = fmaxf(m0, mx0);
        const float nm1 = fmaxf(m1, mx1);
        const float cr0 = __expf(m0 - nm0);
        const float cr1 = __expf(m1 - nm1);
        m0 = nm0; m1 = nm1;

        float sm0 = 0.f, sm1 = 0.f;
#pragma unroll
        for (int nt = 0; nt < 8; nt++) {
            float p0 = __expf(s[nt][0] - nm0);
            float p1 = __expf(s[nt][1] - nm0);
            float p2 = __expf(s[nt][2] - nm1);
            float p3 = __expf(s[nt][3] - nm1);
            s[nt][0] = p0; s[nt][1] = p1; s[nt][2] = p2; s[nt][3] = p3;
            sm0 += p0 + p1;
            sm1 += p2 + p3;
        }
        sm0 += __shfl_xor_sync(0xffffffffu, sm0, 1);
        sm0 += __shfl_xor_sync(0xffffffffu, sm0, 2);
        sm1 += __shfl_xor_sync(0xffffffffu, sm1, 1);
        sm1 += __shfl_xor_sync(0xffffffffu, sm1, 2);
        l0 = l0 * cr0 + sm0;
        l1 = l1 * cr1 + sm1;

#pragma unroll
        for (int nt = 0; nt < 8; nt++) {
            o[nt][0] *= cr0; o[nt][1] *= cr0;
            o[nt][2] *= cr1; o[nt][3] *= cr1;
        }

        // O += P @ V  (A from S regs; B via ldmatrix.trans on V)
#pragma unroll
        for (int kk = 0; kk < 4; kk++) {
            unsigned a0 = pack_h2(s[2 * kk][0], s[2 * kk][1]);
            unsigned a1 = pack_h2(s[2 * kk][2], s[2 * kk][3]);
            unsigned a2 = pack_h2(s[2 * kk + 1][0], s[2 * kk + 1][1]);
            unsigned a3 = pack_h2(s[2 * kk + 1][2], s[2 * kk + 1][3]);
            const unsigned kb2 = kk * 16 * SR * 2;   // advance 16 key-rows
#pragma unroll
            for (int j = 0; j < 4; j++) {
                unsigned b0, b1, b2, b3;
                ldsm4t(b0, b1, b2, b3, vbase_s + voff[j] + kb2);
                mma_f16(o[2 * j][0], o[2 * j][1], o[2 * j][2], o[2 * j][3],
                        a0, a1, a2, a3, b0, b1);
                mma_f16(o[2 * j + 1][0], o[2 * j + 1][1], o[2 * j + 1][2], o[2 * j + 1][3],
                        a0, a1, a2, a3, b2, b3);
            }
        }
    }

    const float inv0 = 1.f / l0;
    const float inv1 = 1.f / l1;
    __half* o0p = O + (size_t)r0 * CDIM + h * HD;
    __half* o1p = O + (size_t)r1 * CDIM + h * HD;
#pragma unroll
    for (int nt = 0; nt < 8; nt++) {
        const int c = nt * 8 + 2 * t;
        *reinterpret_cast<unsigned*>(o0p + c) = pack_h2(o[nt][0] * inv0, o[nt][1] * inv0);
        *reinterpret_cast<unsigned*>(o1p + c) = pack_h2(o[nt][2] * inv1, o[nt][3] * inv1);
    }
}

// ---------------- fused residual add + LayerNorm ---------------------------
template <bool DUALOUT>
__global__ __launch_bounds__(256) void add_ln(
    const float* __restrict__ A, const float* __restrict__ Bb,
    const float* __restrict__ g, const float* __restrict__ be,
    float* __restrict__ out, __half* __restrict__ out_h)
{
    const int row = blockIdx.x;
    const int tid = threadIdx.x;
    const float* pa = A + (size_t)row * CDIM;
    const float* pb = Bb + (size_t)row * CDIM;

    float v[3];
    float s = 0.f, sq = 0.f;
#pragma unroll
    for (int i = 0; i < 3; i++) {
        int idx = tid + i * 256;
        v[i] = pa[idx] + pb[idx];
        s += v[i];
        sq += v[i] * v[i];
    }
#pragma unroll
    for (int off = 16; off; off >>= 1) {
        s += __shfl_xor_sync(0xffffffffu, s, off);
        sq += __shfl_xor_sync(0xffffffffu, sq, off);
    }
    __shared__ float ss[8], ssq[8];
    int w = tid >> 5, lane = tid & 31;
    if (lane == 0) { ss[w] = s; ssq[w] = sq; }
    __syncthreads();
    if (tid < 32) {
        s = (tid < 8) ? ss[tid] : 0.f;
        sq = (tid < 8) ? ssq[tid] : 0.f;
#pragma unroll
        for (int off = 4; off; off >>= 1) {
            s += __shfl_xor_sync(0xffffffffu, s, off);
            sq += __shfl_xor_sync(0xffffffffu, sq, off);
        }
        if (tid == 0) { ss[0] = s; ssq[0] = sq; }
    }
    __syncthreads();
    const float mean = ss[0] * (1.0f / CDIM);
    const float var = ssq[0] * (1.0f / CDIM) - mean * mean;
    const float inv = rsqrtf(var + 1e-5f);
#pragma unroll
    for (int i = 0; i < 3; i++) {
        int idx = tid + i * 256;
        float r = (v[i] - mean) * inv * g[idx] + be[idx];
        out[(size_t)row * CDIM + idx] = r;
        if (DUALOUT)
            out_h[(size_t)row * CDIM + idx] = __float2half_rn(r);
    }
}

// ---------------- launch ----------------------------------------------------
extern "C" void kernel_launch(void* const* d_in, const int* in_sizes, int n_in,
                              void* d_out, int out_size)
{
    const float* x     = (const float*)d_in[0];
    const float* Wq    = (const float*)d_in[1];
    const float* bq    = (const float*)d_in[2];
    const float* Wk    = (const float*)d_in[3];
    const float* bk    = (const float*)d_in[4];
    const float* Wv    = (const float*)d_in[5];
    const float* bv    = (const float*)d_in[6];
    const float* Wo    = (const float*)d_in[7];
    const float* bo    = (const float*)d_in[8];
    const float* ln1g  = (const float*)d_in[9];
    const float* ln1b  = (const float*)d_in[10];
    const float* W1    = (const float*)d_in[11];
    const float* b1    = (const float*)d_in[12];
    const float* W2    = (const float*)d_in[13];
    const float* b2    = (const float*)d_in[14];
    const float* ln2g  = (const float*)d_in[15];
    const float* ln2b  = (const float*)d_in[16];
    float* y = (float*)d_out;

    __half *q, *k, *v, *attn, *hh, *m1, *xh, *wq, *wk, *wv, *wo, *w1, *w2;
    float *proj, *h, *m2;
    cudaGetSymbolAddress((void**)&q,    g_q);
    cudaGetSymbolAddress((void**)&k,    g_k);
    cudaGetSymbolAddress((void**)&v,    g_v);
    cudaGetSymbolAddress((void**)&attn, g_attn);
    cudaGetSymbolAddress((void**)&proj, g_proj);
    cudaGetSymbolAddress((void**)&h,    g_h);
    cudaGetSymbolAddress((void**)&hh,   g_hh);
    cudaGetSymbolAddress((void**)&m1,   g_mlp1);
    cudaGetSymbolAddress((void**)&m2,   g_mlp2);
    cudaGetSymbolAddress((void**)&xh,   g_xh);
    cudaGetSymbolAddress((void**)&wq,   g_wq);
    cudaGetSymbolAddress((void**)&wk,   g_wk);
    cudaGetSymbolAddress((void**)&wv,   g_wv);
    cudaGetSymbolAddress((void**)&wo,   g_wo);
    cudaGetSymbolAddress((void**)&w1,   g_w1);
    cudaGetSymbolAddress((void**)&w2,   g_w2);

    const int SMEM_G = 4 * 128 * 72 * 2;   // 73728 bytes
    cudaFuncSetAttribute(gemm_h_qkv, cudaFuncAttributeMaxDynamicSharedMemorySize, SMEM_G);
    cudaFuncSetAttribute(gemm_h<false, float>,  cudaFuncAttributeMaxDynamicSharedMemorySize, SMEM_G);
    cudaFuncSetAttribute(gemm_h<true, __half>,  cudaFuncAttributeMaxDynamicSharedMemorySize, SMEM_G);

    // converts
    cvt_h_kernel<<<SEQ * CDIM / 1024, 256>>>(x, xh, SEQ * CDIM);
    Ptr4 p4 = { Wq, Wk, Wv, Wo, wq, wk, wv, wo };
    cvt_t4_kernel<<<dim3(CDIM / 32, CDIM / 32, 4), 256>>>(p4);
    cvt_t_kernel<<<dim3(CDIM / 32, FDIM / 32), 256>>>(W1, w1, CDIM, FDIM);
    cvt_t_kernel<<<dim3(FDIM / 32, CDIM / 32), 256>>>(W2, w2, FDIM, CDIM);

    // fused QKV projection
    gemm_h_qkv<<<dim3(18, SEQ / 128), 256, SMEM_G>>>(xh, wq, wk, wv, bq, bk, bv, q, k, v);

    // causal attention
    flash_attn_h<<<dim3(SEQ / 128, NH), 256>>>(q, k, v, attn);

    // output projection (fp32 out)
    gemm_h<false, float><<<dim3(CDIM / 128, SEQ / 128), 256, SMEM_G>>>(attn, wo, bo, proj, CDIM, CDIM);

    // h = LN(x + proj), plus half copy for W1
    add_ln<true><<<SEQ, 256>>>(x, proj, ln1g, ln1b, h, hh);

    // MLP
    gemm_h<true, __half><<<dim3(FDIM / 128, SEQ / 128), 256, SMEM_G>>>(hh, w1, b1, m1, FDIM, CDIM);
    gemm_h<false, float><<<dim3(CDIM / 128, SEQ / 128), 256, SMEM_G>>>(m1, w2, b2, m2, CDIM, FDIM);

    // y = LN(h + mlp)
    add_ln<false><<<SEQ, 256>>>(h, m2, ln2g, ln2b, y, nullptr);

    (void)in_sizes; (void)n_in; (void)out_size;
}

// round 9
// speedup vs baseline: 8.0786x; 1.0151x over previous
#include <cuda_runtime.h>
#include <cuda_fp16.h>
#include <math.h>
#include <cstdint>
#include <stdint.h>

#define SEQ 4096
#define CDIM 768
#define NH 12
#define HD 64
#define FDIM 3072

// ---------------- scratch (device globals; no allocation allowed) ----------
__device__ __half g_q[SEQ * CDIM];
__device__ __half g_k[SEQ * CDIM];
__device__ __half g_v[SEQ * CDIM];
__device__ __half g_attn[SEQ * CDIM];
__device__ float  g_proj[SEQ * CDIM];
__device__ float  g_h[SEQ * CDIM];
__device__ __half g_hh[SEQ * CDIM];
__device__ __half g_mlp1[SEQ * FDIM];
__device__ float  g_mlp2[SEQ * CDIM];
__device__ __half g_xh[SEQ * CDIM];
__device__ __half g_wq[CDIM * CDIM];     // [N,K] half
__device__ __half g_wk[CDIM * CDIM];
__device__ __half g_wv[CDIM * CDIM];
__device__ __half g_wo[CDIM * CDIM];
__device__ __half g_w1[FDIM * CDIM];     // W1^T
__device__ __half g_w2[CDIM * FDIM];     // W2^T

__device__ __forceinline__ void cp16(unsigned int dst, const void* src) {
    asm volatile("cp.async.cg.shared.global [%0], [%1], 16;" :: "r"(dst), "l"(src));
}
__device__ __forceinline__ void cp_commit() {
    asm volatile("cp.async.commit_group;");
}
__device__ __forceinline__ void cp_wait0() {
    asm volatile("cp.async.wait_group 0;");
}
__device__ __forceinline__ void cp_wait1() {
    asm volatile("cp.async.wait_group 1;");
}

__device__ __forceinline__ unsigned smem_u32(const void* p) {
    unsigned a;
    asm("{ .reg .u64 t; cvta.to.shared.u64 t, %1; cvt.u32.u64 %0, t; }" : "=r"(a) : "l"(p));
    return a;
}

__device__ __forceinline__ void mma_f16(
    float& d0, float& d1, float& d2, float& d3,
    unsigned a0, unsigned a1, unsigned a2, unsigned a3,
    unsigned b0, unsigned b1)
{
    asm volatile(
        "mma.sync.aligned.m16n8k16.row.col.f32.f16.f16.f32 "
        "{%0,%1,%2,%3},{%4,%5,%6,%7},{%8,%9},{%0,%1,%2,%3};"
        : "+f"(d0), "+f"(d1), "+f"(d2), "+f"(d3)
        : "r"(a0), "r"(a1), "r"(a2), "r"(a3), "r"(b0), "r"(b1));
}

__device__ __forceinline__ void ldsm4(
    unsigned& r0, unsigned& r1, unsigned& r2, unsigned& r3, unsigned addr)
{
    asm volatile("ldmatrix.sync.aligned.m8n8.x4.shared.b16 {%0,%1,%2,%3}, [%4];"
                 : "=r"(r0), "=r"(r1), "=r"(r2), "=r"(r3) : "r"(addr));
}

__device__ __forceinline__ void ldsm4t(
    unsigned& r0, unsigned& r1, unsigned& r2, unsigned& r3, unsigned addr)
{
    asm volatile("ldmatrix.sync.aligned.m8n8.x4.trans.shared.b16 {%0,%1,%2,%3}, [%4];"
                 : "=r"(r0), "=r"(r1), "=r"(r2), "=r"(r3) : "r"(addr));
}

__device__ __forceinline__ unsigned pack_h2(float lo, float hi) {
    __half2 h = __floats2half2_rn(lo, hi);
    return *reinterpret_cast<unsigned*>(&h);
}

// ---------------- float -> half convert -------------------------------------
__global__ __launch_bounds__(256) void cvt_h_kernel(
    const float* __restrict__ in, __half* __restrict__ out, int n)
{
    int i = (blockIdx.x * 256 + threadIdx.x) * 4;
    if (i < n) {
        float4 v = *reinterpret_cast<const float4*>(in + i);
        uint2 u;
        u.x = pack_h2(v.x, v.y);
        u.y = pack_h2(v.z, v.w);
        *reinterpret_cast<uint2*>(out + i) = u;
    }
}

// ---------------- transpose + convert helpers -------------------------------
__device__ __forceinline__ void cvt_t_body(
    const float* __restrict__ in, __half* __restrict__ out, int K, int N)
{
    __shared__ float t[32][33];
    const int k0 = blockIdx.x * 32, n0 = blockIdx.y * 32;
    const int tx = threadIdx.x & 31, ty = threadIdx.x >> 5;
#pragma unroll
    for (int i = 0; i < 4; i++)
        t[ty + i * 8][tx] = in[(size_t)(k0 + ty + i * 8) * N + n0 + tx];
    __syncthreads();
#pragma unroll
    for (int i = 0; i < 4; i++)
        out[(size_t)(n0 + ty + i * 8) * K + k0 + tx] = __float2half_rn(t[tx][ty + i * 8]);
}

__global__ __launch_bounds__(256) void cvt_t_kernel(
    const float* __restrict__ in, __half* __restrict__ out, int K, int N)
{
    cvt_t_body(in, out, K, N);
}

struct Ptr4 {
    const float* s0; const float* s1; const float* s2; const float* s3;
    __half* d0; __half* d1; __half* d2; __half* d3;
};
__global__ __launch_bounds__(256) void cvt_t4_kernel(Ptr4 p)
{
    const int z = blockIdx.z;
    const float* in = (z == 0) ? p.s0 : (z == 1) ? p.s1 : (z == 2) ? p.s2 : p.s3;
    __half* out     = (z == 0) ? p.d0 : (z == 1) ? p.d1 : (z == 2) ? p.d2 : p.d3;
    cvt_t_body(in, out, CDIM, CDIM);
}

// ---------------- FP16 tensor-core GEMM (3-stage cp.async + ldmatrix) -------
// C[M,N] = A[M,K] @ Bt[N,K]^T + bias. Tile BMx128, BK=64, triple-buffered,
// 256 thr = 8 warps (4Mx2N), 2 CTAs/SM.
template <int BM, bool GELU, typename OutT>
__device__ __forceinline__ void gemm_h_body(
    const __half* __restrict__ A, const __half* __restrict__ Bt,
    const float* __restrict__ bias, OutT* __restrict__ C,
    int N, int K, int bx, int by)
{
    constexpr int BK = 64, SR = 72;
    constexpr int MT = BM / 64;                  // m-subtiles per warp (1 or 2)
    constexpr unsigned ABYTES = BM * SR * 2;
    constexpr unsigned STAGE = ABYTES + 128 * SR * 2;

    extern __shared__ __half smh[];
    const unsigned smb = smem_u32(smh);

    const int tid = threadIdx.x, lane = tid & 31, warp = tid >> 5;
    const int wm = warp & 3, wn = warp >> 2, g = lane >> 2, t = lane & 3;

    // ldmatrix source offsets (bytes, relative to stage base)
    const int lr = lane & 15;
    const int lc = (lane >> 4) << 3;
    unsigned aoff[MT];
#pragma unroll
    for (int mt = 0; mt < MT; mt++)
        aoff[mt] = ((wm * (BM / 4) + mt * 16 + lr) * SR + lc) * 2;
    const int rb = (lane & 7) | ((lane & 16) >> 1);
    const int cbh = lane & 8;
    unsigned boff[4];
#pragma unroll
    for (int j = 0; j < 4; j++)
        boff[j] = ABYTES + ((wn * 64 + j * 16 + rb) * SR + cbh) * 2;

    // loaders
    constexpr int AU = BM / 32;                  // A 16B-units per thread
    const int u0a = tid * AU;
    const int u0b = tid * 4;
    const __half* Abase = A + (size_t)(by * BM) * K;
    const __half* Bbase = Bt + (size_t)(bx * 128) * K;

    const int nchunks = K / BK;

    auto prefetch = [&](int ch) {
        const unsigned dst = smb + (unsigned)(ch % 3) * STAGE;
        const int k0 = ch * BK;
#pragma unroll
        for (int j = 0; j < AU; j++) {
            const int u = u0a + j, row = u >> 3, c16 = u & 7;
            cp16(dst + (unsigned)(row * SR + c16 * 8) * 2,
                 Abase + (size_t)row * K + k0 + c16 * 8);
        }
#pragma unroll
        for (int j = 0; j < 4; j++) {
            const int u = u0b + j, row = u >> 3, c16 = u & 7;
            cp16(dst + ABYTES + (unsigned)(row * SR + c16 * 8) * 2,
                 Bbase + (size_t)row * K + k0 + c16 * 8);
        }
        cp_commit();
    };

    float acc[MT][8][4] = {};

    prefetch(0);
    if (nchunks > 1) prefetch(1);

    for (int ch = 0; ch < nchunks; ch++) {
        if (ch + 1 < nchunks) cp_wait1(); else cp_wait0();
        __syncthreads();
        if (ch + 2 < nchunks) prefetch(ch + 2);

        const unsigned sbase = smb + (unsigned)(ch % 3) * STAGE;
#pragma unroll
        for (int kk = 0; kk < 4; kk++) {
            const unsigned kb2 = kk * 32;
            unsigned af[MT][4], bf[8][2];
#pragma unroll
            for (int mt = 0; mt < MT; mt++)
                ldsm4(af[mt][0], af[mt][1], af[mt][2], af[mt][3],
                      sbase + aoff[mt] + kb2);
#pragma unroll
            for (int j = 0; j < 4; j++)
                ldsm4(bf[2 * j][0], bf[2 * j][1], bf[2 * j + 1][0], bf[2 * j + 1][1],
                      sbase + boff[j] + kb2);
#pragma unroll
            for (int mt = 0; mt < MT; mt++)
#pragma unroll
                for (int nt = 0; nt < 8; nt++)
                    mma_f16(acc[mt][nt][0], acc[mt][nt][1], acc[mt][nt][2], acc[mt][nt][3],
                            af[mt][0], af[mt][1], af[mt][2], af[mt][3],
                            bf[nt][0], bf[nt][1]);
        }
        __syncthreads();
    }

#pragma unroll
    for (int mt = 0; mt < MT; mt++) {
        const int r0 = by * BM + wm * (BM / 4) + mt * 16 + g;
#pragma unroll
        for (int nt = 0; nt < 8; nt++) {
            const int c0 = bx * 128 + wn * 64 + nt * 8 + t * 2;
            const float bz0 = bias[c0], bz1 = bias[c0 + 1];
            float v0 = acc[mt][nt][0] + bz0;
            float v1 = acc[mt][nt][1] + bz1;
            float v2 = acc[mt][nt][2] + bz0;
            float v3 = acc[mt][nt][3] + bz1;
            if (GELU) {
                v0 = 0.5f * v0 * (1.0f + erff(v0 * 0.70710678118654752f));
                v1 = 0.5f * v1 * (1.0f + erff(v1 * 0.70710678118654752f));
                v2 = 0.5f * v2 * (1.0f + erff(v2 * 0.70710678118654752f));
                v3 = 0.5f * v3 * (1.0f + erff(v3 * 0.70710678118654752f));
            }
            if (sizeof(OutT) == 2) {
                __half* Ch = reinterpret_cast<__half*>(C);
                *reinterpret_cast<unsigned*>(Ch + (size_t)r0 * N + c0) = pack_h2(v0, v1);
                *reinterpret_cast<unsigned*>(Ch + (size_t)(r0 + 8) * N + c0) = pack_h2(v2, v3);
            } else {
                float* Cf = reinterpret_cast<float*>(C);
                *reinterpret_cast<float2*>(Cf + (size_t)r0 * N + c0) = make_float2(v0, v1);
                *reinterpret_cast<float2*>(Cf + (size_t)(r0 + 8) * N + c0) = make_float2(v2, v3);
            }
        }
    }
}

template <int BM, bool GELU, typename OutT>
__global__ __launch_bounds__(256, 2) void gemm_h(
    const __half* __restrict__ A, const __half* __restrict__ Bt,
    const float* __restrict__ bias, OutT* __restrict__ C, int N, int K)
{
    gemm_h_body<BM, GELU, OutT>(A, Bt, bias, C, N, K, blockIdx.x, blockIdx.y);
}

__global__ __launch_bounds__(256, 2) void gemm_h_qkv(
    const __half* __restrict__ X,
    const __half* __restrict__ WqT, const __half* __restrict__ WkT, const __half* __restrict__ WvT,
    const float* __restrict__ bq, const float* __restrict__ bk, const float* __restrict__ bv,
    __half* __restrict__ q, __half* __restrict__ k, __half* __restrict__ v)
{
    const int which = blockIdx.x / 6;
    const int bx = blockIdx.x % 6;
    const __half* Bt  = (which == 0) ? WqT : (which == 1) ? WkT : WvT;
    const float* bias = (which == 0) ? bq  : (which == 1) ? bk  : bv;
    __half* C         = (which == 0) ? q   : (which == 1) ? k   : v;
    gemm_h_body<128, false, __half>(X, Bt, bias, C, CDIM, CDIM, bx, blockIdx.y);
}

// ---------------- FP16 flash attention (3-stage cp.async + ldmatrix) --------
__global__ __launch_bounds__(256, 2) void flash_attn_h(
    const __half* __restrict__ Q, const __half* __restrict__ K,
    const __half* __restrict__ V, __half* __restrict__ O)
{
    constexpr int SR = 72;
    constexpr unsigned TILE = 64 * SR * 2;       // 9216 bytes (one K or V tile)
    constexpr unsigned STAGE = 2 * TILE;         // 18432

    extern __shared__ __half smh[];
    const unsigned kvb = smem_u32(smh);

    const int h  = blockIdx.y;
    const int qb = (gridDim.x - 1) - blockIdx.x;
    const int tid  = threadIdx.x;
    const int lane = tid & 31;
    const int w = tid >> 5;
    const int g = lane >> 2;
    const int t = lane & 3;

    const int r0 = qb * 128 + w * 16 + g;
    const int r1 = r0 + 8;

    // Q A-fragments, scaled by 1/8
    unsigned qf[4][4];
    {
        const __half2 sc = __float2half2_rn(0.125f);
        const __half* q0p = Q + (size_t)r0 * CDIM + h * HD;
        const __half* q1p = Q + (size_t)r1 * CDIM + h * HD;
#pragma unroll
        for (int kk = 0; kk < 4; kk++) {
            __half2 x0 = __hmul2(*reinterpret_cast<const __half2*>(q0p + kk * 16 + 2 * t), sc);
            __half2 x1 = __hmul2(*reinterpret_cast<const __half2*>(q1p + kk * 16 + 2 * t), sc);
            __half2 x2 = __hmul2(*reinterpret_cast<const __half2*>(q0p + kk * 16 + 2 * t + 8), sc);
            __half2 x3 = __hmul2(*reinterpret_cast<const __half2*>(q1p + kk * 16 + 2 * t + 8), sc);
            qf[kk][0] = *reinterpret_cast<unsigned*>(&x0);
            qf[kk][1] = *reinterpret_cast<unsigned*>(&x1);
            qf[kk][2] = *reinterpret_cast<unsigned*>(&x2);
            qf[kk][3] = *reinterpret_cast<unsigned*>(&x3);
        }
    }

    // ldmatrix offsets
    const int rb = (lane & 7) | ((lane & 16) >> 1);
    const int cbh = lane & 8;
    unsigned koff[4];
#pragma unroll
    for (int j = 0; j < 4; j++)
        koff[j] = ((j * 16 + rb) * SR + cbh) * 2;
    const int vr = lane & 15;
    const int vc = (lane >> 4) << 3;
    unsigned voff[4];
#pragma unroll
    for (int j = 0; j < 4; j++)
        voff[j] = TILE + (vr * SR + j * 16 + vc) * 2;

    float o[8][4] = {};
    float m0 = -1e30f, m1 = -1e30f, l0 = 0.f, l1 = 0.f;

    const int u0 = tid * 2;
    const int ntiles = 2 * (qb + 1);

    auto prefetch = [&](int kb) {
        const unsigned dst = kvb + (unsigned)(kb % 3) * STAGE;
        const int kbase = kb * 64;
#pragma unroll
        for (int j = 0; j < 2; j++) {
            const int u = u0 + j, row = u >> 3, c = u & 7;
            const unsigned off = (unsigned)(row * SR + c * 8) * 2;
            cp16(dst + off, K + (size_t)(kbase + row) * CDIM + h * HD + c * 8);
            cp16(dst + TILE + off, V + (size_t)(kbase + row) * CDIM + h * HD + c * 8);
        }
        cp_commit();
    };

    prefetch(0);
    if (ntiles > 1) prefetch(1);

    for (int kb = 0; kb < ntiles; kb++) {
        if (kb + 1 < ntiles) cp_wait1(); else cp_wait0();
        __syncthreads();
        if (kb + 2 < ntiles) prefetch(kb + 2);

        const unsigned kbase_s = kvb + (unsigned)(kb % 3) * STAGE;

        // S = Q @ K^T
        float s[8][4] = {};
#pragma unroll
        for (int kk = 0; kk < 4; kk++) {
            const unsigned kb2 = kk * 32;
#pragma unroll
            for (int j = 0; j < 4; j++) {
                unsigned b0, b1, b2, b3;
                ldsm4(b0, b1, b2, b3, kbase_s + koff[j] + kb2);
                mma_f16(s[2 * j][0], s[2 * j][1], s[2 * j][2], s[2 * j][3],
                        qf[kk][0], qf[kk][1], qf[kk][2], qf[kk][3], b0, b1);
                mma_f16(s[2 * j + 1][0], s[2 * j + 1][1], s[2 * j + 1][2], s[2 * j + 1][3],
                        qf[kk][0], qf[kk][1], qf[kk][2], qf[kk][3], b2, b3);
            }
        }

        if (kb >= 2 * qb) {
            const int cb = kb * 64;
#pragma unroll
            for (int nt = 0; nt < 8; nt++) {
                const int c0 = cb + nt * 8 + 2 * t;
                if (c0 > r0)     s[nt][0] = -1e30f;
                if (c0 + 1 > r0) s[nt][1] = -1e30f;
                if (c0 > r1)     s[nt][2] = -1e30f;
                if (c0 + 1 > r1) s[nt][3] = -1e30f;
            }
        }

        float mx0 = -1e30f, mx1 = -1e30f;
#pragma unroll
        for (int nt = 0; nt < 8; nt++) {
            mx0 = fmaxf(mx0, fmaxf(s[nt][0], s[nt][1]));
            mx1 = fmaxf(mx1, fmaxf(s[nt][2], s[nt][3]));
        }
        mx0 = fmaxf(mx0, __shfl_xor_sync(0xffffffffu, mx0, 1));
        mx0 = fmaxf(mx0, __shfl_xor_sync(0xffffffffu, mx0, 2));
        mx1 = fmaxf(mx1, __shfl_xor_sync(0xffffffffu, mx1, 1));
        mx1 = fmaxf(mx1, __shfl_xor_sync(0xffffffffu, mx1, 2));

        const float nm0 = fmaxf(m0, mx0);
        const float nm1 = fmaxf(m1, mx1);
        const float cr0 = __expf(m0 - nm0);
        const float cr1 = __expf(m1 - nm1);
        m0 = nm0; m1 = nm1;

        float sm0 = 0.f, sm1 = 0.f;
#pragma unroll
        for (int nt = 0; nt < 8; nt++) {
            float p0 = __expf(s[nt][0] - nm0);
            float p1 = __expf(s[nt][1] - nm0);
            float p2 = __expf(s[nt][2] - nm1);
            float p3 = __expf(s[nt][3] - nm1);
            s[nt][0] = p0; s[nt][1] = p1; s[nt][2] = p2; s[nt][3] = p3;
            sm0 += p0 + p1;
            sm1 += p2 + p3;
        }
        sm0 += __shfl_xor_sync(0xffffffffu, sm0, 1);
        sm0 += __shfl_xor_sync(0xffffffffu, sm0, 2);
        sm1 += __shfl_xor_sync(0xffffffffu, sm1, 1);
        sm1 += __shfl_xor_sync(0xffffffffu, sm1, 2);
        l0 = l0 * cr0 + sm0;
        l1 = l1 * cr1 + sm1;

#pragma unroll
        for (int nt = 0; nt < 8; nt++) {
            o[nt][0] *= cr0; o[nt][1] *= cr0;
            o[nt][2] *= cr1; o[nt][3] *= cr1;
        }

        // O += P @ V
#pragma unroll
        for (int kk = 0; kk < 4; kk++) {
            unsigned a0 = pack_h2(s[2 * kk][0], s[2 * kk][1]);
            unsigned a1 = pack_h2(s[2 * kk][2], s[2 * kk][3]);
            unsigned a2 = pack_h2(s[2 * kk + 1][0], s[2 * kk + 1][1]);
            unsigned a3 = pack_h2(s[2 * kk + 1][2], s[2 * kk + 1][3]);
            const unsigned kb2 = kk * 16 * SR * 2;
#pragma unroll
            for (int j = 0; j < 4; j++) {
                unsigned b0, b1, b2, b3;
                ldsm4t(b0, b1, b2, b3, kbase_s + voff[j] + kb2);
                mma_f16(o[2 * j][0], o[2 * j][1], o[2 * j][2], o[2 * j][3],
                        a0, a1, a2, a3, b0, b1);
                mma_f16(o[2 * j + 1][0], o[2 * j + 1][1], o[2 * j + 1][2], o[2 * j + 1][3],
                        a0, a1, a2, a3, b2, b3);
            }
        }
        __syncthreads();
    }

    const float inv0 = 1.f / l0;
    const float inv1 = 1.f / l1;
    __half* o0p = O + (size_t)r0 * CDIM + h * HD;
    __half* o1p = O + (size_t)r1 * CDIM + h * HD;
#pragma unroll
    for (int nt = 0; nt < 8; nt++) {
        const int c = nt * 8 + 2 * t;
        *reinterpret_cast<unsigned*>(o0p + c) = pack_h2(o[nt][0] * inv0, o[nt][1] * inv0);
        *reinterpret_cast<unsigned*>(o1p + c) = pack_h2(o[nt][2] * inv1, o[nt][3] * inv1);
    }
}

// ---------------- fused residual add + LayerNorm ---------------------------
template <bool DUALOUT>
__global__ __launch_bounds__(256) void add_ln(
    const float* __restrict__ A, const float* __restrict__ Bb,
    const float* __restrict__ g, const float* __restrict__ be,
    float* __restrict__ out, __half* __restrict__ out_h)
{
    const int row = blockIdx.x;
    const int tid = threadIdx.x;
    const float* pa = A + (size_t)row * CDIM;
    const float* pb = Bb + (size_t)row * CDIM;

    float v[3];
    float s = 0.f, sq = 0.f;
#pragma unroll
    for (int i = 0; i < 3; i++) {
        int idx = tid + i * 256;
        v[i] = pa[idx] + pb[idx];
        s += v[i];
        sq += v[i] * v[i];
    }
#pragma unroll
    for (int off = 16; off; off >>= 1) {
        s += __shfl_xor_sync(0xffffffffu, s, off);
        sq += __shfl_xor_sync(0xffffffffu, sq, off);
    }
    __shared__ float ss[8], ssq[8];
    int w = tid >> 5, lane = tid & 31;
    if (lane == 0) { ss[w] = s; ssq[w] = sq; }
    __syncthreads();
    if (tid < 32) {
        s = (tid < 8) ? ss[tid] : 0.f;
        sq = (tid < 8) ? ssq[tid] : 0.f;
#pragma unroll
        for (int off = 4; off; off >>= 1) {
            s += __shfl_xor_sync(0xffffffffu, s, off);
            sq += __shfl_xor_sync(0xffffffffu, sq, off);
        }
        if (tid == 0) { ss[0] = s; ssq[0] = sq; }
    }
    __syncthreads();
    const float mean = ss[0] * (1.0f / CDIM);
    const float var = ssq[0] * (1.0f / CDIM) - mean * mean;
    const float inv = rsqrtf(var + 1e-5f);
#pragma unroll
    for (int i = 0; i < 3; i++) {
        int idx = tid + i * 256;
        float r = (v[i] - mean) * inv * g[idx] + be[idx];
        out[(size_t)row * CDIM + idx] = r;
        if (DUALOUT)
            out_h[(size_t)row * CDIM + idx] = __float2half_rn(r);
    }
}

// ---------------- launch ----------------------------------------------------
extern "C" void kernel_launch(void* const* d_in, const int* in_sizes, int n_in,
                              void* d_out, int out_size)
{
    const float* x     = (const float*)d_in[0];
    const float* Wq    = (const float*)d_in[1];
    const float* bq    = (const float*)d_in[2];
    const float* Wk    = (const float*)d_in[3];
    const float* bk    = (const float*)d_in[4];
    const float* Wv    = (const float*)d_in[5];
    const float* bv    = (const float*)d_in[6];
    const float* Wo    = (const float*)d_in[7];
    const float* bo    = (const float*)d_in[8];
    const float* ln1g  = (const float*)d_in[9];
    const float* ln1b  = (const float*)d_in[10];
    const float* W1    = (const float*)d_in[11];
    const float* b1    = (const float*)d_in[12];
    const float* W2    = (const float*)d_in[13];
    const float* b2    = (const float*)d_in[14];
    const float* ln2g  = (const float*)d_in[15];
    const float* ln2b  = (const float*)d_in[16];
    float* y = (float*)d_out;

    __half *q, *k, *v, *attn, *hh, *m1, *xh, *wq, *wk, *wv, *wo, *w1, *w2;
    float *proj, *h, *m2;
    cudaGetSymbolAddress((void**)&q,    g_q);
    cudaGetSymbolAddress((void**)&k,    g_k);
    cudaGetSymbolAddress((void**)&v,    g_v);
    cudaGetSymbolAddress((void**)&attn, g_attn);
    cudaGetSymbolAddress((void**)&proj, g_proj);
    cudaGetSymbolAddress((void**)&h,    g_h);
    cudaGetSymbolAddress((void**)&hh,   g_hh);
    cudaGetSymbolAddress((void**)&m1,   g_mlp1);
    cudaGetSymbolAddress((void**)&m2,   g_mlp2);
    cudaGetSymbolAddress((void**)&xh,   g_xh);
    cudaGetSymbolAddress((void**)&wq,   g_wq);
    cudaGetSymbolAddress((void**)&wk,   g_wk);
    cudaGetSymbolAddress((void**)&wv,   g_wv);
    cudaGetSymbolAddress((void**)&wo,   g_wo);
    cudaGetSymbolAddress((void**)&w1,   g_w1);
    cudaGetSymbolAddress((void**)&w2,   g_w2);

    const int SMEM_128 = 3 * (128 + 128) * 72 * 2;   // 110592
    const int SMEM_64  = 3 * (64 + 128) * 72 * 2;    // 82944
    const int SMEM_FA  = 3 * 2 * 64 * 72 * 2;        // 55296
    cudaFuncSetAttribute(gemm_h_qkv, cudaFuncAttributeMaxDynamicSharedMemorySize, SMEM_128);
    cudaFuncSetAttribute(gemm_h<128, true, __half>, cudaFuncAttributeMaxDynamicSharedMemorySize, SMEM_128);
    cudaFuncSetAttribute(gemm_h<64, false, float>,  cudaFuncAttributeMaxDynamicSharedMemorySize, SMEM_64);
    cudaFuncSetAttribute(flash_attn_h, cudaFuncAttributeMaxDynamicSharedMemorySize, SMEM_FA);

    // converts
    cvt_h_kernel<<<SEQ * CDIM / 1024, 256>>>(x, xh, SEQ * CDIM);
    Ptr4 p4 = { Wq, Wk, Wv, Wo, wq, wk, wv, wo };
    cvt_t4_kernel<<<dim3(CDIM / 32, CDIM / 32, 4), 256>>>(p4);
    cvt_t_kernel<<<dim3(CDIM / 32, FDIM / 32), 256>>>(W1, w1, CDIM, FDIM);
    cvt_t_kernel<<<dim3(FDIM / 32, CDIM / 32), 256>>>(W2, w2, FDIM, CDIM);

    // fused QKV projection (BM=128)
    gemm_h_qkv<<<dim3(18, SEQ / 128), 256, SMEM_128>>>(xh, wq, wk, wv, bq, bk, bv, q, k, v);

    // causal attention
    flash_attn_h<<<dim3(SEQ / 128, NH), 256, SMEM_FA>>>(q, k, v, attn);

    // output projection (BM=64, 384 CTAs for balance)
    gemm_h<64, false, float><<<dim3(CDIM / 128, SEQ / 64), 256, SMEM_64>>>(attn, wo, bo, proj, CDIM, CDIM);

    // h = LN(x + proj), plus half copy for W1
    add_ln<true><<<SEQ, 256>>>(x, proj, ln1g, ln1b, h, hh);

    // MLP
    gemm_h<128, true, __half><<<dim3(FDIM / 128, SEQ / 128), 256, SMEM_128>>>(hh, w1, b1, m1, FDIM, CDIM);
    gemm_h<64, false, float><<<dim3(CDIM / 128, SEQ / 64), 256, SMEM_64>>>(m1, w2, b2, m2, CDIM, FDIM);

    // y = LN(h + mlp)
    add_ln<false><<<SEQ, 256>>>(h, m2, ln2g, ln2b, y, nullptr);

    (void)in_sizes; (void)n_in; (void)out_size;
}

// round 10
// speedup vs baseline: 8.3516x; 1.0338x over previous
#include <cuda_runtime.h>
#include <cuda_fp16.h>
#include <math.h>
#include <cstdint>
#include <stdint.h>

#define SEQ 4096
#define CDIM 768
#define NH 12
#define HD 64
#define FDIM 3072

// ---------------- scratch (device globals; no allocation allowed) ----------
__device__ __half g_q[SEQ * CDIM];
__device__ __half g_k[SEQ * CDIM];
__device__ __half g_v[SEQ * CDIM];
__device__ __half g_attn[SEQ * CDIM];
__device__ float  g_proj[SEQ * CDIM];
__device__ float  g_h[SEQ * CDIM];
__device__ __half g_hh[SEQ * CDIM];
__device__ __half g_mlp1[SEQ * FDIM];
__device__ float  g_mlp2[SEQ * CDIM];
__device__ __half g_xh[SEQ * CDIM];
__device__ __half g_wq[CDIM * CDIM];     // [K,N] half (natural layout)
__device__ __half g_wk[CDIM * CDIM];
__device__ __half g_wv[CDIM * CDIM];
__device__ __half g_wo[CDIM * CDIM];
__device__ __half g_w1[CDIM * FDIM];     // [K=C, N=F]
__device__ __half g_w2[FDIM * CDIM];     // [K=F, N=C]

__device__ __forceinline__ void cp16(unsigned int dst, const void* src) {
    asm volatile("cp.async.cg.shared.global [%0], [%1], 16;" :: "r"(dst), "l"(src));
}
__device__ __forceinline__ void cp_commit() { asm volatile("cp.async.commit_group;"); }
__device__ __forceinline__ void cp_wait0() { asm volatile("cp.async.wait_group 0;"); }
__device__ __forceinline__ void cp_wait1() { asm volatile("cp.async.wait_group 1;"); }

__device__ __forceinline__ unsigned smem_u32(const void* p) {
    unsigned a;
    asm("{ .reg .u64 t; cvta.to.shared.u64 t, %1; cvt.u32.u64 %0, t; }" : "=r"(a) : "l"(p));
    return a;
}

__device__ __forceinline__ void mma_f16(
    float& d0, float& d1, float& d2, float& d3,
    unsigned a0, unsigned a1, unsigned a2, unsigned a3,
    unsigned b0, unsigned b1)
{
    asm volatile(
        "mma.sync.aligned.m16n8k16.row.col.f32.f16.f16.f32 "
        "{%0,%1,%2,%3},{%4,%5,%6,%7},{%8,%9},{%0,%1,%2,%3};"
        : "+f"(d0), "+f"(d1), "+f"(d2), "+f"(d3)
        : "r"(a0), "r"(a1), "r"(a2), "r"(a3), "r"(b0), "r"(b1));
}

__device__ __forceinline__ void ldsm4(
    unsigned& r0, unsigned& r1, unsigned& r2, unsigned& r3, unsigned addr)
{
    asm volatile("ldmatrix.sync.aligned.m8n8.x4.shared.b16 {%0,%1,%2,%3}, [%4];"
                 : "=r"(r0), "=r"(r1), "=r"(r2), "=r"(r3) : "r"(addr));
}

__device__ __forceinline__ void ldsm4t(
    unsigned& r0, unsigned& r1, unsigned& r2, unsigned& r3, unsigned addr)
{
    asm volatile("ldmatrix.sync.aligned.m8n8.x4.trans.shared.b16 {%0,%1,%2,%3}, [%4];"
                 : "=r"(r0), "=r"(r1), "=r"(r2), "=r"(r3) : "r"(addr));
}

__device__ __forceinline__ unsigned pack_h2(float lo, float hi) {
    __half2 h = __floats2half2_rn(lo, hi);
    return *reinterpret_cast<unsigned*>(&h);
}

// ---------------- fused float -> half converts (7 segments) -----------------
struct CvtSeg { const float* src; __half* dst; int n; };
struct CvtArgs { CvtSeg s[7]; };

__global__ __launch_bounds__(256) void cvt_all_kernel(CvtArgs a)
{
    const CvtSeg seg = a.s[blockIdx.y];
    int i = (blockIdx.x * 256 + threadIdx.x) * 4;
    if (i < seg.n) {
        float4 v = *reinterpret_cast<const float4*>(seg.src + i);
        uint2 u;
        u.x = pack_h2(v.x, v.y);
        u.y = pack_h2(v.z, v.w);
        *reinterpret_cast<uint2*>(seg.dst + i) = u;
    }
}

// ---------------- FP16 tensor-core GEMM (natural-layout B, ldmatrix.trans) --
// C[M,N] = A[M,K] @ B[K,N] + bias.  A row-major [M,K], B row-major [K,N].
// Tile BMx128, BK=64, 3-stage cp.async, 256 thr = 8 warps (4Mx2N), 2 CTAs/SM.
template <int BM, bool GELU, typename OutT>
__device__ __forceinline__ void gemm_h_body(
    const __half* __restrict__ A, const __half* __restrict__ B,
    const float* __restrict__ bias, OutT* __restrict__ C,
    int N, int K, int bx, int by)
{
    constexpr int BK = 64, SRA = 72, SRB = 136;
    constexpr int MT = BM / 64;
    constexpr unsigned ABYTES = BM * SRA * 2;
    constexpr unsigned BBYTES = BK * SRB * 2;      // 17408
    constexpr unsigned STAGE = ABYTES + BBYTES;

    extern __shared__ __half smh[];
    const unsigned smb = smem_u32(smh);

    const int tid = threadIdx.x, lane = tid & 31, warp = tid >> 5;
    const int wm = warp & 3, wn = warp >> 2, g = lane >> 2, t = lane & 3;

    // A frag offsets (non-trans ldmatrix)
    const int lr = lane & 15;
    const int lc = (lane >> 4) << 3;
    unsigned aoff[MT];
#pragma unroll
    for (int mt = 0; mt < MT; mt++)
        aoff[mt] = ((wm * (BM / 4) + mt * 16 + lr) * SRA + lc) * 2;

    // B frag offsets (trans ldmatrix on [k][n] tile) — flash V pattern
    const int vr = lane & 15;                      // k-row within 16
    const int vc = (lane >> 4) << 3;               // n offset 0/8
    unsigned boff[4];
#pragma unroll
    for (int j = 0; j < 4; j++)
        boff[j] = ABYTES + (vr * SRB + wn * 64 + j * 16 + vc) * 2;

    // loaders
    constexpr int AU = BM / 32;                    // A 16B-units per thread
    const int u0a = tid * AU;
    const int u0b = tid * 4;                        // B: 64 rows x 16 units
    const __half* Abase = A + (size_t)(by * BM) * K;
    const __half* Bbase = B + (size_t)bx * 128;

    const int nchunks = K / BK;

    auto prefetch = [&](int ch) {
        const unsigned dst = smb + (unsigned)(ch % 3) * STAGE;
        const int k0 = ch * BK;
#pragma unroll
        for (int j = 0; j < AU; j++) {
            const int u = u0a + j, row = u >> 3, c16 = u & 7;
            cp16(dst + (unsigned)(row * SRA + c16 * 8) * 2,
                 Abase + (size_t)row * K + k0 + c16 * 8);
        }
#pragma unroll
        for (int j = 0; j < 4; j++) {
            const int u = u0b + j, row = u >> 4, c16 = u & 15;
            cp16(dst + ABYTES + (unsigned)(row * SRB + c16 * 8) * 2,
                 Bbase + (size_t)(k0 + row) * N + c16 * 8);
        }
        cp_commit();
    };

    float acc[MT][8][4] = {};

    prefetch(0);
    prefetch(1);

    for (int ch = 0; ch < nchunks; ch++) {
        if (ch + 1 < nchunks) cp_wait1(); else cp_wait0();
        __syncthreads();
        if (ch + 2 < nchunks) prefetch(ch + 2);

        const unsigned sbase = smb + (unsigned)(ch % 3) * STAGE;
#pragma unroll
        for (int kk = 0; kk < 4; kk++) {
            unsigned af[MT][4], bf[8][2];
#pragma unroll
            for (int mt = 0; mt < MT; mt++)
                ldsm4(af[mt][0], af[mt][1], af[mt][2], af[mt][3],
                      sbase + aoff[mt] + kk * 32);
            const unsigned kadv = (unsigned)(kk * 16 * SRB * 2);
#pragma unroll
            for (int j = 0; j < 4; j++)
                ldsm4t(bf[2 * j][0], bf[2 * j][1], bf[2 * j + 1][0], bf[2 * j + 1][1],
                       sbase + boff[j] + kadv);
#pragma unroll
            for (int mt = 0; mt < MT; mt++)
#pragma unroll
                for (int nt = 0; nt < 8; nt++)
                    mma_f16(acc[mt][nt][0], acc[mt][nt][1], acc[mt][nt][2], acc[mt][nt][3],
                            af[mt][0], af[mt][1], af[mt][2], af[mt][3],
                            bf[nt][0], bf[nt][1]);
        }
    }

#pragma unroll
    for (int mt = 0; mt < MT; mt++) {
        const int r0 = by * BM + wm * (BM / 4) + mt * 16 + g;
#pragma unroll
        for (int nt = 0; nt < 8; nt++) {
            const int c0 = bx * 128 + wn * 64 + nt * 8 + t * 2;
            const float bz0 = bias[c0], bz1 = bias[c0 + 1];
            float v0 = acc[mt][nt][0] + bz0;
            float v1 = acc[mt][nt][1] + bz1;
            float v2 = acc[mt][nt][2] + bz0;
            float v3 = acc[mt][nt][3] + bz1;
            if (GELU) {
                v0 = 0.5f * v0 * (1.0f + erff(v0 * 0.70710678118654752f));
                v1 = 0.5f * v1 * (1.0f + erff(v1 * 0.70710678118654752f));
                v2 = 0.5f * v2 * (1.0f + erff(v2 * 0.70710678118654752f));
                v3 = 0.5f * v3 * (1.0f + erff(v3 * 0.70710678118654752f));
            }
            if (sizeof(OutT) == 2) {
                __half* Ch = reinterpret_cast<__half*>(C);
                *reinterpret_cast<unsigned*>(Ch + (size_t)r0 * N + c0) = pack_h2(v0, v1);
                *reinterpret_cast<unsigned*>(Ch + (size_t)(r0 + 8) * N + c0) = pack_h2(v2, v3);
            } else {
                float* Cf = reinterpret_cast<float*>(C);
                *reinterpret_cast<float2*>(Cf + (size_t)r0 * N + c0) = make_float2(v0, v1);
                *reinterpret_cast<float2*>(Cf + (size_t)(r0 + 8) * N + c0) = make_float2(v2, v3);
            }
        }
    }
}

template <int BM, bool GELU, typename OutT>
__global__ __launch_bounds__(256, 2) void gemm_h(
    const __half* __restrict__ A, const __half* __restrict__ B,
    const float* __restrict__ bias, OutT* __restrict__ C, int N, int K)
{
    gemm_h_body<BM, GELU, OutT>(A, B, bias, C, N, K, blockIdx.x, blockIdx.y);
}

__global__ __launch_bounds__(256, 2) void gemm_h_qkv(
    const __half* __restrict__ X,
    const __half* __restrict__ Wqh, const __half* __restrict__ Wkh, const __half* __restrict__ Wvh,
    const float* __restrict__ bq, const float* __restrict__ bk, const float* __restrict__ bv,
    __half* __restrict__ q, __half* __restrict__ k, __half* __restrict__ v)
{
    const int which = blockIdx.x / 6;
    const int bx = blockIdx.x % 6;
    const __half* B   = (which == 0) ? Wqh : (which == 1) ? Wkh : Wvh;
    const float* bias = (which == 0) ? bq  : (which == 1) ? bk  : bv;
    __half* C         = (which == 0) ? q   : (which == 1) ? k   : v;
    gemm_h_body<128, false, __half>(X, B, bias, C, CDIM, CDIM, bx, blockIdx.y);
}

// ---------------- FP16 flash attention (3-stage cp.async + ldmatrix) --------
// grid (NH, SEQ/128) — globally heaviest q-blocks scheduled first.
__global__ __launch_bounds__(256, 2) void flash_attn_h(
    const __half* __restrict__ Q, const __half* __restrict__ K,
    const __half* __restrict__ V, __half* __restrict__ O)
{
    constexpr int SR = 72;
    constexpr unsigned TILE = 64 * SR * 2;
    constexpr unsigned STAGE = 2 * TILE;

    extern __shared__ __half smh[];
    const unsigned kvb = smem_u32(smh);

    const int h  = blockIdx.x;
    const int qb = (gridDim.y - 1) - blockIdx.y;   // heavy blocks first
    const int tid  = threadIdx.x;
    const int lane = tid & 31;
    const int w = tid >> 5;
    const int g = lane >> 2;
    const int t = lane & 3;

    const int r0 = qb * 128 + w * 16 + g;
    const int r1 = r0 + 8;

    unsigned qf[4][4];
    {
        const __half2 sc = __float2half2_rn(0.125f);
        const __half* q0p = Q + (size_t)r0 * CDIM + h * HD;
        const __half* q1p = Q + (size_t)r1 * CDIM + h * HD;
#pragma unroll
        for (int kk = 0; kk < 4; kk++) {
            __half2 x0 = __hmul2(*reinterpret_cast<const __half2*>(q0p + kk * 16 + 2 * t), sc);
            __half2 x1 = __hmul2(*reinterpret_cast<const __half2*>(q1p + kk * 16 + 2 * t), sc);
            __half2 x2 = __hmul2(*reinterpret_cast<const __half2*>(q0p + kk * 16 + 2 * t + 8), sc);
            __half2 x3 = __hmul2(*reinterpret_cast<const __half2*>(q1p + kk * 16 + 2 * t + 8), sc);
            qf[kk][0] = *reinterpret_cast<unsigned*>(&x0);
            qf[kk][1] = *reinterpret_cast<unsigned*>(&x1);
            qf[kk][2] = *reinterpret_cast<unsigned*>(&x2);
            qf[kk][3] = *reinterpret_cast<unsigned*>(&x3);
        }
    }

    const int rb = (lane & 7) | ((lane & 16) >> 1);
    const int cbh = lane & 8;
    unsigned koff[4];
#pragma unroll
    for (int j = 0; j < 4; j++)
        koff[j] = ((j * 16 + rb) * SR + cbh) * 2;
    const int vr = lane & 15;
    const int vc = (lane >> 4) << 3;
    unsigned voff[4];
#pragma unroll
    for (int j = 0; j < 4; j++)
        voff[j] = TILE + (vr * SR + j * 16 + vc) * 2;

    float o[8][4] = {};
    float m0 = -1e30f, m1 = -1e30f, l0 = 0.f, l1 = 0.f;

    const int u0 = tid * 2;
    const int ntiles = 2 * (qb + 1);

    auto prefetch = [&](int kb) {
        const unsigned dst = kvb + (unsigned)(kb % 3) * STAGE;
        const int kbase = kb * 64;
#pragma unroll
        for (int j = 0; j < 2; j++) {
            const int u = u0 + j, row = u >> 3, c = u & 7;
            const unsigned off = (unsigned)(row * SR + c * 8) * 2;
            cp16(dst + off, K + (size_t)(kbase + row) * CDIM + h * HD + c * 8);
            cp16(dst + TILE + off, V + (size_t)(kbase + row) * CDIM + h * HD + c * 8);
        }
        cp_commit();
    };

    prefetch(0);
    if (ntiles > 1) prefetch(1);

    for (int kb = 0; kb < ntiles; kb++) {
        if (kb + 1 < ntiles) cp_wait1(); else cp_wait0();
        __syncthreads();
        if (kb + 2 < ntiles) prefetch(kb + 2);

        const unsigned kbase_s = kvb + (unsigned)(kb % 3) * STAGE;

        float s[8][4] = {};
#pragma unroll
        for (int kk = 0; kk < 4; kk++) {
            const unsigned kb2 = kk * 32;
#pragma unroll
            for (int j = 0; j < 4; j++) {
                unsigned b0, b1, b2, b3;
                ldsm4(b0, b1, b2, b3, kbase_s + koff[j] + kb2);
                mma_f16(s[2 * j][0], s[2 * j][1], s[2 * j][2], s[2 * j][3],
                        qf[kk][0], qf[kk][1], qf[kk][2], qf[kk][3], b0, b1);
                mma_f16(s[2 * j + 1][0], s[2 * j + 1][1], s[2 * j + 1][2], s[2 * j + 1][3],
                        qf[kk][0], qf[kk][1], qf[kk][2], qf[kk][3], b2, b3);
            }
        }

        if (kb >= 2 * qb) {
            const int cb = kb * 64;
#pragma unroll
            for (int nt = 0; nt < 8; nt++) {
                const int c0 = cb + nt * 8 + 2 * t;
                if (c0 > r0)     s[nt][0] = -1e30f;
                if (c0 + 1 > r0) s[nt][1] = -1e30f;
                if (c0 > r1)     s[nt][2] = -1e30f;
                if (c0 + 1 > r1) s[nt][3] = -1e30f;
            }
        }

        float mx0 = -1e30f, mx1 = -1e30f;
#pragma unroll
        for (int nt = 0; nt < 8; nt++) {
            mx0 = fmaxf(mx0, fmaxf(s[nt][0], s[nt][1]));
            mx1 = fmaxf(mx1, fmaxf(s[nt][2], s[nt][3]));
        }
        mx0 = fmaxf(mx0, __shfl_xor_sync(0xffffffffu, mx0, 1));
        mx0 = fmaxf(mx0, __shfl_xor_sync(0xffffffffu, mx0, 2));
        mx1 = fmaxf(mx1, __shfl_xor_sync(0xffffffffu, mx1, 1));
        mx1 = fmaxf(mx1, __shfl_xor_sync(0xffffffffu, mx1, 2));

        const float nm0 = fmaxf(m0, mx0);
        const float nm1 = fmaxf(m1, mx1);
        const float cr0 = __expf(m0 - nm0);
        const float cr1 = __expf(m1 - nm1);
        m0 = nm0; m1 = nm1;

        float sm0 = 0.f, sm1 = 0.f;
#pragma unroll
        for (int nt = 0; nt < 8; nt++) {
            float p0 = __expf(s[nt][0] - nm0);
            float p1 = __expf(s[nt][1] - nm0);
            float p2 = __expf(s[nt][2] - nm1);
            float p3 = __expf(s[nt][3] - nm1);
            s[nt][0] = p0; s[nt][1] = p1; s[nt][2] = p2; s[nt][3] = p3;
            sm0 += p0 + p1;
            sm1 += p2 + p3;
        }
        sm0 += __shfl_xor_sync(0xffffffffu, sm0, 1);
        sm0 += __shfl_xor_sync(0xffffffffu, sm0, 2);
        sm1 += __shfl_xor_sync(0xffffffffu, sm1, 1);
        sm1 += __shfl_xor_sync(0xffffffffu, sm1, 2);
        l0 = l0 * cr0 + sm0;
        l1 = l1 * cr1 + sm1;

#pragma unroll
        for (int nt = 0; nt < 8; nt++) {
            o[nt][0] *= cr0; o[nt][1] *= cr0;
            o[nt][2] *= cr1; o[nt][3] *= cr1;
        }

#pragma unroll
        for (int kk = 0; kk < 4; kk++) {
            unsigned a0 = pack_h2(s[2 * kk][0], s[2 * kk][1]);
            unsigned a1 = pack_h2(s[2 * kk][2], s[2 * kk][3]);
            unsigned a2 = pack_h2(s[2 * kk + 1][0], s[2 * kk + 1][1]);
            unsigned a3 = pack_h2(s[2 * kk + 1][2], s[2 * kk + 1][3]);
            const unsigned kb2 = kk * 16 * SR * 2;
#pragma unroll
            for (int j = 0; j < 4; j++) {
                unsigned b0, b1, b2, b3;
                ldsm4t(b0, b1, b2, b3, kbase_s + voff[j] + kb2);
                mma_f16(o[2 * j][0], o[2 * j][1], o[2 * j][2], o[2 * j][3],
                        a0, a1, a2, a3, b0, b1);
                mma_f16(o[2 * j + 1][0], o[2 * j + 1][1], o[2 * j + 1][2], o[2 * j + 1][3],
                        a0, a1, a2, a3, b2, b3);
            }
        }
    }

    const float inv0 = 1.f / l0;
    const float inv1 = 1.f / l1;
    __half* o0p = O + (size_t)r0 * CDIM + h * HD;
    __half* o1p = O + (size_t)r1 * CDIM + h * HD;
#pragma unroll
    for (int nt = 0; nt < 8; nt++) {
        const int c = nt * 8 + 2 * t;
        *reinterpret_cast<unsigned*>(o0p + c) = pack_h2(o[nt][0] * inv0, o[nt][1] * inv0);
        *reinterpret_cast<unsigned*>(o1p + c) = pack_h2(o[nt][2] * inv1, o[nt][3] * inv1);
    }
}

// ---------------- fused residual add + LayerNorm ---------------------------
template <bool DUALOUT>
__global__ __launch_bounds__(256) void add_ln(
    const float* __restrict__ A, const float* __restrict__ Bb,
    const float* __restrict__ g, const float* __restrict__ be,
    float* __restrict__ out, __half* __restrict__ out_h)
{
    const int row = blockIdx.x;
    const int tid = threadIdx.x;
    const float* pa = A + (size_t)row * CDIM;
    const float* pb = Bb + (size_t)row * CDIM;

    float v[3];
    float s = 0.f, sq = 0.f;
#pragma unroll
    for (int i = 0; i < 3; i++) {
        int idx = tid + i * 256;
        v[i] = pa[idx] + pb[idx];
        s += v[i];
        sq += v[i] * v[i];
    }
#pragma unroll
    for (int off = 16; off; off >>= 1) {
        s += __shfl_xor_sync(0xffffffffu, s, off);
        sq += __shfl_xor_sync(0xffffffffu, sq, off);
    }
    __shared__ float ss[8], ssq[8];
    int w = tid >> 5, lane = tid & 31;
    if (lane == 0) { ss[w] = s; ssq[w] = sq; }
    __syncthreads();
    if (tid < 32) {
        s = (tid < 8) ? ss[tid] : 0.f;
        sq = (tid < 8) ? ssq[tid] : 0.f;
#pragma unroll
        for (int off = 4; off; off >>= 1) {
            s += __shfl_xor_sync(0xffffffffu, s, off);
            sq += __shfl_xor_sync(0xffffffffu, sq, off);
        }
        if (tid == 0) { ss[0] = s; ssq[0] = sq; }
    }
    __syncthreads();
    const float mean = ss[0] * (1.0f / CDIM);
    const float var = ssq[0] * (1.0f / CDIM) - mean * mean;
    const float inv = rsqrtf(var + 1e-5f);
#pragma unroll
    for (int i = 0; i < 3; i++) {
        int idx = tid + i * 256;
        float r = (v[i] - mean) * inv * g[idx] + be[idx];
        out[(size_t)row * CDIM + idx] = r;
        if (DUALOUT)
            out_h[(size_t)row * CDIM + idx] = __float2half_rn(r);
    }
}

// ---------------- launch ----------------------------------------------------
extern "C" void kernel_launch(void* const* d_in, const int* in_sizes, int n_in,
                              void* d_out, int out_size)
{
    const float* x     = (const float*)d_in[0];
    const float* Wq    = (const float*)d_in[1];
    const float* bq    = (const float*)d_in[2];
    const float* Wk    = (const float*)d_in[3];
    const float* bk    = (const float*)d_in[4];
    const float* Wv    = (const float*)d_in[5];
    const float* bv    = (const float*)d_in[6];
    const float* Wo    = (const float*)d_in[7];
    const float* bo    = (const float*)d_in[8];
    const float* ln1g  = (const float*)d_in[9];
    const float* ln1b  = (const float*)d_in[10];
    const float* W1    = (const float*)d_in[11];
    const float* b1    = (const float*)d_in[12];
    const float* W2    = (const float*)d_in[13];
    const float* b2    = (const float*)d_in[14];
    const float* ln2g  = (const float*)d_in[15];
    const float* ln2b  = (const float*)d_in[16];
    float* y = (float*)d_out;

    __half *q, *k, *v, *attn, *hh, *m1, *xh, *wq, *wk, *wv, *wo, *w1, *w2;
    float *proj, *h, *m2;
    cudaGetSymbolAddress((void**)&q,    g_q);
    cudaGetSymbolAddress((void**)&k,    g_k);
    cudaGetSymbolAddress((void**)&v,    g_v);
    cudaGetSymbolAddress((void**)&attn, g_attn);
    cudaGetSymbolAddress((void**)&proj, g_proj);
    cudaGetSymbolAddress((void**)&h,    g_h);
    cudaGetSymbolAddress((void**)&hh,   g_hh);
    cudaGetSymbolAddress((void**)&m1,   g_mlp1);
    cudaGetSymbolAddress((void**)&m2,   g_mlp2);
    cudaGetSymbolAddress((void**)&xh,   g_xh);
    cudaGetSymbolAddress((void**)&wq,   g_wq);
    cudaGetSymbolAddress((void**)&wk,   g_wk);
    cudaGetSymbolAddress((void**)&wv,   g_wv);
    cudaGetSymbolAddress((void**)&wo,   g_wo);
    cudaGetSymbolAddress((void**)&w1,   g_w1);
    cudaGetSymbolAddress((void**)&w2,   g_w2);

    const int SMEM_128 = 3 * (128 * 72 + 64 * 136) * 2;   // 107520
    const int SMEM_64  = 3 * (64 * 72 + 64 * 136) * 2;    // 79872
    const int SMEM_FA  = 3 * 2 * 64 * 72 * 2;             // 55296
    cudaFuncSetAttribute(gemm_h_qkv, cudaFuncAttributeMaxDynamicSharedMemorySize, SMEM_128);
    cudaFuncSetAttribute(gemm_h<128, true, __half>, cudaFuncAttributeMaxDynamicSharedMemorySize, SMEM_128);
    cudaFuncSetAttribute(gemm_h<64, false, float>,  cudaFuncAttributeMaxDynamicSharedMemorySize, SMEM_64);
    cudaFuncSetAttribute(flash_attn_h, cudaFuncAttributeMaxDynamicSharedMemorySize, SMEM_FA);

    // one fused convert launch: x + 6 weights -> half (natural layout)
    CvtArgs ca;
    ca.s[0] = { x,  xh, SEQ * CDIM };
    ca.s[1] = { Wq, wq, CDIM * CDIM };
    ca.s[2] = { Wk, wk, CDIM * CDIM };
    ca.s[3] = { Wv, wv, CDIM * CDIM };
    ca.s[4] = { Wo, wo, CDIM * CDIM };
    ca.s[5] = { W1, w1, CDIM * FDIM };
    ca.s[6] = { W2, w2, FDIM * CDIM };
    cvt_all_kernel<<<dim3(SEQ * CDIM / 1024, 7), 256>>>(ca);

    // fused QKV projection
    gemm_h_qkv<<<dim3(18, SEQ / 128), 256, SMEM_128>>>(xh, wq, wk, wv, bq, bk, bv, q, k, v);

    // causal attention (heavy-first global order)
    flash_attn_h<<<dim3(NH, SEQ / 128), 256, SMEM_FA>>>(q, k, v, attn);

    // output projection (BM=64 for wave balance)
    gemm_h<64, false, float><<<dim3(CDIM / 128, SEQ / 64), 256, SMEM_64>>>(attn, wo, bo, proj, CDIM, CDIM);

    // h = LN(x + proj), plus half copy for W1
    add_ln<true><<<SEQ, 256>>>(x, proj, ln1g, ln1b, h, hh);

    // MLP
    gemm_h<128, true, __half><<<dim3(FDIM / 128, SEQ / 128), 256, SMEM_128>>>(hh, w1, b1, m1, FDIM, CDIM);
    gemm_h<64, false, float><<<dim3(CDIM / 128, SEQ / 64), 256, SMEM_64>>>(m1, w2, b2, m2, CDIM, FDIM);

    // y = LN(h + mlp)
    add_ln<false><<<SEQ, 256>>>(h, m2, ln2g, ln2b, y, nullptr);

    (void)in_sizes; (void)n_in; (void)out_size;
}

// round 11
// speedup vs baseline: 8.4701x; 1.0142x over previous
#include <cuda_runtime.h>
#include <cuda_fp16.h>
#include <math.h>
#include <cstdint>
#include <stdint.h>

#define SEQ 4096
#define CDIM 768
#define NH 12
#define HD 64
#define FDIM 3072

// ---------------- scratch (device globals; no allocation allowed) ----------
__device__ __half g_q[SEQ * CDIM];
__device__ __half g_k[SEQ * CDIM];
__device__ __half g_v[SEQ * CDIM];
__device__ __half g_attn[SEQ * CDIM];
__device__ float  g_proj[SEQ * CDIM];
__device__ float  g_h[SEQ * CDIM];
__device__ __half g_hh[SEQ * CDIM];
__device__ __half g_mlp1[SEQ * FDIM];
__device__ float  g_mlp2[SEQ * CDIM];
__device__ __half g_xh[SEQ * CDIM];
__device__ __half g_wq[CDIM * CDIM];     // [K,N] half (natural layout)
__device__ __half g_wk[CDIM * CDIM];
__device__ __half g_wv[CDIM * CDIM];
__device__ __half g_wo[CDIM * CDIM];
__device__ __half g_w1[CDIM * FDIM];
__device__ __half g_w2[FDIM * CDIM];

__device__ __forceinline__ void cp16(unsigned int dst, const void* src) {
    asm volatile("cp.async.cg.shared.global [%0], [%1], 16;" :: "r"(dst), "l"(src));
}
__device__ __forceinline__ void cp_commit() { asm volatile("cp.async.commit_group;"); }
__device__ __forceinline__ void cp_wait0() { asm volatile("cp.async.wait_group 0;"); }
__device__ __forceinline__ void cp_wait1() { asm volatile("cp.async.wait_group 1;"); }

__device__ __forceinline__ unsigned smem_u32(const void* p) {
    unsigned a;
    asm("{ .reg .u64 t; cvta.to.shared.u64 t, %1; cvt.u32.u64 %0, t; }" : "=r"(a) : "l"(p));
    return a;
}

__device__ __forceinline__ void mma_f16(
    float& d0, float& d1, float& d2, float& d3,
    unsigned a0, unsigned a1, unsigned a2, unsigned a3,
    unsigned b0, unsigned b1)
{
    asm volatile(
        "mma.sync.aligned.m16n8k16.row.col.f32.f16.f16.f32 "
        "{%0,%1,%2,%3},{%4,%5,%6,%7},{%8,%9},{%0,%1,%2,%3};"
        : "+f"(d0), "+f"(d1), "+f"(d2), "+f"(d3)
        : "r"(a0), "r"(a1), "r"(a2), "r"(a3), "r"(b0), "r"(b1));
}

__device__ __forceinline__ void ldsm4(
    unsigned& r0, unsigned& r1, unsigned& r2, unsigned& r3, unsigned addr)
{
    asm volatile("ldmatrix.sync.aligned.m8n8.x4.shared.b16 {%0,%1,%2,%3}, [%4];"
                 : "=r"(r0), "=r"(r1), "=r"(r2), "=r"(r3) : "r"(addr));
}

__device__ __forceinline__ void ldsm4t(
    unsigned& r0, unsigned& r1, unsigned& r2, unsigned& r3, unsigned addr)
{
    asm volatile("ldmatrix.sync.aligned.m8n8.x4.trans.shared.b16 {%0,%1,%2,%3}, [%4];"
                 : "=r"(r0), "=r"(r1), "=r"(r2), "=r"(r3) : "r"(addr));
}

__device__ __forceinline__ unsigned pack_h2(float lo, float hi) {
    __half2 h = __floats2half2_rn(lo, hi);
    return *reinterpret_cast<unsigned*>(&h);
}

// ---------------- fused float -> half converts (7 segments) -----------------
struct CvtSeg { const float* src; __half* dst; int n; };
struct CvtArgs { CvtSeg s[7]; };

__global__ __launch_bounds__(256) void cvt_all_kernel(CvtArgs a)
{
    const CvtSeg seg = a.s[blockIdx.y];
    int i = (blockIdx.x * 256 + threadIdx.x) * 4;
    if (i < seg.n) {
        float4 v = *reinterpret_cast<const float4*>(seg.src + i);
        uint2 u;
        u.x = pack_h2(v.x, v.y);
        u.y = pack_h2(v.z, v.w);
        *reinterpret_cast<uint2*>(seg.dst + i) = u;
    }
}

// ---------------- FP16 tensor-core GEMM -------------------------------------
// C[M,N] = A[M,K] @ B[K,N] + bias.  BM=64 x BN=128 tile, BK=64, 2-stage
// cp.async, 256 thr = 8 warps (4Mx2N, warp tile 16x64), 3 CTAs/SM.
template <bool GELU, typename OutT>
__device__ __forceinline__ void gemm_h_body(
    const __half* __restrict__ A, const __half* __restrict__ B,
    const float* __restrict__ bias, OutT* __restrict__ C,
    int N, int K, int bx, int by)
{
    constexpr int BM = 64, BK = 64, SRA = 72, SRB = 136;
    constexpr unsigned ABYTES = BM * SRA * 2;      // 9216
    constexpr unsigned BBYTES = BK * SRB * 2;      // 17408
    constexpr unsigned STAGE = ABYTES + BBYTES;    // 26624

    extern __shared__ __half smh[];
    const unsigned smb = smem_u32(smh);

    const int tid = threadIdx.x, lane = tid & 31, warp = tid >> 5;
    const int wm = warp & 3, wn = warp >> 2, g = lane >> 2, t = lane & 3;

    // A frag offset (non-trans ldmatrix, one 16-row m-tile per warp)
    const int lr = lane & 15;
    const int lc = (lane >> 4) << 3;
    const unsigned aoff = ((wm * 16 + lr) * SRA + lc) * 2;

    // B frag offsets (trans ldmatrix on [k][n] tile)
    const int vr = lane & 15;
    const int vc = (lane >> 4) << 3;
    unsigned boff[4];
#pragma unroll
    for (int j = 0; j < 4; j++)
        boff[j] = ABYTES + (vr * SRB + wn * 64 + j * 16 + vc) * 2;

    // loaders: A 64 rows x 8 units (2/thread); B 64 rows x 16 units (4/thread)
    const int u0a = tid * 2;
    const int u0b = tid * 4;
    const __half* Abase = A + (size_t)(by * BM) * K;
    const __half* Bbase = B + (size_t)bx * 128;

    const int nchunks = K / BK;

    auto prefetch = [&](int ch) {
        const unsigned dst = smb + (unsigned)(ch & 1) * STAGE;
        const int k0 = ch * BK;
#pragma unroll
        for (int j = 0; j < 2; j++) {
            const int u = u0a + j, row = u >> 3, c16 = u & 7;
            cp16(dst + (unsigned)(row * SRA + c16 * 8) * 2,
                 Abase + (size_t)row * K + k0 + c16 * 8);
        }
#pragma unroll
        for (int j = 0; j < 4; j++) {
            const int u = u0b + j, row = u >> 4, c16 = u & 15;
            cp16(dst + ABYTES + (unsigned)(row * SRB + c16 * 8) * 2,
                 Bbase + (size_t)(k0 + row) * N + c16 * 8);
        }
        cp_commit();
    };

    float acc[8][4] = {};

    prefetch(0);

    for (int ch = 0; ch < nchunks; ch++) {
        cp_wait0();
        __syncthreads();
        if (ch + 1 < nchunks) prefetch(ch + 1);

        const unsigned sbase = smb + (unsigned)(ch & 1) * STAGE;
#pragma unroll
        for (int kk = 0; kk < 4; kk++) {
            unsigned a0, a1, a2, a3;
            ldsm4(a0, a1, a2, a3, sbase + aoff + kk * 32);
            const unsigned kadv = (unsigned)(kk * 16 * SRB * 2);
            unsigned bf[8][2];
#pragma unroll
            for (int j = 0; j < 4; j++)
                ldsm4t(bf[2 * j][0], bf[2 * j][1], bf[2 * j + 1][0], bf[2 * j + 1][1],
                       sbase + boff[j] + kadv);
#pragma unroll
            for (int nt = 0; nt < 8; nt++)
                mma_f16(acc[nt][0], acc[nt][1], acc[nt][2], acc[nt][3],
                        a0, a1, a2, a3, bf[nt][0], bf[nt][1]);
        }
        __syncthreads();
    }

    const int r0 = by * BM + wm * 16 + g;
#pragma unroll
    for (int nt = 0; nt < 8; nt++) {
        const int c0 = bx * 128 + wn * 64 + nt * 8 + t * 2;
        const float bz0 = bias[c0], bz1 = bias[c0 + 1];
        float v0 = acc[nt][0] + bz0;
        float v1 = acc[nt][1] + bz1;
        float v2 = acc[nt][2] + bz0;
        float v3 = acc[nt][3] + bz1;
        if (GELU) {
            v0 = 0.5f * v0 * (1.0f + erff(v0 * 0.70710678118654752f));
            v1 = 0.5f * v1 * (1.0f + erff(v1 * 0.70710678118654752f));
            v2 = 0.5f * v2 * (1.0f + erff(v2 * 0.70710678118654752f));
            v3 = 0.5f * v3 * (1.0f + erff(v3 * 0.70710678118654752f));
        }
        if (sizeof(OutT) == 2) {
            __half* Ch = reinterpret_cast<__half*>(C);
            *reinterpret_cast<unsigned*>(Ch + (size_t)r0 * N + c0) = pack_h2(v0, v1);
            *reinterpret_cast<unsigned*>(Ch + (size_t)(r0 + 8) * N + c0) = pack_h2(v2, v3);
        } else {
            float* Cf = reinterpret_cast<float*>(C);
            *reinterpret_cast<float2*>(Cf + (size_t)r0 * N + c0) = make_float2(v0, v1);
            *reinterpret_cast<float2*>(Cf + (size_t)(r0 + 8) * N + c0) = make_float2(v2, v3);
        }
    }
}

template <bool GELU, typename OutT>
__global__ __launch_bounds__(256, 3) void gemm_h(
    const __half* __restrict__ A, const __half* __restrict__ B,
    const float* __restrict__ bias, OutT* __restrict__ C, int N, int K)
{
    gemm_h_body<GELU, OutT>(A, B, bias, C, N, K, blockIdx.x, blockIdx.y);
}

__global__ __launch_bounds__(256, 3) void gemm_h_qkv(
    const __half* __restrict__ X,
    const __half* __restrict__ Wqh, const __half* __restrict__ Wkh, const __half* __restrict__ Wvh,
    const float* __restrict__ bq, const float* __restrict__ bk, const float* __restrict__ bv,
    __half* __restrict__ q, __half* __restrict__ k, __half* __restrict__ v)
{
    const int which = blockIdx.x / 6;
    const int bx = blockIdx.x % 6;
    const __half* B   = (which == 0) ? Wqh : (which == 1) ? Wkh : Wvh;
    const float* bias = (which == 0) ? bq  : (which == 1) ? bk  : bv;
    __half* C         = (which == 0) ? q   : (which == 1) ? k   : v;
    gemm_h_body<false, __half>(X, B, bias, C, CDIM, CDIM, bx, blockIdx.y);
}

// ---------------- FP16 flash attention (3-stage cp.async + ldmatrix) --------
__global__ __launch_bounds__(256, 2) void flash_attn_h(
    const __half* __restrict__ Q, const __half* __restrict__ K,
    const __half* __restrict__ V, __half* __restrict__ O)
{
    constexpr int SR = 72;
    constexpr unsigned TILE = 64 * SR * 2;
    constexpr unsigned STAGE = 2 * TILE;

    extern __shared__ __half smh[];
    const unsigned kvb = smem_u32(smh);

    const int h  = blockIdx.x;
    const int qb = (gridDim.y - 1) - blockIdx.y;   // heavy blocks first
    const int tid  = threadIdx.x;
    const int lane = tid & 31;
    const int w = tid >> 5;
    const int g = lane >> 2;
    const int t = lane & 3;

    const int r0 = qb * 128 + w * 16 + g;
    const int r1 = r0 + 8;

    unsigned qf[4][4];
    {
        const __half2 sc = __float2half2_rn(0.125f);
        const __half* q0p = Q + (size_t)r0 * CDIM + h * HD;
        const __half* q1p = Q + (size_t)r1 * CDIM + h * HD;
#pragma unroll
        for (int kk = 0; kk < 4; kk++) {
            __half2 x0 = __hmul2(*reinterpret_cast<const __half2*>(q0p + kk * 16 + 2 * t), sc);
            __half2 x1 = __hmul2(*reinterpret_cast<const __half2*>(q1p + kk * 16 + 2 * t), sc);
            __half2 x2 = __hmul2(*reinterpret_cast<const __half2*>(q0p + kk * 16 + 2 * t + 8), sc);
            __half2 x3 = __hmul2(*reinterpret_cast<const __half2*>(q1p + kk * 16 + 2 * t + 8), sc);
            qf[kk][0] = *reinterpret_cast<unsigned*>(&x0);
            qf[kk][1] = *reinterpret_cast<unsigned*>(&x1);
            qf[kk][2] = *reinterpret_cast<unsigned*>(&x2);
            qf[kk][3] = *reinterpret_cast<unsigned*>(&x3);
        }
    }

    const int rb = (lane & 7) | ((lane & 16) >> 1);
    const int cbh = lane & 8;
    unsigned koff[4];
#pragma unroll
    for (int j = 0; j < 4; j++)
        koff[j] = ((j * 16 + rb) * SR + cbh) * 2;
    const int vr = lane & 15;
    const int vc = (lane >> 4) << 3;
    unsigned voff[4];
#pragma unroll
    for (int j = 0; j < 4; j++)
        voff[j] = TILE + (vr * SR + j * 16 + vc) * 2;

    float o[8][4] = {};
    float m0 = -1e30f, m1 = -1e30f, l0 = 0.f, l1 = 0.f;

    const int u0 = tid * 2;
    const int ntiles = 2 * (qb + 1);

    auto prefetch = [&](int kb) {
        const unsigned dst = kvb + (unsigned)(kb % 3) * STAGE;
        const int kbase = kb * 64;
#pragma unroll
        for (int j = 0; j < 2; j++) {
            const int u = u0 + j, row = u >> 3, c = u & 7;
            const unsigned off = (unsigned)(row * SR + c * 8) * 2;
            cp16(dst + off, K + (size_t)(kbase + row) * CDIM + h * HD + c * 8);
            cp16(dst + TILE + off, V + (size_t)(kbase + row) * CDIM + h * HD + c * 8);
        }
        cp_commit();
    };

    prefetch(0);
    if (ntiles > 1) prefetch(1);

    for (int kb = 0; kb < ntiles; kb++) {
        if (kb + 1 < ntiles) cp_wait1(); else cp_wait0();
        __syncthreads();
        if (kb + 2 < ntiles) prefetch(kb + 2);

        const unsigned kbase_s = kvb + (unsigned)(kb % 3) * STAGE;

        float s[8][4] = {};
#pragma unroll
        for (int kk = 0; kk < 4; kk++) {
            const unsigned kb2 = kk * 32;
#pragma unroll
            for (int j = 0; j < 4; j++) {
                unsigned b0, b1, b2, b3;
                ldsm4(b0, b1, b2, b3, kbase_s + koff[j] + kb2);
                mma_f16(s[2 * j][0], s[2 * j][1], s[2 * j][2], s[2 * j][3],
                        qf[kk][0], qf[kk][1], qf[kk][2], qf[kk][3], b0, b1);
                mma_f16(s[2 * j + 1][0], s[2 * j + 1][1], s[2 * j + 1][2], s[2 * j + 1][3],
                        qf[kk][0], qf[kk][1], qf[kk][2], qf[kk][3], b2, b3);
            }
        }

        if (kb >= 2 * qb) {
            const int cb = kb * 64;
#pragma unroll
            for (int nt = 0; nt < 8; nt++) {
                const int c0 = cb + nt * 8 + 2 * t;
                if (c0 > r0)     s[nt][0] = -1e30f;
                if (c0 + 1 > r0) s[nt][1] = -1e30f;
                if (c0 > r1)     s[nt][2] = -1e30f;
                if (c0 + 1 > r1) s[nt][3] = -1e30f;
            }
        }

        float mx0 = -1e30f, mx1 = -1e30f;
#pragma unroll
        for (int nt = 0; nt < 8; nt++) {
            mx0 = fmaxf(mx0, fmaxf(s[nt][0], s[nt][1]));
            mx1 = fmaxf(mx1, fmaxf(s[nt][2], s[nt][3]));
        }
        mx0 = fmaxf(mx0, __shfl_xor_sync(0xffffffffu, mx0, 1));
        mx0 = fmaxf(mx0, __shfl_xor_sync(0xffffffffu, mx0, 2));
        mx1 = fmaxf(mx1, __shfl_xor_sync(0xffffffffu, mx1, 1));
        mx1 = fmaxf(mx1, __shfl_xor_sync(0xffffffffu, mx1, 2));

        const float nm0 = fmaxf(m0, mx0);
        const float nm1 = fmaxf(m1, mx1);
        const float cr0 = __expf(m0 - nm0);
        const float cr1 = __expf(m1 - nm1);
        m0 = nm0; m1 = nm1;

        float sm0 = 0.f, sm1 = 0.f;
#pragma unroll
        for (int nt = 0; nt < 8; nt++) {
            float p0 = __expf(s[nt][0] - nm0);
            float p1 = __expf(s[nt][1] - nm0);
            float p2 = __expf(s[nt][2] - nm1);
            float p3 = __expf(s[nt][3] - nm1);
            s[nt][0] = p0; s[nt][1] = p1; s[nt][2] = p2; s[nt][3] = p3;
            sm0 += p0 + p1;
            sm1 += p2 + p3;
        }
        sm0 += __shfl_xor_sync(0xffffffffu, sm0, 1);
        sm0 += __shfl_xor_sync(0xffffffffu, sm0, 2);
        sm1 += __shfl_xor_sync(0xffffffffu, sm1, 1);
        sm1 += __shfl_xor_sync(0xffffffffu, sm1, 2);
        l0 = l0 * cr0 + sm0;
        l1 = l1 * cr1 + sm1;

#pragma unroll
        for (int nt = 0; nt < 8; nt++) {
            o[nt][0] *= cr0; o[nt][1] *= cr0;
            o[nt][2] *= cr1; o[nt][3] *= cr1;
        }

#pragma unroll
        for (int kk = 0; kk < 4; kk++) {
            unsigned a0 = pack_h2(s[2 * kk][0], s[2 * kk][1]);
            unsigned a1 = pack_h2(s[2 * kk][2], s[2 * kk][3]);
            unsigned a2 = pack_h2(s[2 * kk + 1][0], s[2 * kk + 1][1]);
            unsigned a3 = pack_h2(s[2 * kk + 1][2], s[2 * kk + 1][3]);
            const unsigned kb2 = kk * 16 * SR * 2;
#pragma unroll
            for (int j = 0; j < 4; j++) {
                unsigned b0, b1, b2, b3;
                ldsm4t(b0, b1, b2, b3, kbase_s + voff[j] + kb2);
                mma_f16(o[2 * j][0], o[2 * j][1], o[2 * j][2], o[2 * j][3],
                        a0, a1, a2, a3, b0, b1);
                mma_f16(o[2 * j + 1][0], o[2 * j + 1][1], o[2 * j + 1][2], o[2 * j + 1][3],
                        a0, a1, a2, a3, b2, b3);
            }
        }
    }

    const float inv0 = 1.f / l0;
    const float inv1 = 1.f / l1;
    __half* o0p = O + (size_t)r0 * CDIM + h * HD;
    __half* o1p = O + (size_t)r1 * CDIM + h * HD;
#pragma unroll
    for (int nt = 0; nt < 8; nt++) {
        const int c = nt * 8 + 2 * t;
        *reinterpret_cast<unsigned*>(o0p + c) = pack_h2(o[nt][0] * inv0, o[nt][1] * inv0);
        *reinterpret_cast<unsigned*>(o1p + c) = pack_h2(o[nt][2] * inv1, o[nt][3] * inv1);
    }
}

// ---------------- fused residual add + LayerNorm ---------------------------
template <bool DUALOUT>
__global__ __launch_bounds__(256) void add_ln(
    const float* __restrict__ A, const float* __restrict__ Bb,
    const float* __restrict__ g, const float* __restrict__ be,
    float* __restrict__ out, __half* __restrict__ out_h)
{
    const int row = blockIdx.x;
    const int tid = threadIdx.x;
    const float* pa = A + (size_t)row * CDIM;
    const float* pb = Bb + (size_t)row * CDIM;

    float v[3];
    float s = 0.f, sq = 0.f;
#pragma unroll
    for (int i = 0; i < 3; i++) {
        int idx = tid + i * 256;
        v[i] = pa[idx] + pb[idx];
        s += v[i];
        sq += v[i] * v[i];
    }
#pragma unroll
    for (int off = 16; off; off >>= 1) {
        s += __shfl_xor_sync(0xffffffffu, s, off);
        sq += __shfl_xor_sync(0xffffffffu, sq, off);
    }
    __shared__ float ss[8], ssq[8];
    int w = tid >> 5, lane = tid & 31;
    if (lane == 0) { ss[w] = s; ssq[w] = sq; }
    __syncthreads();
    if (tid < 32) {
        s = (tid < 8) ? ss[tid] : 0.f;
        sq = (tid < 8) ? ssq[tid] : 0.f;
#pragma unroll
        for (int off = 4; off; off >>= 1) {
            s += __shfl_xor_sync(0xffffffffu, s, off);
            sq += __shfl_xor_sync(0xffffffffu, sq, off);
        }
        if (tid == 0) { ss[0] = s; ssq[0] = sq; }
    }
    __syncthreads();
    const float mean = ss[0] * (1.0f / CDIM);
    const float var = ssq[0] * (1.0f / CDIM) - mean * mean;
    const float inv = rsqrtf(var + 1e-5f);
#pragma unroll
    for (int i = 0; i < 3; i++) {
        int idx = tid + i * 256;
        float r = (v[i] - mean) * inv * g[idx] + be[idx];
        out[(size_t)row * CDIM + idx] = r;
        if (DUALOUT)
            out_h[(size_t)row * CDIM + idx] = __float2half_rn(r);
    }
}

// ---------------- launch ----------------------------------------------------
extern "C" void kernel_launch(void* const* d_in, const int* in_sizes, int n_in,
                              void* d_out, int out_size)
{
    const float* x     = (const float*)d_in[0];
    const float* Wq    = (const float*)d_in[1];
    const float* bq    = (const float*)d_in[2];
    const float* Wk    = (const float*)d_in[3];
    const float* bk    = (const float*)d_in[4];
    const float* Wv    = (const float*)d_in[5];
    const float* bv    = (const float*)d_in[6];
    const float* Wo    = (const float*)d_in[7];
    const float* bo    = (const float*)d_in[8];
    const float* ln1g  = (const float*)d_in[9];
    const float* ln1b  = (const float*)d_in[10];
    const float* W1    = (const float*)d_in[11];
    const float* b1    = (const float*)d_in[12];
    const float* W2    = (const float*)d_in[13];
    const float* b2    = (const float*)d_in[14];
    const float* ln2g  = (const float*)d_in[15];
    const float* ln2b  = (const float*)d_in[16];
    float* y = (float*)d_out;

    __half *q, *k, *v, *attn, *hh, *m1, *xh, *wq, *wk, *wv, *wo, *w1, *w2;
    float *proj, *h, *m2;
    cudaGetSymbolAddress((void**)&q,    g_q);
    cudaGetSymbolAddress((void**)&k,    g_k);
    cudaGetSymbolAddress((void**)&v,    g_v);
    cudaGetSymbolAddress((void**)&attn, g_attn);
    cudaGetSymbolAddress((void**)&proj, g_proj);
    cudaGetSymbolAddress((void**)&h,    g_h);
    cudaGetSymbolAddress((void**)&hh,   g_hh);
    cudaGetSymbolAddress((void**)&m1,   g_mlp1);
    cudaGetSymbolAddress((void**)&m2,   g_mlp2);
    cudaGetSymbolAddress((void**)&xh,   g_xh);
    cudaGetSymbolAddress((void**)&wq,   g_wq);
    cudaGetSymbolAddress((void**)&wk,   g_wk);
    cudaGetSymbolAddress((void**)&wv,   g_wv);
    cudaGetSymbolAddress((void**)&wo,   g_wo);
    cudaGetSymbolAddress((void**)&w1,   g_w1);
    cudaGetSymbolAddress((void**)&w2,   g_w2);

    const int SMEM_G  = 2 * (64 * 72 + 64 * 136) * 2;   // 53248
    const int SMEM_FA = 3 * 2 * 64 * 72 * 2;            // 55296
    cudaFuncSetAttribute(gemm_h_qkv, cudaFuncAttributeMaxDynamicSharedMemorySize, SMEM_G);
    cudaFuncSetAttribute(gemm_h<false, float>,  cudaFuncAttributeMaxDynamicSharedMemorySize, SMEM_G);
    cudaFuncSetAttribute(gemm_h<true, __half>,  cudaFuncAttributeMaxDynamicSharedMemorySize, SMEM_G);
    cudaFuncSetAttribute(flash_attn_h, cudaFuncAttributeMaxDynamicSharedMemorySize, SMEM_FA);

    // one fused convert launch: x + 6 weights -> half (natural layout)
    CvtArgs ca;
    ca.s[0] = { x,  xh, SEQ * CDIM };
    ca.s[1] = { Wq, wq, CDIM * CDIM };
    ca.s[2] = { Wk, wk, CDIM * CDIM };
    ca.s[3] = { Wv, wv, CDIM * CDIM };
    ca.s[4] = { Wo, wo, CDIM * CDIM };
    ca.s[5] = { W1, w1, CDIM * FDIM };
    ca.s[6] = { W2, w2, FDIM * CDIM };
    cvt_all_kernel<<<dim3(SEQ * CDIM / 1024, 7), 256>>>(ca);

    // fused QKV projection (BM=64)
    gemm_h_qkv<<<dim3(18, SEQ / 64), 256, SMEM_G>>>(xh, wq, wk, wv, bq, bk, bv, q, k, v);

    // causal attention (heavy-first global order)
    flash_attn_h<<<dim3(NH, SEQ / 128), 256, SMEM_FA>>>(q, k, v, attn);

    // output projection
    gemm_h<false, float><<<dim3(CDIM / 128, SEQ / 64), 256, SMEM_G>>>(attn, wo, bo, proj, CDIM, CDIM);

    // h = LN(x + proj), plus half copy for W1
    add_ln<true><<<SEQ, 256>>>(x, proj, ln1g, ln1b, h, hh);

    // MLP
    gemm_h<true, __half><<<dim3(FDIM / 128, SEQ / 64), 256, SMEM_G>>>(hh, w1, b1, m1, FDIM, CDIM);
    gemm_h<false, float><<<dim3(CDIM / 128, SEQ / 64), 256, SMEM_G>>>(m1, w2, b2, m2, CDIM, FDIM);

    // y = LN(h + mlp)
    add_ln<false><<<SEQ, 256>>>(h, m2, ln2g, ln2b, y, nullptr);

    (void)in_sizes; (void)n_in; (void)out_size;
}

// round 12
// speedup vs baseline: 8.7113x; 1.0285x over previous
#include <cuda_runtime.h>
#include <cuda_fp16.h>
#include <math.h>
#include <cstdint>
#include <stdint.h>

#define SEQ 4096
#define CDIM 768
#define NH 12
#define HD 64
#define FDIM 3072

// ---------------- scratch (device globals; no allocation allowed) ----------
__device__ __half g_q[SEQ * CDIM];
__device__ __half g_k[SEQ * CDIM];
__device__ __half g_v[SEQ * CDIM];
__device__ __half g_attn[SEQ * CDIM];
__device__ float  g_proj[SEQ * CDIM];
__device__ float  g_h[SEQ * CDIM];
__device__ __half g_hh[SEQ * CDIM];
__device__ __half g_mlp1[SEQ * FDIM];
__device__ float  g_mlp2[SEQ * CDIM];
__device__ __half g_xh[SEQ * CDIM];
__device__ __half g_wq[CDIM * CDIM];     // [K,N] half (natural layout)
__device__ __half g_wk[CDIM * CDIM];
__device__ __half g_wv[CDIM * CDIM];
__device__ __half g_wo[CDIM * CDIM];
__device__ __half g_w1[CDIM * FDIM];
__device__ __half g_w2[FDIM * CDIM];

__device__ __forceinline__ void cp16(unsigned int dst, const void* src) {
    asm volatile("cp.async.cg.shared.global [%0], [%1], 16;" :: "r"(dst), "l"(src));
}
__device__ __forceinline__ void cp_commit() { asm volatile("cp.async.commit_group;"); }
__device__ __forceinline__ void cp_wait0() { asm volatile("cp.async.wait_group 0;"); }
__device__ __forceinline__ void cp_wait1() { asm volatile("cp.async.wait_group 1;"); }

__device__ __forceinline__ unsigned smem_u32(const void* p) {
    unsigned a;
    asm("{ .reg .u64 t; cvta.to.shared.u64 t, %1; cvt.u32.u64 %0, t; }" : "=r"(a) : "l"(p));
    return a;
}

__device__ __forceinline__ void mma_f16(
    float& d0, float& d1, float& d2, float& d3,
    unsigned a0, unsigned a1, unsigned a2, unsigned a3,
    unsigned b0, unsigned b1)
{
    asm volatile(
        "mma.sync.aligned.m16n8k16.row.col.f32.f16.f16.f32 "
        "{%0,%1,%2,%3},{%4,%5,%6,%7},{%8,%9},{%0,%1,%2,%3};"
        : "+f"(d0), "+f"(d1), "+f"(d2), "+f"(d3)
        : "r"(a0), "r"(a1), "r"(a2), "r"(a3), "r"(b0), "r"(b1));
}

__device__ __forceinline__ void ldsm4(
    unsigned& r0, unsigned& r1, unsigned& r2, unsigned& r3, unsigned addr)
{
    asm volatile("ldmatrix.sync.aligned.m8n8.x4.shared.b16 {%0,%1,%2,%3}, [%4];"
                 : "=r"(r0), "=r"(r1), "=r"(r2), "=r"(r3) : "r"(addr));
}

__device__ __forceinline__ void ldsm4t(
    unsigned& r0, unsigned& r1, unsigned& r2, unsigned& r3, unsigned addr)
{
    asm volatile("ldmatrix.sync.aligned.m8n8.x4.trans.shared.b16 {%0,%1,%2,%3}, [%4];"
                 : "=r"(r0), "=r"(r1), "=r"(r2), "=r"(r3) : "r"(addr));
}

__device__ __forceinline__ unsigned pack_h2(float lo, float hi) {
    __half2 h = __floats2half2_rn(lo, hi);
    return *reinterpret_cast<unsigned*>(&h);
}

// ---------------- fused float -> half converts (7 segments, 16 f/thread) ----
struct CvtSeg { const float* src; __half* dst; int n; };
struct CvtArgs { CvtSeg s[7]; };

__global__ __launch_bounds__(256) void cvt_all_kernel(CvtArgs a)
{
    const CvtSeg seg = a.s[blockIdx.y];
    const int base = (blockIdx.x * 256 + threadIdx.x) * 16;
#pragma unroll
    for (int j = 0; j < 4; j++) {
        const int i = base + j * 4;
        if (i < seg.n) {
            float4 v = *reinterpret_cast<const float4*>(seg.src + i);
            uint2 u;
            u.x = pack_h2(v.x, v.y);
            u.y = pack_h2(v.z, v.w);
            *reinterpret_cast<uint2*>(seg.dst + i) = u;
        }
    }
}

// ---------------- FP16 tensor-core GEMM -------------------------------------
// C[M,N] = A[M,K] @ B[K,N] + bias.  BM=64 x BN=128 tile, BK=64, 2-stage
// cp.async, 256 thr = 8 warps (2M x 4N, warp tile 32x32), 3 CTAs/SM.
template <bool GELU, typename OutT>
__device__ __forceinline__ void gemm_h_body(
    const __half* __restrict__ A, const __half* __restrict__ B,
    const float* __restrict__ bias, OutT* __restrict__ C,
    int N, int K, int bx, int by)
{
    constexpr int BM = 64, BK = 64, SRA = 72, SRB = 136;
    constexpr unsigned ABYTES = BM * SRA * 2;      // 9216
    constexpr unsigned BBYTES = BK * SRB * 2;      // 17408
    constexpr unsigned STAGE = ABYTES + BBYTES;    // 26624

    extern __shared__ __half smh[];
    const unsigned smb = smem_u32(smh);

    const int tid = threadIdx.x, lane = tid & 31, warp = tid >> 5;
    const int wm = warp & 1, wn = warp >> 1, g = lane >> 2, t = lane & 3;

    // A frag offsets (non-trans ldmatrix, two 16-row m-tiles per warp)
    const int lr = lane & 15;
    const int lc = (lane >> 4) << 3;
    unsigned aoff[2];
#pragma unroll
    for (int mt = 0; mt < 2; mt++)
        aoff[mt] = ((wm * 32 + mt * 16 + lr) * SRA + lc) * 2;

    // B frag offsets (trans ldmatrix on [k][n] tile; two 16-col groups)
    const int vr = lane & 15;
    const int vc = (lane >> 4) << 3;
    unsigned boff[2];
#pragma unroll
    for (int j = 0; j < 2; j++)
        boff[j] = ABYTES + (vr * SRB + wn * 32 + j * 16 + vc) * 2;

    // loaders: A 64 rows x 8 units (2/thread); B 64 rows x 16 units (4/thread)
    const int u0a = tid * 2;
    const int u0b = tid * 4;
    const __half* Abase = A + (size_t)(by * BM) * K;
    const __half* Bbase = B + (size_t)bx * 128;

    const int nchunks = K / BK;

    auto prefetch = [&](int ch) {
        const unsigned dst = smb + (unsigned)(ch & 1) * STAGE;
        const int k0 = ch * BK;
#pragma unroll
        for (int j = 0; j < 2; j++) {
            const int u = u0a + j, row = u >> 3, c16 = u & 7;
            cp16(dst + (unsigned)(row * SRA + c16 * 8) * 2,
                 Abase + (size_t)row * K + k0 + c16 * 8);
        }
#pragma unroll
        for (int j = 0; j < 4; j++) {
            const int u = u0b + j, row = u >> 4, c16 = u & 15;
            cp16(dst + ABYTES + (unsigned)(row * SRB + c16 * 8) * 2,
                 Bbase + (size_t)(k0 + row) * N + c16 * 8);
        }
        cp_commit();
    };

    float acc[2][4][4] = {};

    prefetch(0);

    for (int ch = 0; ch < nchunks; ch++) {
        cp_wait0();
        __syncthreads();
        if (ch + 1 < nchunks) prefetch(ch + 1);

        const unsigned sbase = smb + (unsigned)(ch & 1) * STAGE;
#pragma unroll
        for (int kk = 0; kk < 4; kk++) {
            unsigned af[2][4], bf[4][2];
#pragma unroll
            for (int mt = 0; mt < 2; mt++)
                ldsm4(af[mt][0], af[mt][1], af[mt][2], af[mt][3],
                      sbase + aoff[mt] + kk * 32);
            const unsigned kadv = (unsigned)(kk * 16 * SRB * 2);
#pragma unroll
            for (int j = 0; j < 2; j++)
                ldsm4t(bf[2 * j][0], bf[2 * j][1], bf[2 * j + 1][0], bf[2 * j + 1][1],
                       sbase + boff[j] + kadv);
#pragma unroll
            for (int mt = 0; mt < 2; mt++)
#pragma unroll
                for (int nt = 0; nt < 4; nt++)
                    mma_f16(acc[mt][nt][0], acc[mt][nt][1], acc[mt][nt][2], acc[mt][nt][3],
                            af[mt][0], af[mt][1], af[mt][2], af[mt][3],
                            bf[nt][0], bf[nt][1]);
        }
        __syncthreads();
    }

#pragma unroll
    for (int mt = 0; mt < 2; mt++) {
        const int r0 = by * BM + wm * 32 + mt * 16 + g;
#pragma unroll
        for (int nt = 0; nt < 4; nt++) {
            const int c0 = bx * 128 + wn * 32 + nt * 8 + t * 2;
            const float bz0 = bias[c0], bz1 = bias[c0 + 1];
            float v0 = acc[mt][nt][0] + bz0;
            float v1 = acc[mt][nt][1] + bz1;
            float v2 = acc[mt][nt][2] + bz0;
            float v3 = acc[mt][nt][3] + bz1;
            if (GELU) {
                v0 = 0.5f * v0 * (1.0f + erff(v0 * 0.70710678118654752f));
                v1 = 0.5f * v1 * (1.0f + erff(v1 * 0.70710678118654752f));
                v2 = 0.5f * v2 * (1.0f + erff(v2 * 0.70710678118654752f));
                v3 = 0.5f * v3 * (1.0f + erff(v3 * 0.70710678118654752f));
            }
            if (sizeof(OutT) == 2) {
                __half* Ch = reinterpret_cast<__half*>(C);
                *reinterpret_cast<unsigned*>(Ch + (size_t)r0 * N + c0) = pack_h2(v0, v1);
                *reinterpret_cast<unsigned*>(Ch + (size_t)(r0 + 8) * N + c0) = pack_h2(v2, v3);
            } else {
                float* Cf = reinterpret_cast<float*>(C);
                *reinterpret_cast<float2*>(Cf + (size_t)r0 * N + c0) = make_float2(v0, v1);
                *reinterpret_cast<float2*>(Cf + (size_t)(r0 + 8) * N + c0) = make_float2(v2, v3);
            }
        }
    }
}

template <bool GELU, typename OutT>
__global__ __launch_bounds__(256, 3) void gemm_h(
    const __half* __restrict__ A, const __half* __restrict__ B,
    const float* __restrict__ bias, OutT* __restrict__ C, int N, int K)
{
    gemm_h_body<GELU, OutT>(A, B, bias, C, N, K, blockIdx.x, blockIdx.y);
}

__global__ __launch_bounds__(256, 3) void gemm_h_qkv(
    const __half* __restrict__ X,
    const __half* __restrict__ Wqh, const __half* __restrict__ Wkh, const __half* __restrict__ Wvh,
    const float* __restrict__ bq, const float* __restrict__ bk, const float* __restrict__ bv,
    __half* __restrict__ q, __half* __restrict__ k, __half* __restrict__ v)
{
    const int which = blockIdx.x / 6;
    const int bx = blockIdx.x % 6;
    const __half* B   = (which == 0) ? Wqh : (which == 1) ? Wkh : Wvh;
    const float* bias = (which == 0) ? bq  : (which == 1) ? bk  : bv;
    __half* C         = (which == 0) ? q   : (which == 1) ? k   : v;
    gemm_h_body<false, __half>(X, B, bias, C, CDIM, CDIM, bx, blockIdx.y);
}

// ---------------- FP16 flash attention (3-stage cp.async + ldmatrix) --------
__global__ __launch_bounds__(256, 2) void flash_attn_h(
    const __half* __restrict__ Q, const __half* __restrict__ K,
    const __half* __restrict__ V, __half* __restrict__ O)
{
    constexpr int SR = 72;
    constexpr unsigned TILE = 64 * SR * 2;
    constexpr unsigned STAGE = 2 * TILE;

    extern __shared__ __half smh[];
    const unsigned kvb = smem_u32(smh);

    const int h  = blockIdx.x;
    const int qb = (gridDim.y - 1) - blockIdx.y;   // heavy blocks first
    const int tid  = threadIdx.x;
    const int lane = tid & 31;
    const int w = tid >> 5;
    const int g = lane >> 2;
    const int t = lane & 3;

    const int r0 = qb * 128 + w * 16 + g;
    const int r1 = r0 + 8;

    unsigned qf[4][4];
    {
        const __half2 sc = __float2half2_rn(0.125f);
        const __half* q0p = Q + (size_t)r0 * CDIM + h * HD;
        const __half* q1p = Q + (size_t)r1 * CDIM + h * HD;
#pragma unroll
        for (int kk = 0; kk < 4; kk++) {
            __half2 x0 = __hmul2(*reinterpret_cast<const __half2*>(q0p + kk * 16 + 2 * t), sc);
            __half2 x1 = __hmul2(*reinterpret_cast<const __half2*>(q1p + kk * 16 + 2 * t), sc);
            __half2 x2 = __hmul2(*reinterpret_cast<const __half2*>(q0p + kk * 16 + 2 * t + 8), sc);
            __half2 x3 = __hmul2(*reinterpret_cast<const __half2*>(q1p + kk * 16 + 2 * t + 8), sc);
            qf[kk][0] = *reinterpret_cast<unsigned*>(&x0);
            qf[kk][1] = *reinterpret_cast<unsigned*>(&x1);
            qf[kk][2] = *reinterpret_cast<unsigned*>(&x2);
            qf[kk][3] = *reinterpret_cast<unsigned*>(&x3);
        }
    }

    const int rb = (lane & 7) | ((lane & 16) >> 1);
    const int cbh = lane & 8;
    unsigned koff[4];
#pragma unroll
    for (int j = 0; j < 4; j++)
        koff[j] = ((j * 16 + rb) * SR + cbh) * 2;
    const int vr = lane & 15;
    const int vc = (lane >> 4) << 3;
    unsigned voff[4];
#pragma unroll
    for (int j = 0; j < 4; j++)
        voff[j] = TILE + (vr * SR + j * 16 + vc) * 2;

    float o[8][4] = {};
    float m0 = -1e30f, m1 = -1e30f, l0 = 0.f, l1 = 0.f;

    const int u0 = tid * 2;
    const int ntiles = 2 * (qb + 1);

    auto prefetch = [&](int kb) {
        const unsigned dst = kvb + (unsigned)(kb % 3) * STAGE;
        const int kbase = kb * 64;
#pragma unroll
        for (int j = 0; j < 2; j++) {
            const int u = u0 + j, row = u >> 3, c = u & 7;
            const unsigned off = (unsigned)(row * SR + c * 8) * 2;
            cp16(dst + off, K + (size_t)(kbase + row) * CDIM + h * HD + c * 8);
            cp16(dst + TILE + off, V + (size_t)(kbase + row) * CDIM + h * HD + c * 8);
        }
        cp_commit();
    };

    prefetch(0);
    if (ntiles > 1) prefetch(1);

    for (int kb = 0; kb < ntiles; kb++) {
        if (kb + 1 < ntiles) cp_wait1(); else cp_wait0();
        __syncthreads();
        if (kb + 2 < ntiles) prefetch(kb + 2);

        const unsigned kbase_s = kvb + (unsigned)(kb % 3) * STAGE;

        float s[8][4] = {};
#pragma unroll
        for (int kk = 0; kk < 4; kk++) {
            const unsigned kb2 = kk * 32;
#pragma unroll
            for (int j = 0; j < 4; j++) {
                unsigned b0, b1, b2, b3;
                ldsm4(b0, b1, b2, b3, kbase_s + koff[j] + kb2);
                mma_f16(s[2 * j][0], s[2 * j][1], s[2 * j][2], s[2 * j][3],
                        qf[kk][0], qf[kk][1], qf[kk][2], qf[kk][3], b0, b1);
                mma_f16(s[2 * j + 1][0], s[2 * j + 1][1], s[2 * j + 1][2], s[2 * j + 1][3],
                        qf[kk][0], qf[kk][1], qf[kk][2], qf[kk][3], b2, b3);
            }
        }

        if (kb >= 2 * qb) {
            const int cb = kb * 64;
#pragma unroll
            for (int nt = 0; nt < 8; nt++) {
                const int c0 = cb + nt * 8 + 2 * t;
                if (c0 > r0)     s[nt][0] = -1e30f;
                if (c0 + 1 > r0) s[nt][1] = -1e30f;
                if (c0 > r1)     s[nt][2] = -1e30f;
                if (c0 + 1 > r1) s[nt][3] = -1e30f;
            }
        }

        float mx0 = -1e30f, mx1 = -1e30f;
#pragma unroll
        for (int nt = 0; nt < 8; nt++) {
            mx0 = fmaxf(mx0, fmaxf(s[nt][0], s[nt][1]));
            mx1 = fmaxf(mx1, fmaxf(s[nt][2], s[nt][3]));
        }
        mx0 = fmaxf(mx0, __shfl_xor_sync(0xffffffffu, mx0, 1));
        mx0 = fmaxf(mx0, __shfl_xor_sync(0xffffffffu, mx0, 2));
        mx1 = fmaxf(mx1, __shfl_xor_sync(0xffffffffu, mx1, 1));
        mx1 = fmaxf(mx1, __shfl_xor_sync(0xffffffffu, mx1, 2));

        const float nm0 = fmaxf(m0, mx0);
        const float nm1 = fmaxf(m1, mx1);
        const float cr0 = __expf(m0 - nm0);
        const float cr1 = __expf(m1 - nm1);
        m0 = nm0; m1 = nm1;

        float sm0 = 0.f, sm1 = 0.f;
#pragma unroll
        for (int nt = 0; nt < 8; nt++) {
            float p0 = __expf(s[nt][0] - nm0);
            float p1 = __expf(s[nt][1] - nm0);
            float p2 = __expf(s[nt][2] - nm1);
            float p3 = __expf(s[nt][3] - nm1);
            s[nt][0] = p0; s[nt][1] = p1; s[nt][2] = p2; s[nt][3] = p3;
            sm0 += p0 + p1;
            sm1 += p2 + p3;
        }
        sm0 += __shfl_xor_sync(0xffffffffu, sm0, 1);
        sm0 += __shfl_xor_sync(0xffffffffu, sm0, 2);
        sm1 += __shfl_xor_sync(0xffffffffu, sm1, 1);
        sm1 += __shfl_xor_sync(0xffffffffu, sm1, 2);
        l0 = l0 * cr0 + sm0;
        l1 = l1 * cr1 + sm1;

#pragma unroll
        for (int nt = 0; nt < 8; nt++) {
            o[nt][0] *= cr0; o[nt][1] *= cr0;
            o[nt][2] *= cr1; o[nt][3] *= cr1;
        }

#pragma unroll
        for (int kk = 0; kk < 4; kk++) {
            unsigned a0 = pack_h2(s[2 * kk][0], s[2 * kk][1]);
            unsigned a1 = pack_h2(s[2 * kk][2], s[2 * kk][3]);
            unsigned a2 = pack_h2(s[2 * kk + 1][0], s[2 * kk + 1][1]);
            unsigned a3 = pack_h2(s[2 * kk + 1][2], s[2 * kk + 1][3]);
            const unsigned kb2 = kk * 16 * SR * 2;
#pragma unroll
            for (int j = 0; j < 4; j++) {
                unsigned b0, b1, b2, b3;
                ldsm4t(b0, b1, b2, b3, kbase_s + voff[j] + kb2);
                mma_f16(o[2 * j][0], o[2 * j][1], o[2 * j][2], o[2 * j][3],
                        a0, a1, a2, a3, b0, b1);
                mma_f16(o[2 * j + 1][0], o[2 * j + 1][1], o[2 * j + 1][2], o[2 * j + 1][3],
                        a0, a1, a2, a3, b2, b3);
            }
        }
    }

    const float inv0 = 1.f / l0;
    const float inv1 = 1.f / l1;
    __half* o0p = O + (size_t)r0 * CDIM + h * HD;
    __half* o1p = O + (size_t)r1 * CDIM + h * HD;
#pragma unroll
    for (int nt = 0; nt < 8; nt++) {
        const int c = nt * 8 + 2 * t;
        *reinterpret_cast<unsigned*>(o0p + c) = pack_h2(o[nt][0] * inv0, o[nt][1] * inv0);
        *reinterpret_cast<unsigned*>(o1p + c) = pack_h2(o[nt][2] * inv1, o[nt][3] * inv1);
    }
}

// ---------------- fused residual add + LayerNorm ---------------------------
template <bool DUALOUT>
__global__ __launch_bounds__(256) void add_ln(
    const float* __restrict__ A, const float* __restrict__ Bb,
    const float* __restrict__ g, const float* __restrict__ be,
    float* __restrict__ out, __half* __restrict__ out_h)
{
    const int row = blockIdx.x;
    const int tid = threadIdx.x;
    const float* pa = A + (size_t)row * CDIM;
    const float* pb = Bb + (size_t)row * CDIM;

    float v[3];
    float s = 0.f, sq = 0.f;
#pragma unroll
    for (int i = 0; i < 3; i++) {
        int idx = tid + i * 256;
        v[i] = pa[idx] + pb[idx];
        s += v[i];
        sq += v[i] * v[i];
    }
#pragma unroll
    for (int off = 16; off; off >>= 1) {
        s += __shfl_xor_sync(0xffffffffu, s, off);
        sq += __shfl_xor_sync(0xffffffffu, sq, off);
    }
    __shared__ float ss[8], ssq[8];
    int w = tid >> 5, lane = tid & 31;
    if (lane == 0) { ss[w] = s; ssq[w] = sq; }
    __syncthreads();
    if (tid < 32) {
        s = (tid < 8) ? ss[tid] : 0.f;
        sq = (tid < 8) ? ssq[tid] : 0.f;
#pragma unroll
        for (int off = 4; off; off >>= 1) {
            s += __shfl_xor_sync(0xffffffffu, s, off);
            sq += __shfl_xor_sync(0xffffffffu, sq, off);
        }
        if (tid == 0) { ss[0] = s; ssq[0] = sq; }
    }
    __syncthreads();
    const float mean = ss[0] * (1.0f / CDIM);
    const float var = ssq[0] * (1.0f / CDIM) - mean * mean;
    const float inv = rsqrtf(var + 1e-5f);
#pragma unroll
    for (int i = 0; i < 3; i++) {
        int idx = tid + i * 256;
        float r = (v[i] - mean) * inv * g[idx] + be[idx];
        out[(size_t)row * CDIM + idx] = r;
        if (DUALOUT)
            out_h[(size_t)row * CDIM + idx] = __float2half_rn(r);
    }
}

// ---------------- launch ----------------------------------------------------
extern "C" void kernel_launch(void* const* d_in, const int* in_sizes, int n_in,
                              void* d_out, int out_size)
{
    const float* x     = (const float*)d_in[0];
    const float* Wq    = (const float*)d_in[1];
    const float* bq    = (const float*)d_in[2];
    const float* Wk    = (const float*)d_in[3];
    const float* bk    = (const float*)d_in[4];
    const float* Wv    = (const float*)d_in[5];
    const float* bv    = (const float*)d_in[6];
    const float* Wo    = (const float*)d_in[7];
    const float* bo    = (const float*)d_in[8];
    const float* ln1g  = (const float*)d_in[9];
    const float* ln1b  = (const float*)d_in[10];
    const float* W1    = (const float*)d_in[11];
    const float* b1    = (const float*)d_in[12];
    const float* W2    = (const float*)d_in[13];
    const float* b2    = (const float*)d_in[14];
    const float* ln2g  = (const float*)d_in[15];
    const float* ln2b  = (const float*)d_in[16];
    float* y = (float*)d_out;

    __half *q, *k, *v, *attn, *hh, *m1, *xh, *wq, *wk, *wv, *wo, *w1, *w2;
    float *proj, *h, *m2;
    cudaGetSymbolAddress((void**)&q,    g_q);
    cudaGetSymbolAddress((void**)&k,    g_k);
    cudaGetSymbolAddress((void**)&v,    g_v);
    cudaGetSymbolAddress((void**)&attn, g_attn);
    cudaGetSymbolAddress((void**)&proj, g_proj);
    cudaGetSymbolAddress((void**)&h,    g_h);
    cudaGetSymbolAddress((void**)&hh,   g_hh);
    cudaGetSymbolAddress((void**)&m1,   g_mlp1);
    cudaGetSymbolAddress((void**)&m2,   g_mlp2);
    cudaGetSymbolAddress((void**)&xh,   g_xh);
    cudaGetSymbolAddress((void**)&wq,   g_wq);
    cudaGetSymbolAddress((void**)&wk,   g_wk);
    cudaGetSymbolAddress((void**)&wv,   g_wv);
    cudaGetSymbolAddress((void**)&wo,   g_wo);
    cudaGetSymbolAddress((void**)&w1,   g_w1);
    cudaGetSymbolAddress((void**)&w2,   g_w2);

    const int SMEM_G  = 2 * (64 * 72 + 64 * 136) * 2;   // 53248
    const int SMEM_FA = 3 * 2 * 64 * 72 * 2;            // 55296
    cudaFuncSetAttribute(gemm_h_qkv, cudaFuncAttributeMaxDynamicSharedMemorySize, SMEM_G);
    cudaFuncSetAttribute(gemm_h<false, float>,  cudaFuncAttributeMaxDynamicSharedMemorySize, SMEM_G);
    cudaFuncSetAttribute(gemm_h<true, __half>,  cudaFuncAttributeMaxDynamicSharedMemorySize, SMEM_G);
    cudaFuncSetAttribute(flash_attn_h, cudaFuncAttributeMaxDynamicSharedMemorySize, SMEM_FA);

    // one fused convert launch: x + 6 weights -> half (16 floats/thread)
    CvtArgs ca;
    ca.s[0] = { x,  xh, SEQ * CDIM };
    ca.s[1] = { Wq, wq, CDIM * CDIM };
    ca.s[2] = { Wk, wk, CDIM * CDIM };
    ca.s[3] = { Wv, wv, CDIM * CDIM };
    ca.s[4] = { Wo, wo, CDIM * CDIM };
    ca.s[5] = { W1, w1, CDIM * FDIM };
    ca.s[6] = { W2, w2, FDIM * CDIM };
    cvt_all_kernel<<<dim3(SEQ * CDIM / 4096, 7), 256>>>(ca);

    // fused QKV projection (BM=64)
    gemm_h_qkv<<<dim3(18, SEQ / 64), 256, SMEM_G>>>(xh, wq, wk, wv, bq, bk, bv, q, k, v);

    // causal attention (heavy-first global order)
    flash_attn_h<<<dim3(NH, SEQ / 128), 256, SMEM_FA>>>(q, k, v, attn);

    // output projection
    gemm_h<false, float><<<dim3(CDIM / 128, SEQ / 64), 256, SMEM_G>>>(attn, wo, bo, proj, CDIM, CDIM);

    // h = LN(x + proj), plus half copy for W1
    add_ln<true><<<SEQ, 256>>>(x, proj, ln1g, ln1b, h, hh);

    // MLP
    gemm_h<true, __half><<<dim3(FDIM / 128, SEQ / 64), 256, SMEM_G>>>(hh, w1, b1, m1, FDIM, CDIM);
    gemm_h<false, float><<<dim3(CDIM / 128, SEQ / 64), 256, SMEM_G>>>(m1, w2, b2, m2, CDIM, FDIM);

    // y = LN(h + mlp)
    add_ln<false><<<SEQ, 256>>>(h, m2, ln2g, ln2b, y, nullptr);

    (void)in_sizes; (void)n_in; (void)out_size;
}

// round 13
// speedup vs baseline: 9.8809x; 1.1343x over previous
#include <cuda_runtime.h>
#include <cuda_fp16.h>
#include <math.h>
#include <cstdint>
#include <stdint.h>

#define SEQ 4096
#define CDIM 768
#define NH 12
#define HD 64
#define FDIM 3072

// ---------------- scratch (device globals; no allocation allowed) ----------
__device__ __half g_q[SEQ * CDIM];
__device__ __half g_k[SEQ * CDIM];
__device__ __half g_v[SEQ * CDIM];
__device__ __half g_attn[SEQ * CDIM];
__device__ float  g_proj[SEQ * CDIM];
__device__ float  g_h[SEQ * CDIM];
__device__ __half g_hh[SEQ * CDIM];
__device__ __half g_mlp1[SEQ * FDIM];
__device__ float  g_mlp2[SEQ * CDIM];
__device__ __half g_xh[SEQ * CDIM];
__device__ __half g_wq[CDIM * CDIM];     // [K,N] half (natural layout)
__device__ __half g_wk[CDIM * CDIM];
__device__ __half g_wv[CDIM * CDIM];
__device__ __half g_wo[CDIM * CDIM];
__device__ __half g_w1[CDIM * FDIM];
__device__ __half g_w2[FDIM * CDIM];

__device__ __forceinline__ void cp16(unsigned int dst, const void* src) {
    asm volatile("cp.async.cg.shared.global [%0], [%1], 16;" :: "r"(dst), "l"(src));
}
__device__ __forceinline__ void cp_commit() { asm volatile("cp.async.commit_group;"); }
__device__ __forceinline__ void cp_wait0() { asm volatile("cp.async.wait_group 0;"); }
__device__ __forceinline__ void cp_wait1() { asm volatile("cp.async.wait_group 1;"); }

__device__ __forceinline__ unsigned smem_u32(const void* p) {
    unsigned a;
    asm("{ .reg .u64 t; cvta.to.shared.u64 t, %1; cvt.u32.u64 %0, t; }" : "=r"(a) : "l"(p));
    return a;
}

__device__ __forceinline__ void mma_f16(
    float& d0, float& d1, float& d2, float& d3,
    unsigned a0, unsigned a1, unsigned a2, unsigned a3,
    unsigned b0, unsigned b1)
{
    asm volatile(
        "mma.sync.aligned.m16n8k16.row.col.f32.f16.f16.f32 "
        "{%0,%1,%2,%3},{%4,%5,%6,%7},{%8,%9},{%0,%1,%2,%3};"
        : "+f"(d0), "+f"(d1), "+f"(d2), "+f"(d3)
        : "r"(a0), "r"(a1), "r"(a2), "r"(a3), "r"(b0), "r"(b1));
}

__device__ __forceinline__ void ldsm4(
    unsigned& r0, unsigned& r1, unsigned& r2, unsigned& r3, unsigned addr)
{
    asm volatile("ldmatrix.sync.aligned.m8n8.x4.shared.b16 {%0,%1,%2,%3}, [%4];"
                 : "=r"(r0), "=r"(r1), "=r"(r2), "=r"(r3) : "r"(addr));
}

__device__ __forceinline__ void ldsm4t(
    unsigned& r0, unsigned& r1, unsigned& r2, unsigned& r3, unsigned addr)
{
    asm volatile("ldmatrix.sync.aligned.m8n8.x4.trans.shared.b16 {%0,%1,%2,%3}, [%4];"
                 : "=r"(r0), "=r"(r1), "=r"(r2), "=r"(r3) : "r"(addr));
}

__device__ __forceinline__ unsigned pack_h2(float lo, float hi) {
    __half2 h = __floats2half2_rn(lo, hi);
    return *reinterpret_cast<unsigned*>(&h);
}

// ---------------- fused float -> half converts (7 segments, 16 f/thread) ----
struct CvtSeg { const float* src; __half* dst; int n; };
struct CvtArgs { CvtSeg s[7]; };

__global__ __launch_bounds__(256) void cvt_all_kernel(CvtArgs a)
{
    const CvtSeg seg = a.s[blockIdx.y];
    const int base = (blockIdx.x * 256 + threadIdx.x) * 16;
#pragma unroll
    for (int j = 0; j < 4; j++) {
        const int i = base + j * 4;
        if (i < seg.n) {
            float4 v = *reinterpret_cast<const float4*>(seg.src + i);
            uint2 u;
            u.x = pack_h2(v.x, v.y);
            u.y = pack_h2(v.z, v.w);
            *reinterpret_cast<uint2*>(seg.dst + i) = u;
        }
    }
}

// ---------------- FP16 tensor-core GEMM (swizzled smem, 3-stage) ------------
// C[M,N] = A[M,K] @ B[K,N] + bias.  BM=64 x BN=128 tile, BK=64, 3-stage
// cp.async, XOR-swizzled smem (no padding), 256 thr = 8 warps (2Mx4N),
// 3 CTAs/SM, one barrier per chunk.
template <bool GELU, typename OutT>
__device__ __forceinline__ void gemm_h_body(
    const __half* __restrict__ A, const __half* __restrict__ B,
    const float* __restrict__ bias, OutT* __restrict__ C,
    int N, int K, int bx, int by)
{
    constexpr int BM = 64, BK = 64;
    constexpr unsigned ABYTES = 64 * 128;        // 8192  (64 rows x 128B)
    constexpr unsigned BBYTES = 64 * 256;        // 16384 (64 rows x 256B)
    constexpr unsigned STAGE = ABYTES + BBYTES;  // 24576

    extern __shared__ __half smh[];
    const unsigned smb = smem_u32(smh);

    const int tid = threadIdx.x, lane = tid & 31, warp = tid >> 5;
    const int wm = warp & 1, wn = warp >> 1, g = lane >> 2, t = lane & 3;

    // ldmatrix lane geometry
    const int lr = lane & 15;          // row-in-16 (A) / k-row-in-16 (B)
    const int hi = lane >> 4;          // 0/1
    const int rx = lr & 7;             // swizzle xor value

    // A: row byte bases for the two 16-row m-tiles
    unsigned arow[2];
#pragma unroll
    for (int mt = 0; mt < 2; mt++)
        arow[mt] = (unsigned)((wm * 32 + mt * 16 + lr) * 128);

    // B: per-j (two 16-col groups) swizzled base offsets
    unsigned boff[2];
#pragma unroll
    for (int j = 0; j < 2; j++) {
        const int nunit = wn * 4 + j * 2 + hi;           // 16B n-unit 0..15
        boff[j] = ABYTES + (unsigned)(lr * 256) + ((unsigned)(nunit ^ rx) << 4);
    }

    // loaders
    const int u0a = tid * 2;           // A: 512 units, 2/thread
    const int u0b = tid * 4;           // B: 1024 units, 4/thread
    const __half* Abase = A + (size_t)(by * BM) * K;
    const __half* Bbase = B + (size_t)bx * 128;

    const int nchunks = K / BK;

    auto prefetch = [&](int ch) {
        const unsigned dst = smb + (unsigned)(ch % 3) * STAGE;
        const int k0 = ch * BK;
#pragma unroll
        for (int j = 0; j < 2; j++) {
            const int u = u0a + j, row = u >> 3, c16 = u & 7;
            cp16(dst + (unsigned)(row * 128) + ((unsigned)(c16 ^ (row & 7)) << 4),
                 Abase + (size_t)row * K + k0 + c16 * 8);
        }
#pragma unroll
        for (int j = 0; j < 4; j++) {
            const int u = u0b + j, row = u >> 4, c16 = u & 15;
            cp16(dst + ABYTES + (unsigned)(row * 256) + ((unsigned)(c16 ^ (row & 7)) << 4),
                 Bbase + (size_t)(k0 + row) * N + c16 * 8);
        }
        cp_commit();
    };

    float acc[2][4][4] = {};

    prefetch(0);
    prefetch(1);

    for (int ch = 0; ch < nchunks; ch++) {
        if (ch + 1 < nchunks) cp_wait1(); else cp_wait0();
        __syncthreads();
        if (ch + 2 < nchunks) prefetch(ch + 2);

        const unsigned sbase = smb + (unsigned)(ch % 3) * STAGE;
#pragma unroll
        for (int kk = 0; kk < 4; kk++) {
            unsigned af[2][4], bf[4][2];
            const unsigned aku = (unsigned)((kk * 2 + hi) ^ rx) << 4;
#pragma unroll
            for (int mt = 0; mt < 2; mt++)
                ldsm4(af[mt][0], af[mt][1], af[mt][2], af[mt][3],
                      sbase + arow[mt] + aku);
            const unsigned kadv = (unsigned)(kk * 16 * 256);
#pragma unroll
            for (int j = 0; j < 2; j++)
                ldsm4t(bf[2 * j][0], bf[2 * j][1], bf[2 * j + 1][0], bf[2 * j + 1][1],
                       sbase + boff[j] + kadv);
#pragma unroll
            for (int mt = 0; mt < 2; mt++)
#pragma unroll
                for (int nt = 0; nt < 4; nt++)
                    mma_f16(acc[mt][nt][0], acc[mt][nt][1], acc[mt][nt][2], acc[mt][nt][3],
                            af[mt][0], af[mt][1], af[mt][2], af[mt][3],
                            bf[nt][0], bf[nt][1]);
        }
    }

#pragma unroll
    for (int mt = 0; mt < 2; mt++) {
        const int r0 = by * BM + wm * 32 + mt * 16 + g;
#pragma unroll
        for (int nt = 0; nt < 4; nt++) {
            const int c0 = bx * 128 + wn * 32 + nt * 8 + t * 2;
            const float bz0 = bias[c0], bz1 = bias[c0 + 1];
            float v0 = acc[mt][nt][0] + bz0;
            float v1 = acc[mt][nt][1] + bz1;
            float v2 = acc[mt][nt][2] + bz0;
            float v3 = acc[mt][nt][3] + bz1;
            if (GELU) {
                v0 = 0.5f * v0 * (1.0f + erff(v0 * 0.70710678118654752f));
                v1 = 0.5f * v1 * (1.0f + erff(v1 * 0.70710678118654752f));
                v2 = 0.5f * v2 * (1.0f + erff(v2 * 0.70710678118654752f));
                v3 = 0.5f * v3 * (1.0f + erff(v3 * 0.70710678118654752f));
            }
            if (sizeof(OutT) == 2) {
                __half* Ch = reinterpret_cast<__half*>(C);
                *reinterpret_cast<unsigned*>(Ch + (size_t)r0 * N + c0) = pack_h2(v0, v1);
                *reinterpret_cast<unsigned*>(Ch + (size_t)(r0 + 8) * N + c0) = pack_h2(v2, v3);
            } else {
                float* Cf = reinterpret_cast<float*>(C);
                *reinterpret_cast<float2*>(Cf + (size_t)r0 * N + c0) = make_float2(v0, v1);
                *reinterpret_cast<float2*>(Cf + (size_t)(r0 + 8) * N + c0) = make_float2(v2, v3);
            }
        }
    }
}

template <bool GELU, typename OutT>
__global__ __launch_bounds__(256, 3) void gemm_h(
    const __half* __restrict__ A, const __half* __restrict__ B,
    const float* __restrict__ bias, OutT* __restrict__ C, int N, int K)
{
    gemm_h_body<GELU, OutT>(A, B, bias, C, N, K, blockIdx.x, blockIdx.y);
}

__global__ __launch_bounds__(256, 3) void gemm_h_qkv(
    const __half* __restrict__ X,
    const __half* __restrict__ Wqh, const __half* __restrict__ Wkh, const __half* __restrict__ Wvh,
    const float* __restrict__ bq, const float* __restrict__ bk, const float* __restrict__ bv,
    __half* __restrict__ q, __half* __restrict__ k, __half* __restrict__ v)
{
    const int which = blockIdx.x / 6;
    const int bx = blockIdx.x % 6;
    const __half* B   = (which == 0) ? Wqh : (which == 1) ? Wkh : Wvh;
    const float* bias = (which == 0) ? bq  : (which == 1) ? bk  : bv;
    __half* C         = (which == 0) ? q   : (which == 1) ? k   : v;
    gemm_h_body<false, __half>(X, B, bias, C, CDIM, CDIM, bx, blockIdx.y);
}

// ---------------- FP16 flash attention (3-stage cp.async + ldmatrix) --------
__global__ __launch_bounds__(256, 2) void flash_attn_h(
    const __half* __restrict__ Q, const __half* __restrict__ K,
    const __half* __restrict__ V, __half* __restrict__ O)
{
    constexpr int SR = 72;
    constexpr unsigned TILE = 64 * SR * 2;
    constexpr unsigned STAGE = 2 * TILE;

    extern __shared__ __half smh[];
    const unsigned kvb = smem_u32(smh);

    const int h  = blockIdx.x;
    const int qb = (gridDim.y - 1) - blockIdx.y;   // heavy blocks first
    const int tid  = threadIdx.x;
    const int lane = tid & 31;
    const int w = tid >> 5;
    const int g = lane >> 2;
    const int t = lane & 3;

    const int r0 = qb * 128 + w * 16 + g;
    const int r1 = r0 + 8;

    unsigned qf[4][4];
    {
        const __half2 sc = __float2half2_rn(0.125f);
        const __half* q0p = Q + (size_t)r0 * CDIM + h * HD;
        const __half* q1p = Q + (size_t)r1 * CDIM + h * HD;
#pragma unroll
        for (int kk = 0; kk < 4; kk++) {
            __half2 x0 = __hmul2(*reinterpret_cast<const __half2*>(q0p + kk * 16 + 2 * t), sc);
            __half2 x1 = __hmul2(*reinterpret_cast<const __half2*>(q1p + kk * 16 + 2 * t), sc);
            __half2 x2 = __hmul2(*reinterpret_cast<const __half2*>(q0p + kk * 16 + 2 * t + 8), sc);
            __half2 x3 = __hmul2(*reinterpret_cast<const __half2*>(q1p + kk * 16 + 2 * t + 8), sc);
            qf[kk][0] = *reinterpret_cast<unsigned*>(&x0);
            qf[kk][1] = *reinterpret_cast<unsigned*>(&x1);
            qf[kk][2] = *reinterpret_cast<unsigned*>(&x2);
            qf[kk][3] = *reinterpret_cast<unsigned*>(&x3);
        }
    }

    const int rb = (lane & 7) | ((lane & 16) >> 1);
    const int cbh = lane & 8;
    unsigned koff[4];
#pragma unroll
    for (int j = 0; j < 4; j++)
        koff[j] = ((j * 16 + rb) * SR + cbh) * 2;
    const int vr = lane & 15;
    const int vc = (lane >> 4) << 3;
    unsigned voff[4];
#pragma unroll
    for (int j = 0; j < 4; j++)
        voff[j] = TILE + (vr * SR + j * 16 + vc) * 2;

    float o[8][4] = {};
    float m0 = -1e30f, m1 = -1e30f, l0 = 0.f, l1 = 0.f;

    const int u0 = tid * 2;
    const int ntiles = 2 * (qb + 1);

    auto prefetch = [&](int kb) {
        const unsigned dst = kvb + (unsigned)(kb % 3) * STAGE;
        const int kbase = kb * 64;
#pragma unroll
        for (int j = 0; j < 2; j++) {
            const int u = u0 + j, row = u >> 3, c = u & 7;
            const unsigned off = (unsigned)(row * SR + c * 8) * 2;
            cp16(dst + off, K + (size_t)(kbase + row) * CDIM + h * HD + c * 8);
            cp16(dst + TILE + off, V + (size_t)(kbase + row) * CDIM + h * HD + c * 8);
        }
        cp_commit();
    };

    prefetch(0);
    if (ntiles > 1) prefetch(1);

    for (int kb = 0; kb < ntiles; kb++) {
        if (kb + 1 < ntiles) cp_wait1(); else cp_wait0();
        __syncthreads();
        if (kb + 2 < ntiles) prefetch(kb + 2);

        const unsigned kbase_s = kvb + (unsigned)(kb % 3) * STAGE;

        float s[8][4] = {};
#pragma unroll
        for (int kk = 0; kk < 4; kk++) {
            const unsigned kb2 = kk * 32;
#pragma unroll
            for (int j = 0; j < 4; j++) {
                unsigned b0, b1, b2, b3;
                ldsm4(b0, b1, b2, b3, kbase_s + koff[j] + kb2);
                mma_f16(s[2 * j][0], s[2 * j][1], s[2 * j][2], s[2 * j][3],
                        qf[kk][0], qf[kk][1], qf[kk][2], qf[kk][3], b0, b1);
                mma_f16(s[2 * j + 1][0], s[2 * j + 1][1], s[2 * j + 1][2], s[2 * j + 1][3],
                        qf[kk][0], qf[kk][1], qf[kk][2], qf[kk][3], b2, b3);
            }
        }

        if (kb >= 2 * qb) {
            const int cb = kb * 64;
#pragma unroll
            for (int nt = 0; nt < 8; nt++) {
                const int c0 = cb + nt * 8 + 2 * t;
                if (c0 > r0)     s[nt][0] = -1e30f;
                if (c0 + 1 > r0) s[nt][1] = -1e30f;
                if (c0 > r1)     s[nt][2] = -1e30f;
                if (c0 + 1 > r1) s[nt][3] = -1e30f;
            }
        }

        float mx0 = -1e30f, mx1 = -1e30f;
#pragma unroll
        for (int nt = 0; nt < 8; nt++) {
            mx0 = fmaxf(mx0, fmaxf(s[nt][0], s[nt][1]));
            mx1 = fmaxf(mx1, fmaxf(s[nt][2], s[nt][3]));
        }
        mx0 = fmaxf(mx0, __shfl_xor_sync(0xffffffffu, mx0, 1));
        mx0 = fmaxf(mx0, __shfl_xor_sync(0xffffffffu, mx0, 2));
        mx1 = fmaxf(mx1, __shfl_xor_sync(0xffffffffu, mx1, 1));
        mx1 = fmaxf(mx1, __shfl_xor_sync(0xffffffffu, mx1, 2));

        const float nm0 = fmaxf(m0, mx0);
        const float nm1 = fmaxf(m1, mx1);
        const float cr0 = __expf(m0 - nm0);
        const float cr1 = __expf(m1 - nm1);
        m0 = nm0; m1 = nm1;

        float sm0 = 0.f, sm1 = 0.f;
#pragma unroll
        for (int nt = 0; nt < 8; nt++) {
            float p0 = __expf(s[nt][0] - nm0);
            float p1 = __expf(s[nt][1] - nm0);
            float p2 = __expf(s[nt][2] - nm1);
            float p3 = __expf(s[nt][3] - nm1);
            s[nt][0] = p0; s[nt][1] = p1; s[nt][2] = p2; s[nt][3] = p3;
            sm0 += p0 + p1;
            sm1 += p2 + p3;
        }
        sm0 += __shfl_xor_sync(0xffffffffu, sm0, 1);
        sm0 += __shfl_xor_sync(0xffffffffu, sm0, 2);
        sm1 += __shfl_xor_sync(0xffffffffu, sm1, 1);
        sm1 += __shfl_xor_sync(0xffffffffu, sm1, 2);
        l0 = l0 * cr0 + sm0;
        l1 = l1 * cr1 + sm1;

#pragma unroll
        for (int nt = 0; nt < 8; nt++) {
            o[nt][0] *= cr0; o[nt][1] *= cr0;
            o[nt][2] *= cr1; o[nt][3] *= cr1;
        }

#pragma unroll
        for (int kk = 0; kk < 4; kk++) {
            unsigned a0 = pack_h2(s[2 * kk][0], s[2 * kk][1]);
            unsigned a1 = pack_h2(s[2 * kk][2], s[2 * kk][3]);
            unsigned a2 = pack_h2(s[2 * kk + 1][0], s[2 * kk + 1][1]);
            unsigned a3 = pack_h2(s[2 * kk + 1][2], s[2 * kk + 1][3]);
            const unsigned kb2 = kk * 16 * SR * 2;
#pragma unroll
            for (int j = 0; j < 4; j++) {
                unsigned b0, b1, b2, b3;
                ldsm4t(b0, b1, b2, b3, kbase_s + voff[j] + kb2);
                mma_f16(o[2 * j][0], o[2 * j][1], o[2 * j][2], o[2 * j][3],
                        a0, a1, a2, a3, b0, b1);
                mma_f16(o[2 * j + 1][0], o[2 * j + 1][1], o[2 * j + 1][2], o[2 * j + 1][3],
                        a0, a1, a2, a3, b2, b3);
            }
        }
    }

    const float inv0 = 1.f / l0;
    const float inv1 = 1.f / l1;
    __half* o0p = O + (size_t)r0 * CDIM + h * HD;
    __half* o1p = O + (size_t)r1 * CDIM + h * HD;
#pragma unroll
    for (int nt = 0; nt < 8; nt++) {
        const int c = nt * 8 + 2 * t;
        *reinterpret_cast<unsigned*>(o0p + c) = pack_h2(o[nt][0] * inv0, o[nt][1] * inv0);
        *reinterpret_cast<unsigned*>(o1p + c) = pack_h2(o[nt][2] * inv1, o[nt][3] * inv1);
    }
}

// ---------------- fused residual add + LayerNorm ---------------------------
template <bool DUALOUT>
__global__ __launch_bounds__(256) void add_ln(
    const float* __restrict__ A, const float* __restrict__ Bb,
    const float* __restrict__ g, const float* __restrict__ be,
    float* __restrict__ out, __half* __restrict__ out_h)
{
    const int row = blockIdx.x;
    const int tid = threadIdx.x;
    const float* pa = A + (size_t)row * CDIM;
    const float* pb = Bb + (size_t)row * CDIM;

    float v[3];
    float s = 0.f, sq = 0.f;
#pragma unroll
    for (int i = 0; i < 3; i++) {
        int idx = tid + i * 256;
        v[i] = pa[idx] + pb[idx];
        s += v[i];
        sq += v[i] * v[i];
    }
#pragma unroll
    for (int off = 16; off; off >>= 1) {
        s += __shfl_xor_sync(0xffffffffu, s, off);
        sq += __shfl_xor_sync(0xffffffffu, sq, off);
    }
    __shared__ float ss[8], ssq[8];
    int w = tid >> 5, lane = tid & 31;
    if (lane == 0) { ss[w] = s; ssq[w] = sq; }
    __syncthreads();
    if (tid < 32) {
        s = (tid < 8) ? ss[tid] : 0.f;
        sq = (tid < 8) ? ssq[tid] : 0.f;
#pragma unroll
        for (int off = 4; off; off >>= 1) {
            s += __shfl_xor_sync(0xffffffffu, s, off);
            sq += __shfl_xor_sync(0xffffffffu, sq, off);
        }
        if (tid == 0) { ss[0] = s; ssq[0] = sq; }
    }
    __syncthreads();
    const float mean = ss[0] * (1.0f / CDIM);
    const float var = ssq[0] * (1.0f / CDIM) - mean * mean;
    const float inv = rsqrtf(var + 1e-5f);
#pragma unroll
    for (int i = 0; i < 3; i++) {
        int idx = tid + i * 256;
        float r = (v[i] - mean) * inv * g[idx] + be[idx];
        out[(size_t)row * CDIM + idx] = r;
        if (DUALOUT)
            out_h[(size_t)row * CDIM + idx] = __float2half_rn(r);
    }
}

// ---------------- launch ----------------------------------------------------
extern "C" void kernel_launch(void* const* d_in, const int* in_sizes, int n_in,
                              void* d_out, int out_size)
{
    const float* x     = (const float*)d_in[0];
    const float* Wq    = (const float*)d_in[1];
    const float* bq    = (const float*)d_in[2];
    const float* Wk    = (const float*)d_in[3];
    const float* bk    = (const float*)d_in[4];
    const float* Wv    = (const float*)d_in[5];
    const float* bv    = (const float*)d_in[6];
    const float* Wo    = (const float*)d_in[7];
    const float* bo    = (const float*)d_in[8];
    const float* ln1g  = (const float*)d_in[9];
    const float* ln1b  = (const float*)d_in[10];
    const float* W1    = (const float*)d_in[11];
    const float* b1    = (const float*)d_in[12];
    const float* W2    = (const float*)d_in[13];
    const float* b2    = (const float*)d_in[14];
    const float* ln2g  = (const float*)d_in[15];
    const float* ln2b  = (const float*)d_in[16];
    float* y = (float*)d_out;

    __half *q, *k, *v, *attn, *hh, *m1, *xh, *wq, *wk, *wv, *wo, *w1, *w2;
    float *proj, *h, *m2;
    cudaGetSymbolAddress((void**)&q,    g_q);
    cudaGetSymbolAddress((void**)&k,    g_k);
    cudaGetSymbolAddress((void**)&v,    g_v);
    cudaGetSymbolAddress((void**)&attn, g_attn);
    cudaGetSymbolAddress((void**)&proj, g_proj);
    cudaGetSymbolAddress((void**)&h,    g_h);
    cudaGetSymbolAddress((void**)&hh,   g_hh);
    cudaGetSymbolAddress((void**)&m1,   g_mlp1);
    cudaGetSymbolAddress((void**)&m2,   g_mlp2);
    cudaGetSymbolAddress((void**)&xh,   g_xh);
    cudaGetSymbolAddress((void**)&wq,   g_wq);
    cudaGetSymbolAddress((void**)&wk,   g_wk);
    cudaGetSymbolAddress((void**)&wv,   g_wv);
    cudaGetSymbolAddress((void**)&wo,   g_wo);
    cudaGetSymbolAddress((void**)&w1,   g_w1);
    cudaGetSymbolAddress((void**)&w2,   g_w2);

    const int SMEM_G  = 3 * 24576;              // 73728 (3-stage, swizzled)
    const int SMEM_FA = 3 * 2 * 64 * 72 * 2;    // 55296
    cudaFuncSetAttribute(gemm_h_qkv, cudaFuncAttributeMaxDynamicSharedMemorySize, SMEM_G);
    cudaFuncSetAttribute(gemm_h<false, float>,  cudaFuncAttributeMaxDynamicSharedMemorySize, SMEM_G);
    cudaFuncSetAttribute(gemm_h<true, __half>,  cudaFuncAttributeMaxDynamicSharedMemorySize, SMEM_G);
    cudaFuncSetAttribute(flash_attn_h, cudaFuncAttributeMaxDynamicSharedMemorySize, SMEM_FA);

    // one fused convert launch: x + 6 weights -> half (16 floats/thread)
    CvtArgs ca;
    ca.s[0] = { x,  xh, SEQ * CDIM };
    ca.s[1] = { Wq, wq, CDIM * CDIM };
    ca.s[2] = { Wk, wk, CDIM * CDIM };
    ca.s[3] = { Wv, wv, CDIM * CDIM };
    ca.s[4] = { Wo, wo, CDIM * CDIM };
    ca.s[5] = { W1, w1, CDIM * FDIM };
    ca.s[6] = { W2, w2, FDIM * CDIM };
    cvt_all_kernel<<<dim3(SEQ * CDIM / 4096, 7), 256>>>(ca);

    // fused QKV projection (BM=64)
    gemm_h_qkv<<<dim3(18, SEQ / 64), 256, SMEM_G>>>(xh, wq, wk, wv, bq, bk, bv, q, k, v);

    // causal attention (heavy-first global order)
    flash_attn_h<<<dim3(NH, SEQ / 128), 256, SMEM_FA>>>(q, k, v, attn);

    // output projection
    gemm_h<false, float><<<dim3(CDIM / 128, SEQ / 64), 256, SMEM_G>>>(attn, wo, bo, proj, CDIM, CDIM);

    // h = LN(x + proj), plus half copy for W1
    add_ln<true><<<SEQ, 256>>>(x, proj, ln1g, ln1b, h, hh);

    // MLP
    gemm_h<true, __half><<<dim3(FDIM / 128, SEQ / 64), 256, SMEM_G>>>(hh, w1, b1, m1, FDIM, CDIM);
    gemm_h<false, float><<<dim3(CDIM / 128, SEQ / 64), 256, SMEM_G>>>(m1, w2, b2, m2, CDIM, FDIM);

    // y = LN(h + mlp)
    add_ln<false><<<SEQ, 256>>>(h, m2, ln2g, ln2b, y, nullptr);

    (void)in_sizes; (void)n_in; (void)out_size;
}

// round 14
// speedup vs baseline: 9.9820x; 1.0102x over previous
#include <cuda_runtime.h>
#include <cuda_fp16.h>
#include <math.h>
#include <cstdint>
#include <stdint.h>

#define SEQ 4096
#define CDIM 768
#define NH 12
#define HD 64
#define FDIM 3072

// ---------------- scratch (device globals; no allocation allowed) ----------
__device__ __half g_q[SEQ * CDIM];
__device__ __half g_k[SEQ * CDIM];
__device__ __half g_v[SEQ * CDIM];
__device__ __half g_attn[SEQ * CDIM];
__device__ float  g_proj[SEQ * CDIM];
__device__ float  g_h[SEQ * CDIM];
__device__ __half g_hh[SEQ * CDIM];
__device__ __half g_mlp1[SEQ * FDIM];
__device__ float  g_mlp2[SEQ * CDIM];
__device__ __half g_xh[SEQ * CDIM];
__device__ __half g_wq[CDIM * CDIM];     // [K,N] half (natural layout)
__device__ __half g_wk[CDIM * CDIM];
__device__ __half g_wv[CDIM * CDIM];
__device__ __half g_wo[CDIM * CDIM];
__device__ __half g_w1[CDIM * FDIM];
__device__ __half g_w2[FDIM * CDIM];

__device__ __forceinline__ void cp16(unsigned int dst, const void* src) {
    asm volatile("cp.async.cg.shared.global [%0], [%1], 16;" :: "r"(dst), "l"(src));
}
__device__ __forceinline__ void cp_commit() { asm volatile("cp.async.commit_group;"); }
__device__ __forceinline__ void cp_wait0() { asm volatile("cp.async.wait_group 0;"); }
__device__ __forceinline__ void cp_wait1() { asm volatile("cp.async.wait_group 1;"); }

__device__ __forceinline__ unsigned smem_u32(const void* p) {
    unsigned a;
    asm("{ .reg .u64 t; cvta.to.shared.u64 t, %1; cvt.u32.u64 %0, t; }" : "=r"(a) : "l"(p));
    return a;
}

__device__ __forceinline__ void mma_f16(
    float& d0, float& d1, float& d2, float& d3,
    unsigned a0, unsigned a1, unsigned a2, unsigned a3,
    unsigned b0, unsigned b1)
{
    asm volatile(
        "mma.sync.aligned.m16n8k16.row.col.f32.f16.f16.f32 "
        "{%0,%1,%2,%3},{%4,%5,%6,%7},{%8,%9},{%0,%1,%2,%3};"
        : "+f"(d0), "+f"(d1), "+f"(d2), "+f"(d3)
        : "r"(a0), "r"(a1), "r"(a2), "r"(a3), "r"(b0), "r"(b1));
}

__device__ __forceinline__ void ldsm4(
    unsigned& r0, unsigned& r1, unsigned& r2, unsigned& r3, unsigned addr)
{
    asm volatile("ldmatrix.sync.aligned.m8n8.x4.shared.b16 {%0,%1,%2,%3}, [%4];"
                 : "=r"(r0), "=r"(r1), "=r"(r2), "=r"(r3) : "r"(addr));
}

__device__ __forceinline__ void ldsm4t(
    unsigned& r0, unsigned& r1, unsigned& r2, unsigned& r3, unsigned addr)
{
    asm volatile("ldmatrix.sync.aligned.m8n8.x4.trans.shared.b16 {%0,%1,%2,%3}, [%4];"
                 : "=r"(r0), "=r"(r1), "=r"(r2), "=r"(r3) : "r"(addr));
}

__device__ __forceinline__ unsigned pack_h2(float lo, float hi) {
    __half2 h = __floats2half2_rn(lo, hi);
    return *reinterpret_cast<unsigned*>(&h);
}

// ---------------- fused float -> half converts (7 segments, 16 f/thread) ----
struct CvtSeg { const float* src; __half* dst; int n; };
struct CvtArgs { CvtSeg s[7]; };

__global__ __launch_bounds__(256) void cvt_all_kernel(CvtArgs a)
{
    const CvtSeg seg = a.s[blockIdx.y];
    const int base = (blockIdx.x * 256 + threadIdx.x) * 16;
#pragma unroll
    for (int j = 0; j < 4; j++) {
        const int i = base + j * 4;
        if (i < seg.n) {
            float4 v = *reinterpret_cast<const float4*>(seg.src + i);
            uint2 u;
            u.x = pack_h2(v.x, v.y);
            u.y = pack_h2(v.z, v.w);
            *reinterpret_cast<uint2*>(seg.dst + i) = u;
        }
    }
}

// ---------------- FP16 tensor-core GEMM (swizzled smem, 2-stage, 4 CTA/SM) --
// C[M,N] = A[M,K] @ B[K,N] + bias.  BM=64 x BN=128 tile, BK=64, 2-stage
// cp.async, XOR-swizzled smem, 256 thr = 8 warps (2Mx4N, warp tile 32x32),
// 4 CTAs/SM (reg cap 64), one barrier per chunk.
template <bool GELU, typename OutT>
__device__ __forceinline__ void gemm_h_body(
    const __half* __restrict__ A, const __half* __restrict__ B,
    const float* __restrict__ bias, OutT* __restrict__ C,
    int N, int K, int bx, int by)
{
    constexpr int BM = 64, BK = 64;
    constexpr unsigned ABYTES = 64 * 128;        // 8192
    constexpr unsigned BBYTES = 64 * 256;        // 16384
    constexpr unsigned STAGE = ABYTES + BBYTES;  // 24576

    extern __shared__ __half smh[];
    const unsigned smb = smem_u32(smh);

    const int tid = threadIdx.x, lane = tid & 31, warp = tid >> 5;
    const int wm = warp & 1, wn = warp >> 1;

    // ldmatrix lane geometry
    const int lr = lane & 15;
    const int hi = lane >> 4;
    const int rx = lr & 7;

    // A: swizzled row bases (two 16-row m-tiles)
    const unsigned arow0 = (unsigned)((wm * 32 + lr) * 128);
    const unsigned arow1 = arow0 + 16 * 128;

    // B: swizzled base offsets (two 16-col groups)
    const unsigned brow = ABYTES + (unsigned)(lr * 256);
    const unsigned bu0 = ((unsigned)((wn * 4 + hi) ^ rx) << 4);
    const unsigned bu1 = ((unsigned)((wn * 4 + 2 + hi) ^ rx) << 4);

    // loaders
    const int u0a = tid * 2;
    const int u0b = tid * 4;
    const __half* Abase = A + (size_t)(by * BM) * K;
    const __half* Bbase = B + (size_t)bx * 128;

    const int nchunks = K / BK;

    auto prefetch = [&](int ch) {
        const unsigned dst = smb + (unsigned)(ch & 1) * STAGE;
        const int k0 = ch * BK;
#pragma unroll
        for (int j = 0; j < 2; j++) {
            const int u = u0a + j, row = u >> 3, c16 = u & 7;
            cp16(dst + (unsigned)(row * 128) + ((unsigned)(c16 ^ (row & 7)) << 4),
                 Abase + (size_t)row * K + k0 + c16 * 8);
        }
#pragma unroll
        for (int j = 0; j < 4; j++) {
            const int u = u0b + j, row = u >> 4, c16 = u & 15;
            cp16(dst + ABYTES + (unsigned)(row * 256) + ((unsigned)(c16 ^ (row & 7)) << 4),
                 Bbase + (size_t)(k0 + row) * N + c16 * 8);
        }
        cp_commit();
    };

    float acc[2][4][4] = {};

    prefetch(0);

    for (int ch = 0; ch < nchunks; ch++) {
        cp_wait0();
        __syncthreads();
        if (ch + 1 < nchunks) prefetch(ch + 1);

        const unsigned sbase = smb + (unsigned)(ch & 1) * STAGE;
#pragma unroll
        for (int kk = 0; kk < 4; kk++) {
            unsigned af[2][4], bf[4][2];
            const unsigned aku = (unsigned)((kk * 2 + hi) ^ rx) << 4;
            ldsm4(af[0][0], af[0][1], af[0][2], af[0][3], sbase + arow0 + aku);
            ldsm4(af[1][0], af[1][1], af[1][2], af[1][3], sbase + arow1 + aku);
            const unsigned kadv = (unsigned)(kk * 16 * 256);
            ldsm4t(bf[0][0], bf[0][1], bf[1][0], bf[1][1], sbase + brow + bu0 + kadv);
            ldsm4t(bf[2][0], bf[2][1], bf[3][0], bf[3][1], sbase + brow + bu1 + kadv);
#pragma unroll
            for (int mt = 0; mt < 2; mt++)
#pragma unroll
                for (int nt = 0; nt < 4; nt++)
                    mma_f16(acc[mt][nt][0], acc[mt][nt][1], acc[mt][nt][2], acc[mt][nt][3],
                            af[mt][0], af[mt][1], af[mt][2], af[mt][3],
                            bf[nt][0], bf[nt][1]);
        }
        __syncthreads();
    }

    const int g = lane >> 2, t = lane & 3;
#pragma unroll
    for (int mt = 0; mt < 2; mt++) {
        const int r0 = by * BM + wm * 32 + mt * 16 + g;
#pragma unroll
        for (int nt = 0; nt < 4; nt++) {
            const int c0 = bx * 128 + wn * 32 + nt * 8 + t * 2;
            const float bz0 = bias[c0], bz1 = bias[c0 + 1];
            float v0 = acc[mt][nt][0] + bz0;
            float v1 = acc[mt][nt][1] + bz1;
            float v2 = acc[mt][nt][2] + bz0;
            float v3 = acc[mt][nt][3] + bz1;
            if (GELU) {
                v0 = 0.5f * v0 * (1.0f + erff(v0 * 0.70710678118654752f));
                v1 = 0.5f * v1 * (1.0f + erff(v1 * 0.70710678118654752f));
                v2 = 0.5f * v2 * (1.0f + erff(v2 * 0.70710678118654752f));
                v3 = 0.5f * v3 * (1.0f + erff(v3 * 0.70710678118654752f));
            }
            if (sizeof(OutT) == 2) {
                __half* Ch = reinterpret_cast<__half*>(C);
                *reinterpret_cast<unsigned*>(Ch + (size_t)r0 * N + c0) = pack_h2(v0, v1);
                *reinterpret_cast<unsigned*>(Ch + (size_t)(r0 + 8) * N + c0) = pack_h2(v2, v3);
            } else {
                float* Cf = reinterpret_cast<float*>(C);
                *reinterpret_cast<float2*>(Cf + (size_t)r0 * N + c0) = make_float2(v0, v1);
                *reinterpret_cast<float2*>(Cf + (size_t)(r0 + 8) * N + c0) = make_float2(v2, v3);
            }
        }
    }
}

template <bool GELU, typename OutT>
__global__ __launch_bounds__(256, 4) void gemm_h(
    const __half* __restrict__ A, const __half* __restrict__ B,
    const float* __restrict__ bias, OutT* __restrict__ C, int N, int K)
{
    gemm_h_body<GELU, OutT>(A, B, bias, C, N, K, blockIdx.x, blockIdx.y);
}

__global__ __launch_bounds__(256, 4) void gemm_h_qkv(
    const __half* __restrict__ X,
    const __half* __restrict__ Wqh, const __half* __restrict__ Wkh, const __half* __restrict__ Wvh,
    const float* __restrict__ bq, const float* __restrict__ bk, const float* __restrict__ bv,
    __half* __restrict__ q, __half* __restrict__ k, __half* __restrict__ v)
{
    const int which = blockIdx.x / 6;
    const int bx = blockIdx.x % 6;
    const __half* B   = (which == 0) ? Wqh : (which == 1) ? Wkh : Wvh;
    const float* bias = (which == 0) ? bq  : (which == 1) ? bk  : bv;
    __half* C         = (which == 0) ? q   : (which == 1) ? k   : v;
    gemm_h_body<false, __half>(X, B, bias, C, CDIM, CDIM, bx, blockIdx.y);
}

// ---------------- FP16 flash attention (3-stage cp.async + ldmatrix) --------
__global__ __launch_bounds__(256, 2) void flash_attn_h(
    const __half* __restrict__ Q, const __half* __restrict__ K,
    const __half* __restrict__ V, __half* __restrict__ O)
{
    constexpr int SR = 72;
    constexpr unsigned TILE = 64 * SR * 2;
    constexpr unsigned STAGE = 2 * TILE;

    extern __shared__ __half smh[];
    const unsigned kvb = smem_u32(smh);

    const int h  = blockIdx.x;
    const int qb = (gridDim.y - 1) - blockIdx.y;   // heavy blocks first
    const int tid  = threadIdx.x;
    const int lane = tid & 31;
    const int w = tid >> 5;
    const int g = lane >> 2;
    const int t = lane & 3;

    const int r0 = qb * 128 + w * 16 + g;
    const int r1 = r0 + 8;

    unsigned qf[4][4];
    {
        const __half2 sc = __float2half2_rn(0.125f);
        const __half* q0p = Q + (size_t)r0 * CDIM + h * HD;
        const __half* q1p = Q + (size_t)r1 * CDIM + h * HD;
#pragma unroll
        for (int kk = 0; kk < 4; kk++) {
            __half2 x0 = __hmul2(*reinterpret_cast<const __half2*>(q0p + kk * 16 + 2 * t), sc);
            __half2 x1 = __hmul2(*reinterpret_cast<const __half2*>(q1p + kk * 16 + 2 * t), sc);
            __half2 x2 = __hmul2(*reinterpret_cast<const __half2*>(q0p + kk * 16 + 2 * t + 8), sc);
            __half2 x3 = __hmul2(*reinterpret_cast<const __half2*>(q1p + kk * 16 + 2 * t + 8), sc);
            qf[kk][0] = *reinterpret_cast<unsigned*>(&x0);
            qf[kk][1] = *reinterpret_cast<unsigned*>(&x1);
            qf[kk][2] = *reinterpret_cast<unsigned*>(&x2);
            qf[kk][3] = *reinterpret_cast<unsigned*>(&x3);
        }
    }

    const int rb = (lane & 7) | ((lane & 16) >> 1);
    const int cbh = lane & 8;
    unsigned koff[4];
#pragma unroll
    for (int j = 0; j < 4; j++)
        koff[j] = ((j * 16 + rb) * SR + cbh) * 2;
    const int vr = lane & 15;
    const int vc = (lane >> 4) << 3;
    unsigned voff[4];
#pragma unroll
    for (int j = 0; j < 4; j++)
        voff[j] = TILE + (vr * SR + j * 16 + vc) * 2;

    float o[8][4] = {};
    float m0 = -1e30f, m1 = -1e30f, l0 = 0.f, l1 = 0.f;

    const int u0 = tid * 2;
    const int ntiles = 2 * (qb + 1);

    auto prefetch = [&](int kb) {
        const unsigned dst = kvb + (unsigned)(kb % 3) * STAGE;
        const int kbase = kb * 64;
#pragma unroll
        for (int j = 0; j < 2; j++) {
            const int u = u0 + j, row = u >> 3, c = u & 7;
            const unsigned off = (unsigned)(row * SR + c * 8) * 2;
            cp16(dst + off, K + (size_t)(kbase + row) * CDIM + h * HD + c * 8);
            cp16(dst + TILE + off, V + (size_t)(kbase + row) * CDIM + h * HD + c * 8);
        }
        cp_commit();
    };

    prefetch(0);
    if (ntiles > 1) prefetch(1);

    for (int kb = 0; kb < ntiles; kb++) {
        if (kb + 1 < ntiles) cp_wait1(); else cp_wait0();
        __syncthreads();
        if (kb + 2 < ntiles) prefetch(kb + 2);

        const unsigned kbase_s = kvb + (unsigned)(kb % 3) * STAGE;

        float s[8][4] = {};
#pragma unroll
        for (int kk = 0; kk < 4; kk++) {
            const unsigned kb2 = kk * 32;
#pragma unroll
            for (int j = 0; j < 4; j++) {
                unsigned b0, b1, b2, b3;
                ldsm4(b0, b1, b2, b3, kbase_s + koff[j] + kb2);
                mma_f16(s[2 * j][0], s[2 * j][1], s[2 * j][2], s[2 * j][3],
                        qf[kk][0], qf[kk][1], qf[kk][2], qf[kk][3], b0, b1);
                mma_f16(s[2 * j + 1][0], s[2 * j + 1][1], s[2 * j + 1][2], s[2 * j + 1][3],
                        qf[kk][0], qf[kk][1], qf[kk][2], qf[kk][3], b2, b3);
            }
        }

        if (kb >= 2 * qb) {
            const int cb = kb * 64;
#pragma unroll
            for (int nt = 0; nt < 8; nt++) {
                const int c0 = cb + nt * 8 + 2 * t;
                if (c0 > r0)     s[nt][0] = -1e30f;
                if (c0 + 1 > r0) s[nt][1] = -1e30f;
                if (c0 > r1)     s[nt][2] = -1e30f;
                if (c0 + 1 > r1) s[nt][3] = -1e30f;
            }
        }

        float mx0 = -1e30f, mx1 = -1e30f;
#pragma unroll
        for (int nt = 0; nt < 8; nt++) {
            mx0 = fmaxf(mx0, fmaxf(s[nt][0], s[nt][1]));
            mx1 = fmaxf(mx1, fmaxf(s[nt][2], s[nt][3]));
        }
        mx0 = fmaxf(mx0, __shfl_xor_sync(0xffffffffu, mx0, 1));
        mx0 = fmaxf(mx0, __shfl_xor_sync(0xffffffffu, mx0, 2));
        mx1 = fmaxf(mx1, __shfl_xor_sync(0xffffffffu, mx1, 1));
        mx1 = fmaxf(mx1, __shfl_xor_sync(0xffffffffu, mx1, 2));

        const float nm0 = fmaxf(m0, mx0);
        const float nm1 = fmaxf(m1, mx1);
        const float cr0 = __expf(m0 - nm0);
        const float cr1 = __expf(m1 - nm1);
        m0 = nm0; m1 = nm1;

        float sm0 = 0.f, sm1 = 0.f;
#pragma unroll
        for (int nt = 0; nt < 8; nt++) {
            float p0 = __expf(s[nt][0] - nm0);
            float p1 = __expf(s[nt][1] - nm0);
            float p2 = __expf(s[nt][2] - nm1);
            float p3 = __expf(s[nt][3] - nm1);
            s[nt][0] = p0; s[nt][1] = p1; s[nt][2] = p2; s[nt][3] = p3;
            sm0 += p0 + p1;
            sm1 += p2 + p3;
        }
        sm0 += __shfl_xor_sync(0xffffffffu, sm0, 1);
        sm0 += __shfl_xor_sync(0xffffffffu, sm0, 2);
        sm1 += __shfl_xor_sync(0xffffffffu, sm1, 1);
        sm1 += __shfl_xor_sync(0xffffffffu, sm1, 2);
        l0 = l0 * cr0 + sm0;
        l1 = l1 * cr1 + sm1;

#pragma unroll
        for (int nt = 0; nt < 8; nt++) {
            o[nt][0] *= cr0; o[nt][1] *= cr0;
            o[nt][2] *= cr1; o[nt][3] *= cr1;
        }

#pragma unroll
        for (int kk = 0; kk < 4; kk++) {
            unsigned a0 = pack_h2(s[2 * kk][0], s[2 * kk][1]);
            unsigned a1 = pack_h2(s[2 * kk][2], s[2 * kk][3]);
            unsigned a2 = pack_h2(s[2 * kk + 1][0], s[2 * kk + 1][1]);
            unsigned a3 = pack_h2(s[2 * kk + 1][2], s[2 * kk + 1][3]);
            const unsigned kb2 = kk * 16 * SR * 2;
#pragma unroll
            for (int j = 0; j < 4; j++) {
                unsigned b0, b1, b2, b3;
                ldsm4t(b0, b1, b2, b3, kbase_s + voff[j] + kb2);
                mma_f16(o[2 * j][0], o[2 * j][1], o[2 * j][2], o[2 * j][3],
                        a0, a1, a2, a3, b0, b1);
                mma_f16(o[2 * j + 1][0], o[2 * j + 1][1], o[2 * j + 1][2], o[2 * j + 1][3],
                        a0, a1, a2, a3, b2, b3);
            }
        }
    }

    const float inv0 = 1.f / l0;
    const float inv1 = 1.f / l1;
    __half* o0p = O + (size_t)r0 * CDIM + h * HD;
    __half* o1p = O + (size_t)r1 * CDIM + h * HD;
#pragma unroll
    for (int nt = 0; nt < 8; nt++) {
        const int c = nt * 8 + 2 * t;
        *reinterpret_cast<unsigned*>(o0p + c) = pack_h2(o[nt][0] * inv0, o[nt][1] * inv0);
        *reinterpret_cast<unsigned*>(o1p + c) = pack_h2(o[nt][2] * inv1, o[nt][3] * inv1);
    }
}

// ---------------- fused residual add + LayerNorm ---------------------------
template <bool DUALOUT>
__global__ __launch_bounds__(256) void add_ln(
    const float* __restrict__ A, const float* __restrict__ Bb,
    const float* __restrict__ g, const float* __restrict__ be,
    float* __restrict__ out, __half* __restrict__ out_h)
{
    const int row = blockIdx.x;
    const int tid = threadIdx.x;
    const float* pa = A + (size_t)row * CDIM;
    const float* pb = Bb + (size_t)row * CDIM;

    float v[3];
    float s = 0.f, sq = 0.f;
#pragma unroll
    for (int i = 0; i < 3; i++) {
        int idx = tid + i * 256;
        v[i] = pa[idx] + pb[idx];
        s += v[i];
        sq += v[i] * v[i];
    }
#pragma unroll
    for (int off = 16; off; off >>= 1) {
        s += __shfl_xor_sync(0xffffffffu, s, off);
        sq += __shfl_xor_sync(0xffffffffu, sq, off);
    }
    __shared__ float ss[8], ssq[8];
    int w = tid >> 5, lane = tid & 31;
    if (lane == 0) { ss[w] = s; ssq[w] = sq; }
    __syncthreads();
    if (tid < 32) {
        s = (tid < 8) ? ss[tid] : 0.f;
        sq = (tid < 8) ? ssq[tid] : 0.f;
#pragma unroll
        for (int off = 4; off; off >>= 1) {
            s += __shfl_xor_sync(0xffffffffu, s, off);
            sq += __shfl_xor_sync(0xffffffffu, sq, off);
        }
        if (tid == 0) { ss[0] = s; ssq[0] = sq; }
    }
    __syncthreads();
    const float mean = ss[0] * (1.0f / CDIM);
    const float var = ssq[0] * (1.0f / CDIM) - mean * mean;
    const float inv = rsqrtf(var + 1e-5f);
#pragma unroll
    for (int i = 0; i < 3; i++) {
        int idx = tid + i * 256;
        float r = (v[i] - mean) * inv * g[idx] + be[idx];
        out[(size_t)row * CDIM + idx] = r;
        if (DUALOUT)
            out_h[(size_t)row * CDIM + idx] = __float2half_rn(r);
    }
}

// ---------------- launch ----------------------------------------------------
extern "C" void kernel_launch(void* const* d_in, const int* in_sizes, int n_in,
                              void* d_out, int out_size)
{
    const float* x     = (const float*)d_in[0];
    const float* Wq    = (const float*)d_in[1];
    const float* bq    = (const float*)d_in[2];
    const float* Wk    = (const float*)d_in[3];
    const float* bk    = (const float*)d_in[4];
    const float* Wv    = (const float*)d_in[5];
    const float* bv    = (const float*)d_in[6];
    const float* Wo    = (const float*)d_in[7];
    const float* bo    = (const float*)d_in[8];
    const float* ln1g  = (const float*)d_in[9];
    const float* ln1b  = (const float*)d_in[10];
    const float* W1    = (const float*)d_in[11];
    const float* b1    = (const float*)d_in[12];
    const float* W2    = (const float*)d_in[13];
    const float* b2    = (const float*)d_in[14];
    const float* ln2g  = (const float*)d_in[15];
    const float* ln2b  = (const float*)d_in[16];
    float* y = (float*)d_out;

    __half *q, *k, *v, *attn, *hh, *m1, *xh, *wq, *wk, *wv, *wo, *w1, *w2;
    float *proj, *h, *m2;
    cudaGetSymbolAddress((void**)&q,    g_q);
    cudaGetSymbolAddress((void**)&k,    g_k);
    cudaGetSymbolAddress((void**)&v,    g_v);
    cudaGetSymbolAddress((void**)&attn, g_attn);
    cudaGetSymbolAddress((void**)&proj, g_proj);
    cudaGetSymbolAddress((void**)&h,    g_h);
    cudaGetSymbolAddress((void**)&hh,   g_hh);
    cudaGetSymbolAddress((void**)&m1,   g_mlp1);
    cudaGetSymbolAddress((void**)&m2,   g_mlp2);
    cudaGetSymbolAddress((void**)&xh,   g_xh);
    cudaGetSymbolAddress((void**)&wq,   g_wq);
    cudaGetSymbolAddress((void**)&wk,   g_wk);
    cudaGetSymbolAddress((void**)&wv,   g_wv);
    cudaGetSymbolAddress((void**)&wo,   g_wo);
    cudaGetSymbolAddress((void**)&w1,   g_w1);
    cudaGetSymbolAddress((void**)&w2,   g_w2);

    const int SMEM_G  = 2 * 24576;              // 49152 (2-stage, swizzled)
    const int SMEM_FA = 3 * 2 * 64 * 72 * 2;    // 55296
    cudaFuncSetAttribute(gemm_h_qkv, cudaFuncAttributeMaxDynamicSharedMemorySize, SMEM_G);
    cudaFuncSetAttribute(gemm_h<false, float>,  cudaFuncAttributeMaxDynamicSharedMemorySize, SMEM_G);
    cudaFuncSetAttribute(gemm_h<true, __half>,  cudaFuncAttributeMaxDynamicSharedMemorySize, SMEM_G);
    cudaFuncSetAttribute(flash_attn_h, cudaFuncAttributeMaxDynamicSharedMemorySize, SMEM_FA);

    // one fused convert launch: x + 6 weights -> half (16 floats/thread)
    CvtArgs ca;
    ca.s[0] = { x,  xh, SEQ * CDIM };
    ca.s[1] = { Wq, wq, CDIM * CDIM };
    ca.s[2] = { Wk, wk, CDIM * CDIM };
    ca.s[3] = { Wv, wv, CDIM * CDIM };
    ca.s[4] = { Wo, wo, CDIM * CDIM };
    ca.s[5] = { W1, w1, CDIM * FDIM };
    ca.s[6] = { W2, w2, FDIM * CDIM };
    cvt_all_kernel<<<dim3(SEQ * CDIM / 4096, 7), 256>>>(ca);

    // fused QKV projection (BM=64)
    gemm_h_qkv<<<dim3(18, SEQ / 64), 256, SMEM_G>>>(xh, wq, wk, wv, bq, bk, bv, q, k, v);

    // causal attention (heavy-first global order)
    flash_attn_h<<<dim3(NH, SEQ / 128), 256, SMEM_FA>>>(q, k, v, attn);

    // output projection
    gemm_h<false, float><<<dim3(CDIM / 128, SEQ / 64), 256, SMEM_G>>>(attn, wo, bo, proj, CDIM, CDIM);

    // h = LN(x + proj), plus half copy for W1
    add_ln<true><<<SEQ, 256>>>(x, proj, ln1g, ln1b, h, hh);

    // MLP
    gemm_h<true, __half><<<dim3(FDIM / 128, SEQ / 64), 256, SMEM_G>>>(hh, w1, b1, m1, FDIM, CDIM);
    gemm_h<false, float><<<dim3(CDIM / 128, SEQ / 64), 256, SMEM_G>>>(m1, w2, b2, m2, CDIM, FDIM);

    // y = LN(h + mlp)
    add_ln<false><<<SEQ, 256>>>(h, m2, ln2g, ln2b, y, nullptr);

    (void)in_sizes; (void)n_in; (void)out_size;
}

// round 15
// speedup vs baseline: 9.9892x; 1.0007x over previous
#include <cuda_runtime.h>
#include <cuda_fp16.h>
#include <math.h>
#include <cstdint>
#include <stdint.h>

#define SEQ 4096
#define CDIM 768
#define NH 12
#define HD 64
#define FDIM 3072

// ---------------- scratch (device globals; no allocation allowed) ----------
__device__ __half g_q[SEQ * CDIM];
__device__ __half g_k[SEQ * CDIM];
__device__ __half g_v[SEQ * CDIM];
__device__ __half g_attn[SEQ * CDIM];
__device__ float  g_proj[SEQ * CDIM];
__device__ float  g_h[SEQ * CDIM];
__device__ __half g_hh[SEQ * CDIM];
__device__ __half g_mlp1[SEQ * FDIM];
__device__ float  g_mlp2[SEQ * CDIM];
__device__ __half g_xh[SEQ * CDIM];
__device__ __half g_wq[CDIM * CDIM];     // [K,N] half (natural layout)
__device__ __half g_wk[CDIM * CDIM];
__device__ __half g_wv[CDIM * CDIM];
__device__ __half g_wo[CDIM * CDIM];
__device__ __half g_w1[CDIM * FDIM];
__device__ __half g_w2[FDIM * CDIM];

__device__ __forceinline__ void cp16(unsigned int dst, const void* src) {
    asm volatile("cp.async.cg.shared.global [%0], [%1], 16;" :: "r"(dst), "l"(src));
}
__device__ __forceinline__ void cp_commit() { asm volatile("cp.async.commit_group;"); }
__device__ __forceinline__ void cp_wait0() { asm volatile("cp.async.wait_group 0;"); }
__device__ __forceinline__ void cp_wait1() { asm volatile("cp.async.wait_group 1;"); }

__device__ __forceinline__ unsigned smem_u32(const void* p) {
    unsigned a;
    asm("{ .reg .u64 t; cvta.to.shared.u64 t, %1; cvt.u32.u64 %0, t; }" : "=r"(a) : "l"(p));
    return a;
}

__device__ __forceinline__ void mma_f16(
    float& d0, float& d1, float& d2, float& d3,
    unsigned a0, unsigned a1, unsigned a2, unsigned a3,
    unsigned b0, unsigned b1)
{
    asm volatile(
        "mma.sync.aligned.m16n8k16.row.col.f32.f16.f16.f32 "
        "{%0,%1,%2,%3},{%4,%5,%6,%7},{%8,%9},{%0,%1,%2,%3};"
        : "+f"(d0), "+f"(d1), "+f"(d2), "+f"(d3)
        : "r"(a0), "r"(a1), "r"(a2), "r"(a3), "r"(b0), "r"(b1));
}

__device__ __forceinline__ void ldsm4(
    unsigned& r0, unsigned& r1, unsigned& r2, unsigned& r3, unsigned addr)
{
    asm volatile("ldmatrix.sync.aligned.m8n8.x4.shared.b16 {%0,%1,%2,%3}, [%4];"
                 : "=r"(r0), "=r"(r1), "=r"(r2), "=r"(r3) : "r"(addr));
}

__device__ __forceinline__ void ldsm4t(
    unsigned& r0, unsigned& r1, unsigned& r2, unsigned& r3, unsigned addr)
{
    asm volatile("ldmatrix.sync.aligned.m8n8.x4.trans.shared.b16 {%0,%1,%2,%3}, [%4];"
                 : "=r"(r0), "=r"(r1), "=r"(r2), "=r"(r3) : "r"(addr));
}

__device__ __forceinline__ unsigned pack_h2(float lo, float hi) {
    __half2 h = __floats2half2_rn(lo, hi);
    return *reinterpret_cast<unsigned*>(&h);
}

// ---------------- fused float -> half converts (7 segments, 16 f/thread) ----
struct CvtSeg { const float* src; __half* dst; int n; };
struct CvtArgs { CvtSeg s[7]; };

__global__ __launch_bounds__(256) void cvt_all_kernel(CvtArgs a)
{
    const CvtSeg seg = a.s[blockIdx.y];
    const int base = (blockIdx.x * 256 + threadIdx.x) * 16;
#pragma unroll
    for (int j = 0; j < 4; j++) {
        const int i = base + j * 4;
        if (i < seg.n) {
            float4 v = *reinterpret_cast<const float4*>(seg.src + i);
            uint2 u;
            u.x = pack_h2(v.x, v.y);
            u.y = pack_h2(v.z, v.w);
            *reinterpret_cast<uint2*>(seg.dst + i) = u;
        }
    }
}

// ---------------- shared GEMM epilogue ---------------------------------------
template <bool GELU, typename OutT>
__device__ __forceinline__ void gemm_epilogue(
    float acc[2][4][4], const float* __restrict__ bias, OutT* __restrict__ C,
    int N, int bx, int by, int wm, int wn, int lane)
{
    const int g = lane >> 2, t = lane & 3;
#pragma unroll
    for (int mt = 0; mt < 2; mt++) {
        const int r0 = by * 64 + wm * 32 + mt * 16 + g;
#pragma unroll
        for (int nt = 0; nt < 4; nt++) {
            const int c0 = bx * 128 + wn * 32 + nt * 8 + t * 2;
            const float bz0 = bias[c0], bz1 = bias[c0 + 1];
            float v0 = acc[mt][nt][0] + bz0;
            float v1 = acc[mt][nt][1] + bz1;
            float v2 = acc[mt][nt][2] + bz0;
            float v3 = acc[mt][nt][3] + bz1;
            if (GELU) {
                v0 = 0.5f * v0 * (1.0f + erff(v0 * 0.70710678118654752f));
                v1 = 0.5f * v1 * (1.0f + erff(v1 * 0.70710678118654752f));
                v2 = 0.5f * v2 * (1.0f + erff(v2 * 0.70710678118654752f));
                v3 = 0.5f * v3 * (1.0f + erff(v3 * 0.70710678118654752f));
            }
            if (sizeof(OutT) == 2) {
                __half* Ch = reinterpret_cast<__half*>(C);
                *reinterpret_cast<unsigned*>(Ch + (size_t)r0 * N + c0) = pack_h2(v0, v1);
                *reinterpret_cast<unsigned*>(Ch + (size_t)(r0 + 8) * N + c0) = pack_h2(v2, v3);
            } else {
                float* Cf = reinterpret_cast<float*>(C);
                *reinterpret_cast<float2*>(Cf + (size_t)r0 * N + c0) = make_float2(v0, v1);
                *reinterpret_cast<float2*>(Cf + (size_t)(r0 + 8) * N + c0) = make_float2(v2, v3);
            }
        }
    }
}

// ---------------- GEMM body: 3-stage variant (R13, for small grids) ----------
template <bool GELU, typename OutT>
__device__ __forceinline__ void gemm_body3(
    const __half* __restrict__ A, const __half* __restrict__ B,
    const float* __restrict__ bias, OutT* __restrict__ C,
    int N, int K, int bx, int by)
{
    constexpr int BM = 64, BK = 64;
    constexpr unsigned ABYTES = 64 * 128;
    constexpr unsigned STAGE = ABYTES + 64 * 256;   // 24576

    extern __shared__ __half smh[];
    const unsigned smb = smem_u32(smh);

    const int tid = threadIdx.x, lane = tid & 31, warp = tid >> 5;
    const int wm = warp & 1, wn = warp >> 1;

    const int lr = lane & 15;
    const int hi = lane >> 4;
    const int rx = lr & 7;

    unsigned arow[2];
#pragma unroll
    for (int mt = 0; mt < 2; mt++)
        arow[mt] = (unsigned)((wm * 32 + mt * 16 + lr) * 128);

    unsigned boff[2];
#pragma unroll
    for (int j = 0; j < 2; j++) {
        const int nunit = wn * 4 + j * 2 + hi;
        boff[j] = ABYTES + (unsigned)(lr * 256) + ((unsigned)(nunit ^ rx) << 4);
    }

    const int u0a = tid * 2;
    const int u0b = tid * 4;
    const __half* Abase = A + (size_t)(by * BM) * K;
    const __half* Bbase = B + (size_t)bx * 128;

    const int nchunks = K / BK;

    auto prefetch = [&](int ch) {
        const unsigned dst = smb + (unsigned)(ch % 3) * STAGE;
        const int k0 = ch * BK;
#pragma unroll
        for (int j = 0; j < 2; j++) {
            const int u = u0a + j, row = u >> 3, c16 = u & 7;
            cp16(dst + (unsigned)(row * 128) + ((unsigned)(c16 ^ (row & 7)) << 4),
                 Abase + (size_t)row * K + k0 + c16 * 8);
        }
#pragma unroll
        for (int j = 0; j < 4; j++) {
            const int u = u0b + j, row = u >> 4, c16 = u & 15;
            cp16(dst + ABYTES + (unsigned)(row * 256) + ((unsigned)(c16 ^ (row & 7)) << 4),
                 Bbase + (size_t)(k0 + row) * N + c16 * 8);
        }
        cp_commit();
    };

    float acc[2][4][4] = {};

    prefetch(0);
    prefetch(1);

    for (int ch = 0; ch < nchunks; ch++) {
        if (ch + 1 < nchunks) cp_wait1(); else cp_wait0();
        __syncthreads();
        if (ch + 2 < nchunks) prefetch(ch + 2);

        const unsigned sbase = smb + (unsigned)(ch % 3) * STAGE;
#pragma unroll
        for (int kk = 0; kk < 4; kk++) {
            unsigned af[2][4], bf[4][2];
            const unsigned aku = (unsigned)((kk * 2 + hi) ^ rx) << 4;
#pragma unroll
            for (int mt = 0; mt < 2; mt++)
                ldsm4(af[mt][0], af[mt][1], af[mt][2], af[mt][3],
                      sbase + arow[mt] + aku);
            const unsigned kadv = (unsigned)(kk * 16 * 256);
#pragma unroll
            for (int j = 0; j < 2; j++)
                ldsm4t(bf[2 * j][0], bf[2 * j][1], bf[2 * j + 1][0], bf[2 * j + 1][1],
                       sbase + boff[j] + kadv);
#pragma unroll
            for (int mt = 0; mt < 2; mt++)
#pragma unroll
                for (int nt = 0; nt < 4; nt++)
                    mma_f16(acc[mt][nt][0], acc[mt][nt][1], acc[mt][nt][2], acc[mt][nt][3],
                            af[mt][0], af[mt][1], af[mt][2], af[mt][3],
                            bf[nt][0], bf[nt][1]);
        }
    }

    gemm_epilogue<GELU, OutT>(acc, bias, C, N, bx, by, wm, wn, lane);
}

// ---------------- GEMM body: 2-stage variant (R14, for big grids) ------------
template <bool GELU, typename OutT>
__device__ __forceinline__ void gemm_body4(
    const __half* __restrict__ A, const __half* __restrict__ B,
    const float* __restrict__ bias, OutT* __restrict__ C,
    int N, int K, int bx, int by)
{
    constexpr int BM = 64, BK = 64;
    constexpr unsigned ABYTES = 64 * 128;
    constexpr unsigned STAGE = ABYTES + 64 * 256;   // 24576

    extern __shared__ __half smh[];
    const unsigned smb = smem_u32(smh);

    const int tid = threadIdx.x, lane = tid & 31, warp = tid >> 5;
    const int wm = warp & 1, wn = warp >> 1;

    const int lr = lane & 15;
    const int hi = lane >> 4;
    const int rx = lr & 7;

    const unsigned arow0 = (unsigned)((wm * 32 + lr) * 128);
    const unsigned arow1 = arow0 + 16 * 128;

    const unsigned brow = ABYTES + (unsigned)(lr * 256);
    const unsigned bu0 = ((unsigned)((wn * 4 + hi) ^ rx) << 4);
    const unsigned bu1 = ((unsigned)((wn * 4 + 2 + hi) ^ rx) << 4);

    const int u0a = tid * 2;
    const int u0b = tid * 4;
    const __half* Abase = A + (size_t)(by * BM) * K;
    const __half* Bbase = B + (size_t)bx * 128;

    const int nchunks = K / BK;

    auto prefetch = [&](int ch) {
        const unsigned dst = smb + (unsigned)(ch & 1) * STAGE;
        const int k0 = ch * BK;
#pragma unroll
        for (int j = 0; j < 2; j++) {
            const int u = u0a + j, row = u >> 3, c16 = u & 7;
            cp16(dst + (unsigned)(row * 128) + ((unsigned)(c16 ^ (row & 7)) << 4),
                 Abase + (size_t)row * K + k0 + c16 * 8);
        }
#pragma unroll
        for (int j = 0; j < 4; j++) {
            const int u = u0b + j, row = u >> 4, c16 = u & 15;
            cp16(dst + ABYTES + (unsigned)(row * 256) + ((unsigned)(c16 ^ (row & 7)) << 4),
                 Bbase + (size_t)(k0 + row) * N + c16 * 8);
        }
        cp_commit();
    };

    float acc[2][4][4] = {};

    prefetch(0);

    for (int ch = 0; ch < nchunks; ch++) {
        cp_wait0();
        __syncthreads();
        if (ch + 1 < nchunks) prefetch(ch + 1);

        const unsigned sbase = smb + (unsigned)(ch & 1) * STAGE;
#pragma unroll
        for (int kk = 0; kk < 4; kk++) {
            unsigned af[2][4], bf[4][2];
            const unsigned aku = (unsigned)((kk * 2 + hi) ^ rx) << 4;
            ldsm4(af[0][0], af[0][1], af[0][2], af[0][3], sbase + arow0 + aku);
            ldsm4(af[1][0], af[1][1], af[1][2], af[1][3], sbase + arow1 + aku);
            const unsigned kadv = (unsigned)(kk * 16 * 256);
            ldsm4t(bf[0][0], bf[0][1], bf[1][0], bf[1][1], sbase + brow + bu0 + kadv);
            ldsm4t(bf[2][0], bf[2][1], bf[3][0], bf[3][1], sbase + brow + bu1 + kadv);
#pragma unroll
            for (int mt = 0; mt < 2; mt++)
#pragma unroll
                for (int nt = 0; nt < 4; nt++)
                    mma_f16(acc[mt][nt][0], acc[mt][nt][1], acc[mt][nt][2], acc[mt][nt][3],
                            af[mt][0], af[mt][1], af[mt][2], af[mt][3],
                            bf[nt][0], bf[nt][1]);
        }
        __syncthreads();
    }

    gemm_epilogue<GELU, OutT>(acc, bias, C, N, bx, by, wm, wn, lane);
}

// small-grid GEMMs: 3-stage, 3 CTAs/SM
template <bool GELU, typename OutT>
__global__ __launch_bounds__(256, 3) void gemm_s(
    const __half* __restrict__ A, const __half* __restrict__ B,
    const float* __restrict__ bias, OutT* __restrict__ C, int N, int K)
{
    gemm_body3<GELU, OutT>(A, B, bias, C, N, K, blockIdx.x, blockIdx.y);
}

// big-grid GEMMs: 2-stage, 4 CTAs/SM
template <bool GELU, typename OutT>
__global__ __launch_bounds__(256, 4) void gemm_b(
    const __half* __restrict__ A, const __half* __restrict__ B,
    const float* __restrict__ bias, OutT* __restrict__ C, int N, int K)
{
    gemm_body4<GELU, OutT>(A, B, bias, C, N, K, blockIdx.x, blockIdx.y);
}

__global__ __launch_bounds__(256, 4) void gemm_b_qkv(
    const __half* __restrict__ X,
    const __half* __restrict__ Wqh, const __half* __restrict__ Wkh, const __half* __restrict__ Wvh,
    const float* __restrict__ bq, const float* __restrict__ bk, const float* __restrict__ bv,
    __half* __restrict__ q, __half* __restrict__ k, __half* __restrict__ v)
{
    const int which = blockIdx.x / 6;
    const int bx = blockIdx.x % 6;
    const __half* B   = (which == 0) ? Wqh : (which == 1) ? Wkh : Wvh;
    const float* bias = (which == 0) ? bq  : (which == 1) ? bk  : bv;
    __half* C         = (which == 0) ? q   : (which == 1) ? k   : v;
    gemm_body4<false, __half>(X, B, bias, C, CDIM, CDIM, bx, blockIdx.y);
}

// ---------------- FP16 flash attention (3-stage cp.async + ldmatrix) --------
__global__ __launch_bounds__(256, 2) void flash_attn_h(
    const __half* __restrict__ Q, const __half* __restrict__ K,
    const __half* __restrict__ V, __half* __restrict__ O)
{
    constexpr int SR = 72;
    constexpr unsigned TILE = 64 * SR * 2;
    constexpr unsigned STAGE = 2 * TILE;

    extern __shared__ __half smh[];
    const unsigned kvb = smem_u32(smh);

    const int h  = blockIdx.x;
    const int qb = (gridDim.y - 1) - blockIdx.y;   // heavy blocks first
    const int tid  = threadIdx.x;
    const int lane = tid & 31;
    const int w = tid >> 5;
    const int g = lane >> 2;
    const int t = lane & 3;

    const int r0 = qb * 128 + w * 16 + g;
    const int r1 = r0 + 8;

    unsigned qf[4][4];
    {
        const __half2 sc = __float2half2_rn(0.125f);
        const __half* q0p = Q + (size_t)r0 * CDIM + h * HD;
        const __half* q1p = Q + (size_t)r1 * CDIM + h * HD;
#pragma unroll
        for (int kk = 0; kk < 4; kk++) {
            __half2 x0 = __hmul2(*reinterpret_cast<const __half2*>(q0p + kk * 16 + 2 * t), sc);
            __half2 x1 = __hmul2(*reinterpret_cast<const __half2*>(q1p + kk * 16 + 2 * t), sc);
            __half2 x2 = __hmul2(*reinterpret_cast<const __half2*>(q0p + kk * 16 + 2 * t + 8), sc);
            __half2 x3 = __hmul2(*reinterpret_cast<const __half2*>(q1p + kk * 16 + 2 * t + 8), sc);
            qf[kk][0] = *reinterpret_cast<unsigned*>(&x0);
            qf[kk][1] = *reinterpret_cast<unsigned*>(&x1);
            qf[kk][2] = *reinterpret_cast<unsigned*>(&x2);
            qf[kk][3] = *reinterpret_cast<unsigned*>(&x3);
        }
    }

    const int rb = (lane & 7) | ((lane & 16) >> 1);
    const int cbh = lane & 8;
    unsigned koff[4];
#pragma unroll
    for (int j = 0; j < 4; j++)
        koff[j] = ((j * 16 + rb) * SR + cbh) * 2;
    const int vr = lane & 15;
    const int vc = (lane >> 4) << 3;
    unsigned voff[4];
#pragma unroll
    for (int j = 0; j < 4; j++)
        voff[j] = TILE + (vr * SR + j * 16 + vc) * 2;

    float o[8][4] = {};
    float m0 = -1e30f, m1 = -1e30f, l0 = 0.f, l1 = 0.f;

    const int u0 = tid * 2;
    const int ntiles = 2 * (qb + 1);

    auto prefetch = [&](int kb) {
        const unsigned dst = kvb + (unsigned)(kb % 3) * STAGE;
        const int kbase = kb * 64;
#pragma unroll
        for (int j = 0; j < 2; j++) {
            const int u = u0 + j, row = u >> 3, c = u & 7;
            const unsigned off = (unsigned)(row * SR + c * 8) * 2;
            cp16(dst + off, K + (size_t)(kbase + row) * CDIM + h * HD + c * 8);
            cp16(dst + TILE + off, V + (size_t)(kbase + row) * CDIM + h * HD + c * 8);
        }
        cp_commit();
    };

    prefetch(0);
    if (ntiles > 1) prefetch(1);

    for (int kb = 0; kb < ntiles; kb++) {
        if (kb + 1 < ntiles) cp_wait1(); else cp_wait0();
        __syncthreads();
        if (kb + 2 < ntiles) prefetch(kb + 2);

        const unsigned kbase_s = kvb + (unsigned)(kb % 3) * STAGE;

        float s[8][4] = {};
#pragma unroll
        for (int kk = 0; kk < 4; kk++) {
            const unsigned kb2 = kk * 32;
#pragma unroll
            for (int j = 0; j < 4; j++) {
                unsigned b0, b1, b2, b3;
                ldsm4(b0, b1, b2, b3, kbase_s + koff[j] + kb2);
                mma_f16(s[2 * j][0], s[2 * j][1], s[2 * j][2], s[2 * j][3],
                        qf[kk][0], qf[kk][1], qf[kk][2], qf[kk][3], b0, b1);
                mma_f16(s[2 * j + 1][0], s[2 * j + 1][1], s[2 * j + 1][2], s[2 * j + 1][3],
                        qf[kk][0], qf[kk][1], qf[kk][2], qf[kk][3], b2, b3);
            }
        }

        if (kb >= 2 * qb) {
            const int cb = kb * 64;
#pragma unroll
            for (int nt = 0; nt < 8; nt++) {
                const int c0 = cb + nt * 8 + 2 * t;
                if (c0 > r0)     s[nt][0] = -1e30f;
                if (c0 + 1 > r0) s[nt][1] = -1e30f;
                if (c0 > r1)     s[nt][2] = -1e30f;
                if (c0 + 1 > r1) s[nt][3] = -1e30f;
            }
        }

        float mx0 = -1e30f, mx1 = -1e30f;
#pragma unroll
        for (int nt = 0; nt < 8; nt++) {
            mx0 = fmaxf(mx0, fmaxf(s[nt][0], s[nt][1]));
            mx1 = fmaxf(mx1, fmaxf(s[nt][2], s[nt][3]));
        }
        mx0 = fmaxf(mx0, __shfl_xor_sync(0xffffffffu, mx0, 1));
        mx0 = fmaxf(mx0, __shfl_xor_sync(0xffffffffu, mx0, 2));
        mx1 = fmaxf(mx1, __shfl_xor_sync(0xffffffffu, mx1, 1));
        mx1 = fmaxf(mx1, __shfl_xor_sync(0xffffffffu, mx1, 2));

        const float nm0 = fmaxf(m0, mx0);
        const float nm1 = fmaxf(m1, mx1);
        const float cr0 = __expf(m0 - nm0);
        const float cr1 = __expf(m1 - nm1);
        m0 = nm0; m1 = nm1;

        float sm0 = 0.f, sm1 = 0.f;
#pragma unroll
        for (int nt = 0; nt < 8; nt++) {
            float p0 = __expf(s[nt][0] - nm0);
            float p1 = __expf(s[nt][1] - nm0);
            float p2 = __expf(s[nt][2] - nm1);
            float p3 = __expf(s[nt][3] - nm1);
            s[nt][0] = p0; s[nt][1] = p1; s[nt][2] = p2; s[nt][3] = p3;
            sm0 += p0 + p1;
            sm1 += p2 + p3;
        }
        sm0 += __shfl_xor_sync(0xffffffffu, sm0, 1);
        sm0 += __shfl_xor_sync(0xffffffffu, sm0, 2);
        sm1 += __shfl_xor_sync(0xffffffffu, sm1, 1);
        sm1 += __shfl_xor_sync(0xffffffffu, sm1, 2);
        l0 = l0 * cr0 + sm0;
        l1 = l1 * cr1 + sm1;

#pragma unroll
        for (int nt = 0; nt < 8; nt++) {
            o[nt][0] *= cr0; o[nt][1] *= cr0;
            o[nt][2] *= cr1; o[nt][3] *= cr1;
        }

#pragma unroll
        for (int kk = 0; kk < 4; kk++) {
            unsigned a0 = pack_h2(s[2 * kk][0], s[2 * kk][1]);
            unsigned a1 = pack_h2(s[2 * kk][2], s[2 * kk][3]);
            unsigned a2 = pack_h2(s[2 * kk + 1][0], s[2 * kk + 1][1]);
            unsigned a3 = pack_h2(s[2 * kk + 1][2], s[2 * kk + 1][3]);
            const unsigned kb2 = kk * 16 * SR * 2;
#pragma unroll
            for (int j = 0; j < 4; j++) {
                unsigned b0, b1, b2, b3;
                ldsm4t(b0, b1, b2, b3, kbase_s + voff[j] + kb2);
                mma_f16(o[2 * j][0], o[2 * j][1], o[2 * j][2], o[2 * j][3],
                        a0, a1, a2, a3, b0, b1);
                mma_f16(o[2 * j + 1][0], o[2 * j + 1][1], o[2 * j + 1][2], o[2 * j + 1][3],
                        a0, a1, a2, a3, b2, b3);
            }
        }
    }

    const float inv0 = 1.f / l0;
    const float inv1 = 1.f / l1;
    __half* o0p = O + (size_t)r0 * CDIM + h * HD;
    __half* o1p = O + (size_t)r1 * CDIM + h * HD;
#pragma unroll
    for (int nt = 0; nt < 8; nt++) {
        const int c = nt * 8 + 2 * t;
        *reinterpret_cast<unsigned*>(o0p + c) = pack_h2(o[nt][0] * inv0, o[nt][1] * inv0);
        *reinterpret_cast<unsigned*>(o1p + c) = pack_h2(o[nt][2] * inv1, o[nt][3] * inv1);
    }
}

// ---------------- fused residual add + LayerNorm ---------------------------
template <bool DUALOUT>
__global__ __launch_bounds__(256) void add_ln(
    const float* __restrict__ A, const float* __restrict__ Bb,
    const float* __restrict__ g, const float* __restrict__ be,
    float* __restrict__ out, __half* __restrict__ out_h)
{
    const int row = blockIdx.x;
    const int tid = threadIdx.x;
    const float* pa = A + (size_t)row * CDIM;
    const float* pb = Bb + (size_t)row * CDIM;

    float v[3];
    float s = 0.f, sq = 0.f;
#pragma unroll
    for (int i = 0; i < 3; i++) {
        int idx = tid + i * 256;
        v[i] = pa[idx] + pb[idx];
        s += v[i];
        sq += v[i] * v[i];
    }
#pragma unroll
    for (int off = 16; off; off >>= 1) {
        s += __shfl_xor_sync(0xffffffffu, s, off);
        sq += __shfl_xor_sync(0xffffffffu, sq, off);
    }
    __shared__ float ss[8], ssq[8];
    int w = tid >> 5, lane = tid & 31;
    if (lane == 0) { ss[w] = s; ssq[w] = sq; }
    __syncthreads();
    if (tid < 32) {
        s = (tid < 8) ? ss[tid] : 0.f;
        sq = (tid < 8) ? ssq[tid] : 0.f;
#pragma unroll
        for (int off = 4; off; off >>= 1) {
            s += __shfl_xor_sync(0xffffffffu, s, off);
            sq += __shfl_xor_sync(0xffffffffu, sq, off);
        }
        if (tid == 0) { ss[0] = s; ssq[0] = sq; }
    }
    __syncthreads();
    const float mean = ss[0] * (1.0f / CDIM);
    const float var = ssq[0] * (1.0f / CDIM) - mean * mean;
    const float inv = rsqrtf(var + 1e-5f);
#pragma unroll
    for (int i = 0; i < 3; i++) {
        int idx = tid + i * 256;
        float r = (v[i] - mean) * inv * g[idx] + be[idx];
        out[(size_t)row * CDIM + idx] = r;
        if (DUALOUT)
            out_h[(size_t)row * CDIM + idx] = __float2half_rn(r);
    }
}

// ---------------- launch ----------------------------------------------------
extern "C" void kernel_launch(void* const* d_in, const int* in_sizes, int n_in,
                              void* d_out, int out_size)
{
    const float* x     = (const float*)d_in[0];
    const float* Wq    = (const float*)d_in[1];
    const float* bq    = (const float*)d_in[2];
    const float* Wk    = (const float*)d_in[3];
    const float* bk    = (const float*)d_in[4];
    const float* Wv    = (const float*)d_in[5];
    const float* bv    = (const float*)d_in[6];
    const float* Wo    = (const float*)d_in[7];
    const float* bo    = (const float*)d_in[8];
    const float* ln1g  = (const float*)d_in[9];
    const float* ln1b  = (const float*)d_in[10];
    const float* W1    = (const float*)d_in[11];
    const float* b1    = (const float*)d_in[12];
    const float* W2    = (const float*)d_in[13];
    const float* b2    = (const float*)d_in[14];
    const float* ln2g  = (const float*)d_in[15];
    const float* ln2b  = (const float*)d_in[16];
    float* y = (float*)d_out;

    __half *q, *k, *v, *attn, *hh, *m1, *xh, *wq, *wk, *wv, *wo, *w1, *w2;
    float *proj, *h, *m2;
    cudaGetSymbolAddress((void**)&q,    g_q);
    cudaGetSymbolAddress((void**)&k,    g_k);
    cudaGetSymbolAddress((void**)&v,    g_v);
    cudaGetSymbolAddress((void**)&attn, g_attn);
    cudaGetSymbolAddress((void**)&proj, g_proj);
    cudaGetSymbolAddress((void**)&h,    g_h);
    cudaGetSymbolAddress((void**)&hh,   g_hh);
    cudaGetSymbolAddress((void**)&m1,   g_mlp1);
    cudaGetSymbolAddress((void**)&m2,   g_mlp2);
    cudaGetSymbolAddress((void**)&xh,   g_xh);
    cudaGetSymbolAddress((void**)&wq,   g_wq);
    cudaGetSymbolAddress((void**)&wk,   g_wk);
    cudaGetSymbolAddress((void**)&wv,   g_wv);
    cudaGetSymbolAddress((void**)&wo,   g_wo);
    cudaGetSymbolAddress((void**)&w1,   g_w1);
    cudaGetSymbolAddress((void**)&w2,   g_w2);

    const int SMEM_S  = 3 * 24576;              // 73728 (3-stage)
    const int SMEM_B  = 2 * 24576;              // 49152 (2-stage)
    const int SMEM_FA = 3 * 2 * 64 * 72 * 2;    // 55296
    cudaFuncSetAttribute(gemm_b_qkv, cudaFuncAttributeMaxDynamicSharedMemorySize, SMEM_B);
    cudaFuncSetAttribute(gemm_b<true, __half>,  cudaFuncAttributeMaxDynamicSharedMemorySize, SMEM_B);
    cudaFuncSetAttribute(gemm_s<false, float>,  cudaFuncAttributeMaxDynamicSharedMemorySize, SMEM_S);
    cudaFuncSetAttribute(flash_attn_h, cudaFuncAttributeMaxDynamicSharedMemorySize, SMEM_FA);

    // one fused convert launch: x + 6 weights -> half (16 floats/thread)
    CvtArgs ca;
    ca.s[0] = { x,  xh, SEQ * CDIM };
    ca.s[1] = { Wq, wq, CDIM * CDIM };
    ca.s[2] = { Wk, wk, CDIM * CDIM };
    ca.s[3] = { Wv, wv, CDIM * CDIM };
    ca.s[4] = { Wo, wo, CDIM * CDIM };
    ca.s[5] = { W1, w1, CDIM * FDIM };
    ca.s[6] = { W2, w2, FDIM * CDIM };
    cvt_all_kernel<<<dim3(SEQ * CDIM / 4096, 7), 256>>>(ca);

    // fused QKV projection (big grid: 2-stage, 4 CTA/SM)
    gemm_b_qkv<<<dim3(18, SEQ / 64), 256, SMEM_B>>>(xh, wq, wk, wv, bq, bk, bv, q, k, v);

    // causal attention (heavy-first global order)
    flash_attn_h<<<dim3(NH, SEQ / 128), 256, SMEM_FA>>>(q, k, v, attn);

    // output projection (small grid: 3-stage, 3 CTA/SM)
    gemm_s<false, float><<<dim3(CDIM / 128, SEQ / 64), 256, SMEM_S>>>(attn, wo, bo, proj, CDIM, CDIM);

    // h = LN(x + proj), plus half copy for W1
    add_ln<true><<<SEQ, 256>>>(x, proj, ln1g, ln1b, h, hh);

    // MLP1 (big grid: 2-stage, 4 CTA/SM)
    gemm_b<true, __half><<<dim3(FDIM / 128, SEQ / 64), 256, SMEM_B>>>(hh, w1, b1, m1, FDIM, CDIM);
    // MLP2 (small grid: 3-stage, 3 CTA/SM)
    gemm_s<false, float><<<dim3(CDIM / 128, SEQ / 64), 256, SMEM_S>>>(m1, w2, b2, m2, CDIM, FDIM);

    // y = LN(h + mlp)
    add_ln<false><<<SEQ, 256>>>(h, m2, ln2g, ln2b, y, nullptr);

    (void)in_sizes; (void)n_in; (void)out_size;
}